// round 7
// baseline (speedup 1.0000x reference)
#include <cuda_runtime.h>
#include <math.h>
#include <stdint.h>

#define LSEQ 4096
#define DM   256
#define DI   512
#define DS   16
#define NB   2
#define NCH  64   // scan chunks
#define CT   64   // chunk length

// ---------------- scratch (device globals; no runtime alloc allowed) ----------------
__device__ __align__(16) float g_xc [NB*DM*LSEQ];    // (b, c=256, l)
__device__ __align__(16) float g_xi [NB*DI*LSEQ];    // (b, d, l)
__device__ __align__(16) float g_z  [NB*DI*LSEQ];    // (b, d, l)
__device__ __align__(16) float g_u  [NB*DI*LSEQ];    // (b, d, l)
__device__ __align__(16) float g_dbc[48*NB*LSEQ];    // (j=48, b*l)
__device__ __align__(16) float g_dt [NB*DI*LSEQ];    // (b, d, l)
__device__ __align__(16) float g_y  [NB*DI*LSEQ];    // (b, d, l)
__device__ __align__(16) float g_xr [NB*DM*LSEQ];    // (b, c, l)
__device__ __align__(16) float g_y2 [NB*128*LSEQ];   // (b, o, l)
__device__ __align__(16) float g_mv [256];
__device__ __align__(16) float g_S  [NB*DI*NCH*DS];
__device__ __align__(16) float g_hs [NB*DI*NCH*DS];
__device__ __align__(16) float g_sd [NB*DI*NCH];
__device__ __align__(16) float g_wt1[256*1024];      // in_proj_w^T  (k=256, n=1024)
__device__ __align__(16) float g_wt2[512*256];       // out_proj_w^T (k=512, n=256)
__device__ __align__(16) float g_wt3[512*48 + 64];   // x_proj_w^T   (k=512, n=48) + pad

// ---------------- cp.async helpers ----------------
__device__ __forceinline__ void cp16(uint32_t dst, const float* src) {
    asm volatile("cp.async.cg.shared.global [%0], [%1], 16;\n" :: "r"(dst), "l"(src));
}
__device__ __forceinline__ void cp_commit() {
    asm volatile("cp.async.commit_group;\n");
}
__device__ __forceinline__ void cp_wait_dyn(int allow) {
    if (allow <= 0)      asm volatile("cp.async.wait_group 0;\n");
    else if (allow == 1) asm volatile("cp.async.wait_group 1;\n");
    else                 asm volatile("cp.async.wait_group 2;\n");
}

// ================= 128x128x8, 4-stage cp.async + reg double-buffered fp32 GEMM =================
// C[m,n] = sum_k A[m,k]*B[k,n]; A k-major (A[k*lda+m]), B k-major (B[k*ldb+n]).
// Requires M%128==0, N%128==0, K%8==0, K/8 >= 3.
template<class Epi>
__global__ __launch_bounds__(256)
void gemm128(const float* __restrict__ A, int lda, long sA,
             const float* __restrict__ B, int ldb, long sB,
             int M, int N, int K, Epi epi)
{
    __shared__ float As[4][8][128];
    __shared__ float Bs[4][8][128];
    const int tid = threadIdx.x;
    const int bz  = blockIdx.z;
    const float* Ab = A + (size_t)bz * sA;
    const float* Bb = B + (size_t)bz * sB;
    const int m0 = blockIdx.y * 128;
    const int n0 = blockIdx.x * 128;
    const int tx = tid & 15, ty = tid >> 4;

    const int ak = tid >> 5;          // k row 0..7
    const int am = (tid & 31) << 2;   // 4-float column group

    float acc[8][8];
#pragma unroll
    for (int i = 0; i < 8; i++)
#pragma unroll
        for (int j = 0; j < 8; j++) acc[i][j] = 0.f;

    const int nt = K >> 3;

    auto ldtile = [&](int st, int k0) {
        uint32_t da = (uint32_t)__cvta_generic_to_shared(&As[st][ak][am]);
        uint32_t db = (uint32_t)__cvta_generic_to_shared(&Bs[st][ak][am]);
        cp16(da, Ab + (size_t)(k0 + ak)*lda + m0 + am);
        cp16(db, Bb + (size_t)(k0 + ak)*ldb + n0 + am);
        cp_commit();
    };

    ldtile(0, 0);
    ldtile(1, 8);
    ldtile(2, 16);

    float af[2][8], bf[2][8];

    for (int kt = 0; kt < nt; ++kt) {
        int rem = nt - 1 - kt;
        cp_wait_dyn(rem > 2 ? 2 : rem);
        __syncthreads();
        if (kt + 3 < nt) ldtile((kt + 3) & 3, (kt + 3) << 3);

        const int st = kt & 3;
        // prologue fragment load (kk = 0)
        *reinterpret_cast<float4*>(&af[0][0]) = *reinterpret_cast<const float4*>(&As[st][0][ty << 2]);
        *reinterpret_cast<float4*>(&af[0][4]) = *reinterpret_cast<const float4*>(&As[st][0][64 + (ty << 2)]);
        *reinterpret_cast<float4*>(&bf[0][0]) = *reinterpret_cast<const float4*>(&Bs[st][0][tx << 2]);
        *reinterpret_cast<float4*>(&bf[0][4]) = *reinterpret_cast<const float4*>(&Bs[st][0][64 + (tx << 2)]);
#pragma unroll
        for (int kk = 0; kk < 8; ++kk) {
            const int cur = kk & 1, nxt = cur ^ 1;
            if (kk < 7) {
                *reinterpret_cast<float4*>(&af[nxt][0]) = *reinterpret_cast<const float4*>(&As[st][kk+1][ty << 2]);
                *reinterpret_cast<float4*>(&af[nxt][4]) = *reinterpret_cast<const float4*>(&As[st][kk+1][64 + (ty << 2)]);
                *reinterpret_cast<float4*>(&bf[nxt][0]) = *reinterpret_cast<const float4*>(&Bs[st][kk+1][tx << 2]);
                *reinterpret_cast<float4*>(&bf[nxt][4]) = *reinterpret_cast<const float4*>(&Bs[st][kk+1][64 + (tx << 2)]);
            }
#pragma unroll
            for (int i = 0; i < 8; i++)
#pragma unroll
                for (int j = 0; j < 8; j++) acc[i][j] += af[cur][i] * bf[cur][j];
        }
    }

#pragma unroll
    for (int i = 0; i < 8; i++) {
        int mi = m0 + ((i < 4) ? (ty << 2) + i : 64 + (ty << 2) + (i - 4));
#pragma unroll
        for (int j = 0; j < 8; j++) {
            int ni = n0 + ((j < 4) ? (tx << 2) + j : 64 + (tx << 2) + (j - 4));
            epi(bz, mi, ni, acc[i][j]);
        }
    }
}

// ================= small generic 64x64x16 GEMM (x_proj: N=48) =================
template<bool TA, bool TB, class Epi>
__global__ __launch_bounds__(256)
void gemm_k(const float* __restrict__ A, int lda, long sA,
            const float* __restrict__ B, int ldb, long sB,
            int M, int N, int K, Epi epi)
{
    __shared__ float As[16][68];
    __shared__ float Bs[16][68];
    const int tid = threadIdx.x;
    const int bz  = blockIdx.z;
    const float* Ab = A + (size_t)bz * sA;
    const float* Bb = B + (size_t)bz * sB;
    const int m0 = blockIdx.y * 64;
    const int n0 = blockIdx.x * 64;
    const int tx = tid & 15, ty = tid >> 4;

    float acc[4][4];
#pragma unroll
    for (int i = 0; i < 4; i++)
#pragma unroll
        for (int j = 0; j < 4; j++) acc[i][j] = 0.f;

    for (int k0 = 0; k0 < K; k0 += 16) {
        if (TA) {
            int k  = tid >> 4;
            int mq = (tid & 15) << 2;
            float4 v = *reinterpret_cast<const float4*>(Ab + (size_t)(k0 + k)*lda + m0 + mq);
            *reinterpret_cast<float4*>(&As[k][mq]) = v;
        } else {
            int m  = tid >> 2;
            int kq = (tid & 3) << 2;
            float4 v = *reinterpret_cast<const float4*>(Ab + (size_t)(m0 + m)*lda + k0 + kq);
            As[kq+0][m] = v.x; As[kq+1][m] = v.y; As[kq+2][m] = v.z; As[kq+3][m] = v.w;
        }
        if (TB) {
            int nn = tid >> 2;
            int kq = (tid & 3) << 2;
            float4 v = make_float4(0.f,0.f,0.f,0.f);
            if (n0 + nn < N)
                v = *reinterpret_cast<const float4*>(Bb + (size_t)(n0 + nn)*ldb + k0 + kq);
            Bs[kq+0][nn] = v.x; Bs[kq+1][nn] = v.y; Bs[kq+2][nn] = v.z; Bs[kq+3][nn] = v.w;
        } else {
            int k  = tid >> 4;
            int nq = (tid & 15) << 2;
            float4 v = *reinterpret_cast<const float4*>(Bb + (size_t)(k0 + k)*ldb + n0 + nq);
            *reinterpret_cast<float4*>(&Bs[k][nq]) = v;
        }
        __syncthreads();
#pragma unroll
        for (int kk = 0; kk < 16; ++kk) {
            float4 a4 = *reinterpret_cast<const float4*>(&As[kk][ty << 2]);
            float4 b4 = *reinterpret_cast<const float4*>(&Bs[kk][tx << 2]);
            float a[4] = {a4.x, a4.y, a4.z, a4.w};
            float b[4] = {b4.x, b4.y, b4.z, b4.w};
#pragma unroll
            for (int i = 0; i < 4; i++)
#pragma unroll
                for (int j = 0; j < 4; j++) acc[i][j] += a[i] * b[j];
        }
        __syncthreads();
    }
#pragma unroll
    for (int i = 0; i < 4; i++) {
        int mi = m0 + (ty << 2) + i;
#pragma unroll
        for (int j = 0; j < 4; j++) {
            int ni = n0 + (tx << 2) + j;
            if (mi < M && ni < N) epi(bz, mi, ni, acc[i][j]);
        }
    }
}

// ---------------- weight transpose: in (R,C) -> out (C,R) ----------------
__global__ void transp(const float* __restrict__ in, float* __restrict__ out, int R, int C) {
    __shared__ float t[32][33];
    int r0 = blockIdx.y * 32, c0 = blockIdx.x * 32;
    int x = threadIdx.x, y = threadIdx.y;
    for (int i = y; i < 32; i += 8) {
        int r = r0 + i, c = c0 + x;
        t[i][x] = (r < R && c < C) ? in[(size_t)r*C + c] : 0.f;
    }
    __syncthreads();
    for (int i = y; i < 32; i += 8) {
        int c = c0 + i, r = r0 + x;
        if (c < C && r < R) out[(size_t)c*R + r] = t[x][i];
    }
}

// ---------------- epilogues ----------------
struct EpiUp {
    float* xc; const float* up_b;
    __device__ void operator()(int b, int m, int n, float v) const {
        int o = m >> 2, i = (m >> 1) & 1, j = m & 1;
        int h = n >> 5, w = n & 31;
        xc[((size_t)b*DM + o)*LSEQ + (2*h + i)*64 + (2*w + j)] = v + up_b[o];
    }
};
struct EpiXZ {
    float* xi; float* z;
    __device__ void operator()(int b, int m, int n, float v) const {
        if (n < DI) xi[((size_t)b*DI + n)*LSEQ + m] = v;
        else        z [((size_t)b*DI + (n - DI))*LSEQ + m] = v;
    }
};
struct EpiDbc {
    float* dbc;
    __device__ void operator()(int b, int m, int n, float v) const {
        dbc[(size_t)n*(NB*LSEQ) + b*LSEQ + m] = v;
    }
};
struct EpiOut {
    const float* xc; float* xr;
    __device__ void operator()(int b, int m, int n, float v) const {
        size_t idx = ((size_t)b*DM + n)*LSEQ + m;
        xr[idx] = xc[idx] + v;
    }
};

// ---------------- skip concat copy ----------------
__global__ void copy_skip(const float* __restrict__ skip, float* __restrict__ xc) {
    int idx = blockIdx.x * blockDim.x + threadIdx.x;
    int total = NB * 128 * LSEQ;
    if (idx >= total) return;
    int b = idx / (128 * LSEQ);
    int rem = idx - b * (128 * LSEQ);
    xc[((size_t)b*DM + 128)*LSEQ + rem] = skip[idx];
}

// ---------------- depthwise causal conv1d + silu (coalesced) ----------------
__global__ __launch_bounds__(256)
void conv1d_kernel(const float* __restrict__ xi, const float* __restrict__ w,
                   const float* __restrict__ bias, float* __restrict__ u)
{
    __shared__ float s[32][132];
    __shared__ float sw[32][4];
    __shared__ float sb[32];
    int b  = blockIdx.z;
    int d0 = blockIdx.y * 32;
    int l0 = blockIdx.x * 128;
    int tid = threadIdx.x;
    for (int e = tid; e < 32*132; e += 256) {
        int dd = e / 132, li = e - dd*132;
        if (li < 131) {
            int l = l0 - 3 + li;
            s[dd][li] = (l >= 0 && l < LSEQ) ? xi[((size_t)b*DI + d0 + dd)*LSEQ + l] : 0.f;
        }
    }
    if (tid < 128) sw[tid >> 2][tid & 3] = w[(d0 + (tid >> 2))*4 + (tid & 3)];
    if (tid < 32)  sb[tid] = bias[d0 + tid];
    __syncthreads();
#pragma unroll
    for (int it = 0; it < 16; ++it) {
        int idx = it*256 + tid;
        int dd = idx >> 7, li = idx & 127;
        float a = s[dd][li]*sw[dd][0] + s[dd][li+1]*sw[dd][1]
                + s[dd][li+2]*sw[dd][2] + s[dd][li+3]*sw[dd][3] + sb[dd];
        float sv = a / (1.f + __expf(-a));
        u[((size_t)b*DI + d0 + dd)*LSEQ + l0 + li] = sv;
    }
}

// ---------------- dt = softplus(dbc[:,:16] @ dtw^T + dtb), out (b,d,l) ----------------
__global__ __launch_bounds__(256)
void dt_kernel(const float* __restrict__ dbc, const float* __restrict__ dtw,
               const float* __restrict__ dtb, float* __restrict__ dt)
{
    __shared__ float swt[DI*16];   // dtw (512,16) row-major
    __shared__ float sbc[16*64];   // dbc tile: 16 rows x 64 l
    __shared__ float sbias[DI];
    int bl0 = blockIdx.x * 64;
    int tid = threadIdx.x;
    for (int i = tid; i < DI*16; i += 256) swt[i] = dtw[i];
    for (int i = tid; i < DI; i += 256) sbias[i] = dtb[i];
    for (int i = tid; i < 16*64; i += 256) {
        int r = i >> 6, li = i & 63;
        sbc[i] = dbc[(size_t)r*(NB*LSEQ) + bl0 + li];
    }
    __syncthreads();
    int b  = bl0 >> 12;
    int l0 = bl0 & (LSEQ - 1);
#pragma unroll 4
    for (int it = 0; it < 128; ++it) {
        int idx = it*256 + tid;
        int d = idx >> 6, li = idx & 63;
        float acc = sbias[d];
#pragma unroll
        for (int r = 0; r < 16; ++r) acc += swt[d*16 + r] * sbc[r*64 + li];
        float sp = (acc > 20.f) ? acc : log1pf(__expf(acc));
        dt[((size_t)b*DI + d)*LSEQ + l0 + li] = sp;
    }
}

// ================= chunked selective scan =================
__global__ __launch_bounds__(128)
void scan_pass1(const float* __restrict__ dt, const float* __restrict__ u,
                const float* __restrict__ dbc, const float* __restrict__ A_log,
                float* __restrict__ S, float* __restrict__ sd)
{
    int lane = threadIdx.x & 31;
    int n    = lane & 15;
    int half = lane >> 4;
    int warp = threadIdx.x >> 5;
    int gch  = blockIdx.y * 8 + warp * 2 + half;
    int c    = blockIdx.x;
    int b = gch >> 9, d = gch & (DI - 1);

    float A = -__expf(A_log[d*DS + n]);
    const float* dtp = dt  + (size_t)gch*LSEQ + c*CT;
    const float* up  = u   + (size_t)gch*LSEQ + c*CT;
    const float* bp  = dbc + (size_t)(16 + n)*(NB*LSEQ) + b*LSEQ + c*CT;

    float h = 0.f, sda = 0.f;
#pragma unroll 8
    for (int l = 0; l < CT; ++l) {
        float dtv = dtp[l], uv = up[l], bn = bp[l];
        float dA = __expf(dtv * A);
        h = dA * h + (dtv * uv) * bn;
        sda += dtv;
    }
    S[((size_t)gch*NCH + c)*DS + n] = h;
    if (n == 0) sd[(size_t)gch*NCH + c] = sda;
}

__global__ __launch_bounds__(128)
void scan_pass2(const float* __restrict__ S, const float* __restrict__ sd,
                const float* __restrict__ A_log, float* __restrict__ hs)
{
    int lane = threadIdx.x & 31;
    int n    = lane & 15;
    int half = lane >> 4;
    int warp = threadIdx.x >> 5;
    int gch  = blockIdx.x * 8 + warp * 2 + half;
    int d = gch & (DI - 1);
    float A = -__expf(A_log[d*DS + n]);
    float h = 0.f;
    for (int c = 0; c < NCH; ++c) {
        size_t idx = ((size_t)gch*NCH + c)*DS + n;
        hs[idx] = h;
        float P = __expf(A * sd[(size_t)gch*NCH + c]);
        h = P * h + S[idx];
    }
}

__global__ __launch_bounds__(128)
void scan_pass3(const float* __restrict__ dt, const float* __restrict__ u,
                const float* __restrict__ dbc, const float* __restrict__ z,
                const float* __restrict__ A_log, const float* __restrict__ Dp,
                const float* __restrict__ hs, float* __restrict__ y)
{
    int lane = threadIdx.x & 31;
    int n    = lane & 15;
    int half = lane >> 4;
    int warp = threadIdx.x >> 5;
    int gch  = blockIdx.y * 8 + warp * 2 + half;
    int c    = blockIdx.x;
    int b = gch >> 9, d = gch & (DI - 1);

    float A  = -__expf(A_log[d*DS + n]);
    float Dv = Dp[d];
    const float* dtp = dt  + (size_t)gch*LSEQ + c*CT;
    const float* up  = u   + (size_t)gch*LSEQ + c*CT;
    const float* zp  = z   + (size_t)gch*LSEQ + c*CT;
    const float* bp  = dbc + (size_t)(16 + n)*(NB*LSEQ) + b*LSEQ + c*CT;
    const float* cp  = dbc + (size_t)(32 + n)*(NB*LSEQ) + b*LSEQ + c*CT;
    float*       yp  = y   + (size_t)gch*LSEQ + c*CT;

    float h = hs[((size_t)gch*NCH + c)*DS + n];
#pragma unroll 4
    for (int l = 0; l < CT; ++l) {
        float dtv = dtp[l], uv = up[l];
        float bn = bp[l], cn = cp[l];
        float dA = __expf(dtv * A);
        h = dA * h + (dtv * uv) * bn;
        float yv = h * cn;
        yv += __shfl_xor_sync(0xffffffffu, yv, 1);
        yv += __shfl_xor_sync(0xffffffffu, yv, 2);
        yv += __shfl_xor_sync(0xffffffffu, yv, 4);
        yv += __shfl_xor_sync(0xffffffffu, yv, 8);
        if (n == 0) {
            float out = yv + uv * Dv;
            float zv = zp[l];
            float sg = zv / (1.f + __expf(-zv));
            yp[l] = out * sg;
        }
    }
}

// ---------------- 3x3 conv (128 out, 256 in, pad 1), 32 out-ch per block ----------------
__global__ __launch_bounds__(256)
void conv3_kernel(const float* __restrict__ xr, const float* __restrict__ W,
                  const float* __restrict__ bias, float* __restrict__ y2)
{
    __shared__ float in_s[16][18][19];
    __shared__ float w_s[32][16][9];
    int b  = blockIdx.z;
    int o0 = blockIdx.y * 32;
    int pt = blockIdx.x;
    int h0 = (pt >> 2) * 16;
    int w0 = (pt & 3) * 16;
    int tid = threadIdx.x;
    int wo  = tid & 63;
    int og  = tid >> 6;             // 4 groups x 8 channels
    int prow  = wo >> 2;
    int pcol0 = (wo & 3) << 2;

    float acc[8][4];
#pragma unroll
    for (int i = 0; i < 8; i++)
#pragma unroll
        for (int j = 0; j < 4; j++) acc[i][j] = 0.f;

    const float* xrb = xr + (size_t)b * DM * LSEQ;
    for (int c0 = 0; c0 < 256; c0 += 16) {
        for (int e = tid; e < 16*18*18; e += 256) {
            int c = e / 324, r = (e % 324) / 18, cc = e % 18;
            int h = h0 + r - 1, w = w0 + cc - 1;
            float v = 0.f;
            if (h >= 0 && h < 64 && w >= 0 && w < 64)
                v = xrb[(size_t)(c0 + c)*LSEQ + h*64 + w];
            in_s[c][r][cc] = v;
        }
        for (int e = tid; e < 32*16*9; e += 256) {
            int o = e / 144, rest = e % 144, c = rest / 9, t = rest % 9;
            w_s[o][c][t] = W[(size_t)(o0 + o)*2304 + (c0 + c)*9 + t];
        }
        __syncthreads();
#pragma unroll 1
        for (int c = 0; c < 16; ++c) {
#pragma unroll
            for (int t = 0; t < 9; ++t) {
                int di = t / 3, dj = t % 3;
                float iv[4];
#pragma unroll
                for (int j = 0; j < 4; ++j) iv[j] = in_s[c][prow + di][pcol0 + dj + j];
#pragma unroll
                for (int oi = 0; oi < 8; ++oi) {
                    float wv = w_s[og*8 + oi][c][t];
#pragma unroll
                    for (int j = 0; j < 4; ++j) acc[oi][j] += wv * iv[j];
                }
            }
        }
        __syncthreads();
    }
#pragma unroll
    for (int oi = 0; oi < 8; ++oi) {
        int o = o0 + og*8 + oi;
        float bv = bias[o];
#pragma unroll
        for (int j = 0; j < 4; ++j)
            y2[((size_t)b*128 + o)*LSEQ + (h0 + prow)*64 + (w0 + pcol0 + j)] = acc[oi][j] + bv;
    }
}

// ---------------- batchnorm stats + apply + gelu ----------------
__global__ void bn_stats(const float* __restrict__ y2, float* __restrict__ mv) {
    int o = blockIdx.x;
    float s = 0.f, s2 = 0.f;
    for (int i = threadIdx.x; i < NB*LSEQ; i += 256) {
        int b = i >> 12, l = i & (LSEQ - 1);
        float v = y2[((size_t)b*128 + o)*LSEQ + l];
        s += v; s2 += v*v;
    }
    __shared__ float sh0[256], sh1[256];
    sh0[threadIdx.x] = s; sh1[threadIdx.x] = s2;
    __syncthreads();
    for (int st = 128; st > 0; st >>= 1) {
        if (threadIdx.x < st) {
            sh0[threadIdx.x] += sh0[threadIdx.x + st];
            sh1[threadIdx.x] += sh1[threadIdx.x + st];
        }
        __syncthreads();
    }
    if (threadIdx.x == 0) {
        float inv = 1.f / (NB * LSEQ);
        float mu = sh0[0] * inv;
        float var = sh1[0] * inv - mu * mu;
        mv[o] = mu; mv[128 + o] = var;
    }
}

__global__ void bn_apply(const float* __restrict__ y2, const float* __restrict__ mv,
                         const float* __restrict__ gamma, const float* __restrict__ beta,
                         float* __restrict__ out)
{
    int idx = blockIdx.x * blockDim.x + threadIdx.x;
    if (idx >= NB*128*LSEQ) return;
    int o = (idx >> 12) & 127;
    float mu = mv[o], var = mv[128 + o];
    float v = (y2[idx] - mu) * rsqrtf(var + 1e-5f) * gamma[o] + beta[o];
    out[idx] = 0.5f * v * (1.f + erff(v * 0.70710678118654752440f));
}

// ---------------- launch ----------------
extern "C" void kernel_launch(void* const* d_in, const int* in_sizes, int n_in,
                              void* d_out, int out_size)
{
    const float* x        = (const float*)d_in[0];
    const float* skip     = (const float*)d_in[1];
    const float* up_w     = (const float*)d_in[2];
    const float* up_b     = (const float*)d_in[3];
    const float* in_proj  = (const float*)d_in[4];
    const float* c1w      = (const float*)d_in[5];
    const float* c1b      = (const float*)d_in[6];
    const float* xproj    = (const float*)d_in[7];
    const float* dtw      = (const float*)d_in[8];
    const float* dtb      = (const float*)d_in[9];
    const float* A_log    = (const float*)d_in[10];
    const float* Dp       = (const float*)d_in[11];
    const float* outw     = (const float*)d_in[12];
    const float* cw       = (const float*)d_in[13];
    const float* cb       = (const float*)d_in[14];
    const float* bng      = (const float*)d_in[15];
    const float* bnb      = (const float*)d_in[16];
    float* out = (float*)d_out;

    float *xc, *xi, *z, *u, *dbc, *dtv, *y, *xr, *y2, *mv, *S, *hs, *sd;
    float *wt1, *wt2, *wt3;
    cudaGetSymbolAddress((void**)&xc,  g_xc);
    cudaGetSymbolAddress((void**)&xi,  g_xi);
    cudaGetSymbolAddress((void**)&z,   g_z);
    cudaGetSymbolAddress((void**)&u,   g_u);
    cudaGetSymbolAddress((void**)&dbc, g_dbc);
    cudaGetSymbolAddress((void**)&dtv, g_dt);
    cudaGetSymbolAddress((void**)&y,   g_y);
    cudaGetSymbolAddress((void**)&xr,  g_xr);
    cudaGetSymbolAddress((void**)&y2,  g_y2);
    cudaGetSymbolAddress((void**)&mv,  g_mv);
    cudaGetSymbolAddress((void**)&S,   g_S);
    cudaGetSymbolAddress((void**)&hs,  g_hs);
    cudaGetSymbolAddress((void**)&sd,  g_sd);
    cudaGetSymbolAddress((void**)&wt1, g_wt1);
    cudaGetSymbolAddress((void**)&wt2, g_wt2);
    cudaGetSymbolAddress((void**)&wt3, g_wt3);

    // 0) one-time weight transposes
    transp<<<dim3(256/32, 1024/32), dim3(32, 8)>>>(in_proj, wt1, 1024, 256);
    transp<<<dim3(512/32,  256/32), dim3(32, 8)>>>(outw,    wt2,  256, 512);
    transp<<<dim3(512/32,        2), dim3(32, 8)>>>(xproj,   wt3,   48, 512);

    // 1) upsample GEMM: C[512,1024] = up_w^T * x[b]
    gemm128<EpiUp><<<dim3(8, 4, NB), 256>>>(
        up_w, 512, 0, x, 1024, (long)256*1024, 512, 1024, 256, EpiUp{xc, up_b});

    // 2) skip concat
    copy_skip<<<(NB*128*LSEQ + 255)/256, 256>>>(skip, xc);

    // 3) in_proj GEMM: C[4096,1024] = xc^T * in_proj^T (both k-major)
    gemm128<EpiXZ><<<dim3(8, 32, NB), 256>>>(
        xc, LSEQ, (long)DM*LSEQ, wt1, 1024, 0, LSEQ, 2*DI, DM, EpiXZ{xi, z});

    // 4) depthwise conv1d + silu
    conv1d_kernel<<<dim3(LSEQ/128, DI/32, NB), 256>>>(xi, c1w, c1b, u);

    // 5) x_proj GEMM: C[4096,48] per batch = u^T * xproj^T
    gemm_k<true, false, EpiDbc><<<dim3(1, 64, NB), 256>>>(
        u, LSEQ, (long)DI*LSEQ, wt3, 48, 0, LSEQ, 48, DI, EpiDbc{dbc});

    // 6) dt = softplus(dbc[:16]^T @ dtw^T + dtb)
    dt_kernel<<<NB*LSEQ/64, 256>>>(dbc, dtw, dtb, dtv);

    // 7) chunked selective scan
    scan_pass1<<<dim3(NCH, NB*DI/8), 128>>>(dtv, u, dbc, A_log, S, sd);
    scan_pass2<<<NB*DI/8, 128>>>(S, sd, A_log, hs);
    scan_pass3<<<dim3(NCH, NB*DI/8), 128>>>(dtv, u, dbc, z, A_log, Dp, hs, y);

    // 8) out_proj GEMM + residual
    gemm128<EpiOut><<<dim3(2, 32, NB), 256>>>(
        y, LSEQ, (long)DI*LSEQ, wt2, 256, 0, LSEQ, DM, DI, EpiOut{xc, xr});

    // 9) 3x3 conv (32 out-ch per block)
    conv3_kernel<<<dim3(16, 4, NB), 256>>>(xr, cw, cb, y2);

    // 10) batchnorm stats
    bn_stats<<<128, 256>>>(y2, mv);

    // 11) batchnorm apply + gelu
    bn_apply<<<(NB*128*LSEQ + 255)/256, 256>>>(y2, mv, bng, bnb, out);
}

// round 8
// speedup vs baseline: 1.1381x; 1.1381x over previous
#include <cuda_runtime.h>
#include <math.h>
#include <stdint.h>

#define LSEQ 4096
#define DM   256
#define DI   512
#define DS   16
#define NB   2
#define NCH  64   // scan chunks
#define CT   64   // chunk length

// ---------------- scratch (device globals; no runtime alloc allowed) ----------------
__device__ __align__(16) float g_xc [NB*DM*LSEQ];    // (b, c=256, l)
__device__ __align__(16) float g_xi [NB*DI*LSEQ];    // (b, d, l)
__device__ __align__(16) float g_z  [NB*DI*LSEQ];    // (b, d, l)
__device__ __align__(16) float g_u  [NB*DI*LSEQ];    // (b, d, l)
__device__ __align__(16) float g_dbc[48*NB*LSEQ];    // (j=48, b*l)
__device__ __align__(16) float g_dt [NB*DI*LSEQ];    // (b, d, l)
__device__ __align__(16) float g_y  [NB*DI*LSEQ];    // (b, d, l)
__device__ __align__(16) float g_xr [NB*DM*LSEQ];    // (b, c, l)
__device__ __align__(16) float g_y2 [NB*128*LSEQ];   // (b, o, l)
__device__ __align__(16) float g_mv [256];
__device__ __align__(16) float g_S  [NB*DI*NCH*DS];
__device__ __align__(16) float g_hs [NB*DI*NCH*DS];
__device__ __align__(16) float g_sd [NB*DI*NCH];
__device__ __align__(16) float g_wt1[256*1024];      // in_proj_w^T  (k=256, n=1024)
__device__ __align__(16) float g_wt2[512*256];       // out_proj_w^T (k=512, n=256)
__device__ __align__(16) float g_wt3[512*48 + 64];   // x_proj_w^T   (k=512, n=48) + pad

// ---------------- cp.async helpers ----------------
__device__ __forceinline__ void cp16(uint32_t dst, const float* src) {
    asm volatile("cp.async.cg.shared.global [%0], [%1], 16;\n" :: "r"(dst), "l"(src));
}
__device__ __forceinline__ void cp_commit() {
    asm volatile("cp.async.commit_group;\n");
}
__device__ __forceinline__ void cp_wait_dyn(int allow) {
    if (allow <= 0)      asm volatile("cp.async.wait_group 0;\n");
    else if (allow == 1) asm volatile("cp.async.wait_group 1;\n");
    else                 asm volatile("cp.async.wait_group 2;\n");
}

// ---------------- tf32 helpers ----------------
__device__ __forceinline__ uint32_t f2tf(float f) {
    uint32_t r;
    asm("cvt.rna.tf32.f32 %0, %1;" : "=r"(r) : "f"(f));
    return r;
}
__device__ __forceinline__ void mma_tf32(float* c, const uint32_t* a, const uint32_t* b) {
    asm volatile(
        "mma.sync.aligned.m16n8k8.row.col.f32.tf32.tf32.f32 "
        "{%0,%1,%2,%3}, {%4,%5,%6,%7}, {%8,%9}, {%0,%1,%2,%3};"
        : "+f"(c[0]), "+f"(c[1]), "+f"(c[2]), "+f"(c[3])
        : "r"(a[0]), "r"(a[1]), "r"(a[2]), "r"(a[3]), "r"(b[0]), "r"(b[1]));
}

// ================= 128x128x8, 4-stage cp.async, TF32 tensor-core GEMM =================
// C[m,n] = sum_k A[m,k]*B[k,n]; A k-major (A[k*lda+m]), B k-major (B[k*ldb+n]).
// Requires M%128==0, N%128==0, K%8==0, K/8 >= 3.
// 8 warps: warp tile 64(m) x 32(n), mma.m16n8k8 (4 m-tiles x 4 n-tiles).
template<class Epi>
__global__ __launch_bounds__(256)
void gemm128_tc(const float* __restrict__ A, int lda, long sA,
                const float* __restrict__ B, int ldb, long sB,
                int M, int N, int K, Epi epi)
{
    __shared__ float As[4][8][132];
    __shared__ float Bs[4][8][132];
    const int tid = threadIdx.x;
    const int bz  = blockIdx.z;
    const float* Ab = A + (size_t)bz * sA;
    const float* Bb = B + (size_t)bz * sB;
    const int m0 = blockIdx.y * 128;
    const int n0 = blockIdx.x * 128;

    const int warp = tid >> 5;
    const int lane = tid & 31;
    const int gid  = lane >> 2;   // groupID 0..7
    const int tig  = lane & 3;    // thread-in-group 0..3
    const int wm   = (warp >> 2) * 64;  // 0 or 64
    const int wn   = (warp & 3) * 32;   // 0,32,64,96

    const int ak = tid >> 5;          // k row 0..7
    const int am = (tid & 31) << 2;   // 4-float column group

    float acc[4][4][4];
#pragma unroll
    for (int i = 0; i < 4; i++)
#pragma unroll
        for (int j = 0; j < 4; j++)
#pragma unroll
            for (int q = 0; q < 4; q++) acc[i][j][q] = 0.f;

    const int nt = K >> 3;

    auto ldtile = [&](int st, int k0) {
        uint32_t da = (uint32_t)__cvta_generic_to_shared(&As[st][ak][am]);
        uint32_t db = (uint32_t)__cvta_generic_to_shared(&Bs[st][ak][am]);
        cp16(da, Ab + (size_t)(k0 + ak)*lda + m0 + am);
        cp16(db, Bb + (size_t)(k0 + ak)*ldb + n0 + am);
        cp_commit();
    };

    ldtile(0, 0);
    ldtile(1, 8);
    ldtile(2, 16);

    for (int kt = 0; kt < nt; ++kt) {
        int rem = nt - 1 - kt;
        cp_wait_dyn(rem > 2 ? 2 : rem);
        __syncthreads();
        if (kt + 3 < nt) ldtile((kt + 3) & 3, (kt + 3) << 3);

        const int st = kt & 3;
        uint32_t afr[4][4], bfr[4][2];
#pragma unroll
        for (int mt = 0; mt < 4; ++mt) {
            int mb = wm + mt*16 + gid;
            afr[mt][0] = f2tf(As[st][tig  ][mb]);
            afr[mt][1] = f2tf(As[st][tig  ][mb + 8]);
            afr[mt][2] = f2tf(As[st][tig+4][mb]);
            afr[mt][3] = f2tf(As[st][tig+4][mb + 8]);
        }
#pragma unroll
        for (int ntl = 0; ntl < 4; ++ntl) {
            int nb = wn + ntl*8 + gid;
            bfr[ntl][0] = f2tf(Bs[st][tig  ][nb]);
            bfr[ntl][1] = f2tf(Bs[st][tig+4][nb]);
        }
#pragma unroll
        for (int mt = 0; mt < 4; ++mt)
#pragma unroll
            for (int ntl = 0; ntl < 4; ++ntl)
                mma_tf32(acc[mt][ntl], afr[mt], bfr[ntl]);
    }

#pragma unroll
    for (int mt = 0; mt < 4; ++mt) {
        int mb = m0 + wm + mt*16;
#pragma unroll
        for (int ntl = 0; ntl < 4; ++ntl) {
            int nb = n0 + wn + ntl*8;
            epi(bz, mb + gid,     nb + 2*tig,     acc[mt][ntl][0]);
            epi(bz, mb + gid,     nb + 2*tig + 1, acc[mt][ntl][1]);
            epi(bz, mb + gid + 8, nb + 2*tig,     acc[mt][ntl][2]);
            epi(bz, mb + gid + 8, nb + 2*tig + 1, acc[mt][ntl][3]);
        }
    }
}

// ================= small generic 64x64x16 GEMM (x_proj: N=48) =================
template<bool TA, bool TB, class Epi>
__global__ __launch_bounds__(256)
void gemm_k(const float* __restrict__ A, int lda, long sA,
            const float* __restrict__ B, int ldb, long sB,
            int M, int N, int K, Epi epi)
{
    __shared__ float As[16][68];
    __shared__ float Bs[16][68];
    const int tid = threadIdx.x;
    const int bz  = blockIdx.z;
    const float* Ab = A + (size_t)bz * sA;
    const float* Bb = B + (size_t)bz * sB;
    const int m0 = blockIdx.y * 64;
    const int n0 = blockIdx.x * 64;
    const int tx = tid & 15, ty = tid >> 4;

    float acc[4][4];
#pragma unroll
    for (int i = 0; i < 4; i++)
#pragma unroll
        for (int j = 0; j < 4; j++) acc[i][j] = 0.f;

    for (int k0 = 0; k0 < K; k0 += 16) {
        if (TA) {
            int k  = tid >> 4;
            int mq = (tid & 15) << 2;
            float4 v = *reinterpret_cast<const float4*>(Ab + (size_t)(k0 + k)*lda + m0 + mq);
            *reinterpret_cast<float4*>(&As[k][mq]) = v;
        } else {
            int m  = tid >> 2;
            int kq = (tid & 3) << 2;
            float4 v = *reinterpret_cast<const float4*>(Ab + (size_t)(m0 + m)*lda + k0 + kq);
            As[kq+0][m] = v.x; As[kq+1][m] = v.y; As[kq+2][m] = v.z; As[kq+3][m] = v.w;
        }
        if (TB) {
            int nn = tid >> 2;
            int kq = (tid & 3) << 2;
            float4 v = make_float4(0.f,0.f,0.f,0.f);
            if (n0 + nn < N)
                v = *reinterpret_cast<const float4*>(Bb + (size_t)(n0 + nn)*ldb + k0 + kq);
            Bs[kq+0][nn] = v.x; Bs[kq+1][nn] = v.y; Bs[kq+2][nn] = v.z; Bs[kq+3][nn] = v.w;
        } else {
            int k  = tid >> 4;
            int nq = (tid & 15) << 2;
            float4 v = *reinterpret_cast<const float4*>(Bb + (size_t)(k0 + k)*ldb + n0 + nq);
            *reinterpret_cast<float4*>(&Bs[k][nq]) = v;
        }
        __syncthreads();
#pragma unroll
        for (int kk = 0; kk < 16; ++kk) {
            float4 a4 = *reinterpret_cast<const float4*>(&As[kk][ty << 2]);
            float4 b4 = *reinterpret_cast<const float4*>(&Bs[kk][tx << 2]);
            float a[4] = {a4.x, a4.y, a4.z, a4.w};
            float b[4] = {b4.x, b4.y, b4.z, b4.w};
#pragma unroll
            for (int i = 0; i < 4; i++)
#pragma unroll
                for (int j = 0; j < 4; j++) acc[i][j] += a[i] * b[j];
        }
        __syncthreads();
    }
#pragma unroll
    for (int i = 0; i < 4; i++) {
        int mi = m0 + (ty << 2) + i;
#pragma unroll
        for (int j = 0; j < 4; j++) {
            int ni = n0 + (tx << 2) + j;
            if (mi < M && ni < N) epi(bz, mi, ni, acc[i][j]);
        }
    }
}

// ---------------- weight transpose: in (R,C) -> out (C,R) ----------------
__global__ void transp(const float* __restrict__ in, float* __restrict__ out, int R, int C) {
    __shared__ float t[32][33];
    int r0 = blockIdx.y * 32, c0 = blockIdx.x * 32;
    int x = threadIdx.x, y = threadIdx.y;
    for (int i = y; i < 32; i += 8) {
        int r = r0 + i, c = c0 + x;
        t[i][x] = (r < R && c < C) ? in[(size_t)r*C + c] : 0.f;
    }
    __syncthreads();
    for (int i = y; i < 32; i += 8) {
        int c = c0 + i, r = r0 + x;
        if (c < C && r < R) out[(size_t)c*R + r] = t[x][i];
    }
}

// ---------------- epilogues ----------------
struct EpiUp {
    float* xc; const float* up_b;
    __device__ void operator()(int b, int m, int n, float v) const {
        int o = m >> 2, i = (m >> 1) & 1, j = m & 1;
        int h = n >> 5, w = n & 31;
        xc[((size_t)b*DM + o)*LSEQ + (2*h + i)*64 + (2*w + j)] = v + up_b[o];
    }
};
struct EpiXZ {
    float* xi; float* z;
    __device__ void operator()(int b, int m, int n, float v) const {
        if (n < DI) xi[((size_t)b*DI + n)*LSEQ + m] = v;
        else        z [((size_t)b*DI + (n - DI))*LSEQ + m] = v;
    }
};
struct EpiDbc {
    float* dbc;
    __device__ void operator()(int b, int m, int n, float v) const {
        dbc[(size_t)n*(NB*LSEQ) + b*LSEQ + m] = v;
    }
};
struct EpiOut {
    const float* xc; float* xr;
    __device__ void operator()(int b, int m, int n, float v) const {
        size_t idx = ((size_t)b*DM + n)*LSEQ + m;
        xr[idx] = xc[idx] + v;
    }
};

// ---------------- skip concat copy ----------------
__global__ void copy_skip(const float* __restrict__ skip, float* __restrict__ xc) {
    int idx = blockIdx.x * blockDim.x + threadIdx.x;
    int total = NB * 128 * LSEQ;
    if (idx >= total) return;
    int b = idx / (128 * LSEQ);
    int rem = idx - b * (128 * LSEQ);
    xc[((size_t)b*DM + 128)*LSEQ + rem] = skip[idx];
}

// ---------------- depthwise causal conv1d + silu (coalesced) ----------------
__global__ __launch_bounds__(256)
void conv1d_kernel(const float* __restrict__ xi, const float* __restrict__ w,
                   const float* __restrict__ bias, float* __restrict__ u)
{
    __shared__ float s[32][132];
    __shared__ float sw[32][4];
    __shared__ float sb[32];
    int b  = blockIdx.z;
    int d0 = blockIdx.y * 32;
    int l0 = blockIdx.x * 128;
    int tid = threadIdx.x;
    for (int e = tid; e < 32*132; e += 256) {
        int dd = e / 132, li = e - dd*132;
        if (li < 131) {
            int l = l0 - 3 + li;
            s[dd][li] = (l >= 0 && l < LSEQ) ? xi[((size_t)b*DI + d0 + dd)*LSEQ + l] : 0.f;
        }
    }
    if (tid < 128) sw[tid >> 2][tid & 3] = w[(d0 + (tid >> 2))*4 + (tid & 3)];
    if (tid < 32)  sb[tid] = bias[d0 + tid];
    __syncthreads();
#pragma unroll
    for (int it = 0; it < 16; ++it) {
        int idx = it*256 + tid;
        int dd = idx >> 7, li = idx & 127;
        float a = s[dd][li]*sw[dd][0] + s[dd][li+1]*sw[dd][1]
                + s[dd][li+2]*sw[dd][2] + s[dd][li+3]*sw[dd][3] + sb[dd];
        float sv = a / (1.f + __expf(-a));
        u[((size_t)b*DI + d0 + dd)*LSEQ + l0 + li] = sv;
    }
}

// ---------------- dt = softplus(dbc[:,:16] @ dtw^T + dtb), out (b,d,l) ----------------
__global__ __launch_bounds__(256)
void dt_kernel(const float* __restrict__ dbc, const float* __restrict__ dtw,
               const float* __restrict__ dtb, float* __restrict__ dt)
{
    __shared__ float swt[DI*16];   // dtw (512,16) row-major
    __shared__ float sbc[16*64];   // dbc tile: 16 rows x 64 l
    __shared__ float sbias[DI];
    int bl0 = blockIdx.x * 64;
    int tid = threadIdx.x;
    for (int i = tid; i < DI*16; i += 256) swt[i] = dtw[i];
    for (int i = tid; i < DI; i += 256) sbias[i] = dtb[i];
    for (int i = tid; i < 16*64; i += 256) {
        int r = i >> 6, li = i & 63;
        sbc[i] = dbc[(size_t)r*(NB*LSEQ) + bl0 + li];
    }
    __syncthreads();
    int b  = bl0 >> 12;
    int l0 = bl0 & (LSEQ - 1);
#pragma unroll 4
    for (int it = 0; it < 128; ++it) {
        int idx = it*256 + tid;
        int d = idx >> 6, li = idx & 63;
        float acc = sbias[d];
#pragma unroll
        for (int r = 0; r < 16; ++r) acc += swt[d*16 + r] * sbc[r*64 + li];
        float sp = (acc > 20.f) ? acc : log1pf(__expf(acc));
        dt[((size_t)b*DI + d)*LSEQ + l0 + li] = sp;
    }
}

// ================= chunked selective scan =================
__global__ __launch_bounds__(128)
void scan_pass1(const float* __restrict__ dt, const float* __restrict__ u,
                const float* __restrict__ dbc, const float* __restrict__ A_log,
                float* __restrict__ S, float* __restrict__ sd)
{
    int lane = threadIdx.x & 31;
    int n    = lane & 15;
    int half = lane >> 4;
    int warp = threadIdx.x >> 5;
    int gch  = blockIdx.y * 8 + warp * 2 + half;
    int c    = blockIdx.x;
    int b = gch >> 9, d = gch & (DI - 1);

    float A = -__expf(A_log[d*DS + n]);
    const float* dtp = dt  + (size_t)gch*LSEQ + c*CT;
    const float* up  = u   + (size_t)gch*LSEQ + c*CT;
    const float* bp  = dbc + (size_t)(16 + n)*(NB*LSEQ) + b*LSEQ + c*CT;

    float h = 0.f, sda = 0.f;
#pragma unroll 8
    for (int l = 0; l < CT; ++l) {
        float dtv = dtp[l], uv = up[l], bn = bp[l];
        float dA = __expf(dtv * A);
        h = dA * h + (dtv * uv) * bn;
        sda += dtv;
    }
    S[((size_t)gch*NCH + c)*DS + n] = h;
    if (n == 0) sd[(size_t)gch*NCH + c] = sda;
}

__global__ __launch_bounds__(128)
void scan_pass2(const float* __restrict__ S, const float* __restrict__ sd,
                const float* __restrict__ A_log, float* __restrict__ hs)
{
    int lane = threadIdx.x & 31;
    int n    = lane & 15;
    int half = lane >> 4;
    int warp = threadIdx.x >> 5;
    int gch  = blockIdx.x * 8 + warp * 2 + half;
    int d = gch & (DI - 1);
    float A = -__expf(A_log[d*DS + n]);
    float h = 0.f;
    for (int c = 0; c < NCH; ++c) {
        size_t idx = ((size_t)gch*NCH + c)*DS + n;
        hs[idx] = h;
        float P = __expf(A * sd[(size_t)gch*NCH + c]);
        h = P * h + S[idx];
    }
}

__global__ __launch_bounds__(128)
void scan_pass3(const float* __restrict__ dt, const float* __restrict__ u,
                const float* __restrict__ dbc, const float* __restrict__ z,
                const float* __restrict__ A_log, const float* __restrict__ Dp,
                const float* __restrict__ hs, float* __restrict__ y)
{
    int lane = threadIdx.x & 31;
    int n    = lane & 15;
    int half = lane >> 4;
    int warp = threadIdx.x >> 5;
    int gch  = blockIdx.y * 8 + warp * 2 + half;
    int c    = blockIdx.x;
    int b = gch >> 9, d = gch & (DI - 1);

    float A  = -__expf(A_log[d*DS + n]);
    float Dv = Dp[d];
    const float* dtp = dt  + (size_t)gch*LSEQ + c*CT;
    const float* up  = u   + (size_t)gch*LSEQ + c*CT;
    const float* zp  = z   + (size_t)gch*LSEQ + c*CT;
    const float* bp  = dbc + (size_t)(16 + n)*(NB*LSEQ) + b*LSEQ + c*CT;
    const float* cp  = dbc + (size_t)(32 + n)*(NB*LSEQ) + b*LSEQ + c*CT;
    float*       yp  = y   + (size_t)gch*LSEQ + c*CT;

    float h = hs[((size_t)gch*NCH + c)*DS + n];
#pragma unroll 4
    for (int l = 0; l < CT; ++l) {
        float dtv = dtp[l], uv = up[l];
        float bn = bp[l], cn = cp[l];
        float dA = __expf(dtv * A);
        h = dA * h + (dtv * uv) * bn;
        float yv = h * cn;
        yv += __shfl_xor_sync(0xffffffffu, yv, 1);
        yv += __shfl_xor_sync(0xffffffffu, yv, 2);
        yv += __shfl_xor_sync(0xffffffffu, yv, 4);
        yv += __shfl_xor_sync(0xffffffffu, yv, 8);
        if (n == 0) {
            float out = yv + uv * Dv;
            float zv = zp[l];
            float sg = zv / (1.f + __expf(-zv));
            yp[l] = out * sg;
        }
    }
}

// ---------------- 3x3 conv (128 out, 256 in, pad 1), 16 out-ch per block ----------------
__global__ __launch_bounds__(256)
void conv3_kernel(const float* __restrict__ xr, const float* __restrict__ W,
                  const float* __restrict__ bias, float* __restrict__ y2)
{
    __shared__ float in_s[16][18][19];
    __shared__ float w_s[16][16][9];
    int b  = blockIdx.z;
    int o0 = blockIdx.y * 16;
    int pt = blockIdx.x;
    int h0 = (pt >> 2) * 16;
    int w0 = (pt & 3) * 16;
    int tid = threadIdx.x;
    int wo  = tid & 63;
    int og  = tid >> 6;
    int prow  = wo >> 2;
    int pcol0 = (wo & 3) << 2;

    float acc[4][4];
#pragma unroll
    for (int i = 0; i < 4; i++)
#pragma unroll
        for (int j = 0; j < 4; j++) acc[i][j] = 0.f;

    const float* xrb = xr + (size_t)b * DM * LSEQ;
    for (int c0 = 0; c0 < 256; c0 += 16) {
        for (int e = tid; e < 16*18*18; e += 256) {
            int c = e / 324, r = (e % 324) / 18, cc = e % 18;
            int h = h0 + r - 1, w = w0 + cc - 1;
            float v = 0.f;
            if (h >= 0 && h < 64 && w >= 0 && w < 64)
                v = xrb[(size_t)(c0 + c)*LSEQ + h*64 + w];
            in_s[c][r][cc] = v;
        }
        for (int e = tid; e < 16*16*9; e += 256) {
            int o = e / 144, rest = e % 144, c = rest / 9, t = rest % 9;
            w_s[o][c][t] = W[(size_t)(o0 + o)*2304 + (c0 + c)*9 + t];
        }
        __syncthreads();
#pragma unroll 1
        for (int c = 0; c < 16; ++c) {
#pragma unroll
            for (int t = 0; t < 9; ++t) {
                int di = t / 3, dj = t % 3;
                float iv[4];
#pragma unroll
                for (int j = 0; j < 4; ++j) iv[j] = in_s[c][prow + di][pcol0 + dj + j];
#pragma unroll
                for (int oi = 0; oi < 4; ++oi) {
                    float wv = w_s[og*4 + oi][c][t];
#pragma unroll
                    for (int j = 0; j < 4; ++j) acc[oi][j] += wv * iv[j];
                }
            }
        }
        __syncthreads();
    }
#pragma unroll
    for (int oi = 0; oi < 4; ++oi) {
        int o = o0 + og*4 + oi;
        float bv = bias[o];
#pragma unroll
        for (int j = 0; j < 4; ++j)
            y2[((size_t)b*128 + o)*LSEQ + (h0 + prow)*64 + (w0 + pcol0 + j)] = acc[oi][j] + bv;
    }
}

// ---------------- batchnorm stats + apply + gelu ----------------
__global__ void bn_stats(const float* __restrict__ y2, float* __restrict__ mv) {
    int o = blockIdx.x;
    float s = 0.f, s2 = 0.f;
    for (int i = threadIdx.x; i < NB*LSEQ; i += 256) {
        int b = i >> 12, l = i & (LSEQ - 1);
        float v = y2[((size_t)b*128 + o)*LSEQ + l];
        s += v; s2 += v*v;
    }
    __shared__ float sh0[256], sh1[256];
    sh0[threadIdx.x] = s; sh1[threadIdx.x] = s2;
    __syncthreads();
    for (int st = 128; st > 0; st >>= 1) {
        if (threadIdx.x < st) {
            sh0[threadIdx.x] += sh0[threadIdx.x + st];
            sh1[threadIdx.x] += sh1[threadIdx.x + st];
        }
        __syncthreads();
    }
    if (threadIdx.x == 0) {
        float inv = 1.f / (NB * LSEQ);
        float mu = sh0[0] * inv;
        float var = sh1[0] * inv - mu * mu;
        mv[o] = mu; mv[128 + o] = var;
    }
}

__global__ void bn_apply(const float* __restrict__ y2, const float* __restrict__ mv,
                         const float* __restrict__ gamma, const float* __restrict__ beta,
                         float* __restrict__ out)
{
    int idx = blockIdx.x * blockDim.x + threadIdx.x;
    if (idx >= NB*128*LSEQ) return;
    int o = (idx >> 12) & 127;
    float mu = mv[o], var = mv[128 + o];
    float v = (y2[idx] - mu) * rsqrtf(var + 1e-5f) * gamma[o] + beta[o];
    out[idx] = 0.5f * v * (1.f + erff(v * 0.70710678118654752440f));
}

// ---------------- launch ----------------
extern "C" void kernel_launch(void* const* d_in, const int* in_sizes, int n_in,
                              void* d_out, int out_size)
{
    const float* x        = (const float*)d_in[0];
    const float* skip     = (const float*)d_in[1];
    const float* up_w     = (const float*)d_in[2];
    const float* up_b     = (const float*)d_in[3];
    const float* in_proj  = (const float*)d_in[4];
    const float* c1w      = (const float*)d_in[5];
    const float* c1b      = (const float*)d_in[6];
    const float* xproj    = (const float*)d_in[7];
    const float* dtw      = (const float*)d_in[8];
    const float* dtb      = (const float*)d_in[9];
    const float* A_log    = (const float*)d_in[10];
    const float* Dp       = (const float*)d_in[11];
    const float* outw     = (const float*)d_in[12];
    const float* cw       = (const float*)d_in[13];
    const float* cb       = (const float*)d_in[14];
    const float* bng      = (const float*)d_in[15];
    const float* bnb      = (const float*)d_in[16];
    float* out = (float*)d_out;

    float *xc, *xi, *z, *u, *dbc, *dtv, *y, *xr, *y2, *mv, *S, *hs, *sd;
    float *wt1, *wt2, *wt3;
    cudaGetSymbolAddress((void**)&xc,  g_xc);
    cudaGetSymbolAddress((void**)&xi,  g_xi);
    cudaGetSymbolAddress((void**)&z,   g_z);
    cudaGetSymbolAddress((void**)&u,   g_u);
    cudaGetSymbolAddress((void**)&dbc, g_dbc);
    cudaGetSymbolAddress((void**)&dtv, g_dt);
    cudaGetSymbolAddress((void**)&y,   g_y);
    cudaGetSymbolAddress((void**)&xr,  g_xr);
    cudaGetSymbolAddress((void**)&y2,  g_y2);
    cudaGetSymbolAddress((void**)&mv,  g_mv);
    cudaGetSymbolAddress((void**)&S,   g_S);
    cudaGetSymbolAddress((void**)&hs,  g_hs);
    cudaGetSymbolAddress((void**)&sd,  g_sd);
    cudaGetSymbolAddress((void**)&wt1, g_wt1);
    cudaGetSymbolAddress((void**)&wt2, g_wt2);
    cudaGetSymbolAddress((void**)&wt3, g_wt3);

    // 0) one-time weight transposes
    transp<<<dim3(256/32, 1024/32), dim3(32, 8)>>>(in_proj, wt1, 1024, 256);
    transp<<<dim3(512/32,  256/32), dim3(32, 8)>>>(outw,    wt2,  256, 512);
    transp<<<dim3(512/32,        2), dim3(32, 8)>>>(xproj,   wt3,   48, 512);

    // 1) upsample GEMM (tf32 TC): C[512,1024] = up_w^T * x[b]
    gemm128_tc<EpiUp><<<dim3(8, 4, NB), 256>>>(
        up_w, 512, 0, x, 1024, (long)256*1024, 512, 1024, 256, EpiUp{xc, up_b});

    // 2) skip concat
    copy_skip<<<(NB*128*LSEQ + 255)/256, 256>>>(skip, xc);

    // 3) in_proj GEMM (tf32 TC): C[4096,1024] = xc^T * in_proj^T
    gemm128_tc<EpiXZ><<<dim3(8, 32, NB), 256>>>(
        xc, LSEQ, (long)DM*LSEQ, wt1, 1024, 0, LSEQ, 2*DI, DM, EpiXZ{xi, z});

    // 4) depthwise conv1d + silu
    conv1d_kernel<<<dim3(LSEQ/128, DI/32, NB), 256>>>(xi, c1w, c1b, u);

    // 5) x_proj GEMM (fp32): C[4096,48] per batch = u^T * xproj^T
    gemm_k<true, false, EpiDbc><<<dim3(1, 64, NB), 256>>>(
        u, LSEQ, (long)DI*LSEQ, wt3, 48, 0, LSEQ, 48, DI, EpiDbc{dbc});

    // 6) dt = softplus(dbc[:16]^T @ dtw^T + dtb)
    dt_kernel<<<NB*LSEQ/64, 256>>>(dbc, dtw, dtb, dtv);

    // 7) chunked selective scan
    scan_pass1<<<dim3(NCH, NB*DI/8), 128>>>(dtv, u, dbc, A_log, S, sd);
    scan_pass2<<<NB*DI/8, 128>>>(S, sd, A_log, hs);
    scan_pass3<<<dim3(NCH, NB*DI/8), 128>>>(dtv, u, dbc, z, A_log, Dp, hs, y);

    // 8) out_proj GEMM (tf32 TC) + residual
    gemm128_tc<EpiOut><<<dim3(2, 32, NB), 256>>>(
        y, LSEQ, (long)DI*LSEQ, wt2, 256, 0, LSEQ, DM, DI, EpiOut{xc, xr});

    // 9) 3x3 conv (256 blocks)
    conv3_kernel<<<dim3(16, 8, NB), 256>>>(xr, cw, cb, y2);

    // 10) batchnorm stats
    bn_stats<<<128, 256>>>(y2, mv);

    // 11) batchnorm apply + gelu
    bn_apply<<<(NB*128*LSEQ + 255)/256, 256>>>(y2, mv, bng, bnb, out);
}

// round 10
// speedup vs baseline: 1.3321x; 1.1704x over previous
#include <cuda_runtime.h>
#include <math.h>
#include <stdint.h>

#define LSEQ 4096
#define DM   256
#define DI   512
#define DS   16
#define NB   2
#define NCH  64   // scan chunks
#define CT   64   // chunk length

// ---------------- scratch (device globals; no runtime alloc allowed) ----------------
__device__ __align__(16) float g_xc [NB*DM*LSEQ];    // (b, c=256, l)
__device__ __align__(16) float g_xi [NB*DI*LSEQ];    // (b, d, l)
__device__ __align__(16) float g_z  [NB*DI*LSEQ];    // (b, d, l)
__device__ __align__(16) float g_u  [NB*DI*LSEQ];    // (b, d, l)
__device__ __align__(16) float g_dbc[48*NB*LSEQ];    // (j=48, b*l)
__device__ __align__(16) float g_dt [NB*DI*LSEQ];    // (b, d, l)
__device__ __align__(16) float g_y  [NB*DI*LSEQ];    // (b, d, l)
__device__ __align__(16) float g_xr [NB*DM*LSEQ];    // (b, c, l)
__device__ __align__(16) float g_y2 [NB*128*LSEQ];   // (b, o, l)
__device__ __align__(16) float g_mv [256];
__device__ __align__(16) float g_S  [NB*DI*NCH*DS];
__device__ __align__(16) float g_hs [NB*DI*NCH*DS];
__device__ __align__(16) float g_sd [NB*DI*NCH];
__device__ __align__(16) float g_wt1[256*1024];      // in_proj_w^T  (k=256, n=1024)
__device__ __align__(16) float g_wt2[512*256];       // out_proj_w^T (k=512, n=256)
__device__ __align__(16) float g_wt3[512*48 + 64];   // x_proj_w^T   (k=512, n=48) + pad
__device__ __align__(16) float g_wt4[2304*128];      // conv_w^T     (k=c*9+t, o=128)

// ---------------- cp.async helpers ----------------
__device__ __forceinline__ void cp16(uint32_t dst, const float* src) {
    asm volatile("cp.async.cg.shared.global [%0], [%1], 16;\n" :: "r"(dst), "l"(src));
}
__device__ __forceinline__ void cp16z(uint32_t dst, const float* src, int sz) {
    asm volatile("cp.async.cg.shared.global [%0], [%1], 16, %2;\n" :: "r"(dst), "l"(src), "r"(sz));
}
__device__ __forceinline__ void cp_commit() {
    asm volatile("cp.async.commit_group;\n");
}
__device__ __forceinline__ void cp_wait_dyn(int allow) {
    if (allow <= 0)      asm volatile("cp.async.wait_group 0;\n");
    else if (allow == 1) asm volatile("cp.async.wait_group 1;\n");
    else                 asm volatile("cp.async.wait_group 2;\n");
}

// ---------------- tf32 helpers ----------------
__device__ __forceinline__ uint32_t f2tf(float f) {
    uint32_t r;
    asm("cvt.rna.tf32.f32 %0, %1;" : "=r"(r) : "f"(f));
    return r;
}
__device__ __forceinline__ void mma_tf32(float* c, const uint32_t* a, const uint32_t* b) {
    asm volatile(
        "mma.sync.aligned.m16n8k8.row.col.f32.tf32.tf32.f32 "
        "{%0,%1,%2,%3}, {%4,%5,%6,%7}, {%8,%9}, {%0,%1,%2,%3};"
        : "+f"(c[0]), "+f"(c[1]), "+f"(c[2]), "+f"(c[3])
        : "r"(a[0]), "r"(a[1]), "r"(a[2]), "r"(a[3]), "r"(b[0]), "r"(b[1]));
}

// ================= 128x128x8, 4-stage cp.async, TF32 tensor-core GEMM =================
template<class Epi>
__global__ __launch_bounds__(256)
void gemm128_tc(const float* __restrict__ A, int lda, long sA,
                const float* __restrict__ B, int ldb, long sB,
                int M, int N, int K, Epi epi)
{
    __shared__ float As[4][8][132];
    __shared__ float Bs[4][8][132];
    const int tid = threadIdx.x;
    const int bz  = blockIdx.z;
    const float* Ab = A + (size_t)bz * sA;
    const float* Bb = B + (size_t)bz * sB;
    const int m0 = blockIdx.y * 128;
    const int n0 = blockIdx.x * 128;

    const int warp = tid >> 5;
    const int lane = tid & 31;
    const int gid  = lane >> 2;
    const int tig  = lane & 3;
    const int wm   = (warp >> 2) * 64;
    const int wn   = (warp & 3) * 32;

    const int ak = tid >> 5;
    const int am = (tid & 31) << 2;

    float acc[4][4][4];
#pragma unroll
    for (int i = 0; i < 4; i++)
#pragma unroll
        for (int j = 0; j < 4; j++)
#pragma unroll
            for (int q = 0; q < 4; q++) acc[i][j][q] = 0.f;

    const int nt = K >> 3;

    auto ldtile = [&](int st, int k0) {
        uint32_t da = (uint32_t)__cvta_generic_to_shared(&As[st][ak][am]);
        uint32_t db = (uint32_t)__cvta_generic_to_shared(&Bs[st][ak][am]);
        cp16(da, Ab + (size_t)(k0 + ak)*lda + m0 + am);
        cp16(db, Bb + (size_t)(k0 + ak)*ldb + n0 + am);
        cp_commit();
    };

    ldtile(0, 0);
    ldtile(1, 8);
    ldtile(2, 16);

    for (int kt = 0; kt < nt; ++kt) {
        int rem = nt - 1 - kt;
        cp_wait_dyn(rem > 2 ? 2 : rem);
        __syncthreads();
        if (kt + 3 < nt) ldtile((kt + 3) & 3, (kt + 3) << 3);

        const int st = kt & 3;
        uint32_t afr[4][4], bfr[4][2];
#pragma unroll
        for (int mt = 0; mt < 4; ++mt) {
            int mb = wm + mt*16 + gid;
            afr[mt][0] = f2tf(As[st][tig  ][mb]);
            afr[mt][1] = f2tf(As[st][tig  ][mb + 8]);
            afr[mt][2] = f2tf(As[st][tig+4][mb]);
            afr[mt][3] = f2tf(As[st][tig+4][mb + 8]);
        }
#pragma unroll
        for (int ntl = 0; ntl < 4; ++ntl) {
            int nb = wn + ntl*8 + gid;
            bfr[ntl][0] = f2tf(Bs[st][tig  ][nb]);
            bfr[ntl][1] = f2tf(Bs[st][tig+4][nb]);
        }
#pragma unroll
        for (int mt = 0; mt < 4; ++mt)
#pragma unroll
            for (int ntl = 0; ntl < 4; ++ntl)
                mma_tf32(acc[mt][ntl], afr[mt], bfr[ntl]);
    }

#pragma unroll
    for (int mt = 0; mt < 4; ++mt) {
        int mb = m0 + wm + mt*16;
#pragma unroll
        for (int ntl = 0; ntl < 4; ++ntl) {
            int nb = n0 + wn + ntl*8;
            epi(bz, mb + gid,     nb + 2*tig,     acc[mt][ntl][0]);
            epi(bz, mb + gid,     nb + 2*tig + 1, acc[mt][ntl][1]);
            epi(bz, mb + gid + 8, nb + 2*tig,     acc[mt][ntl][2]);
            epi(bz, mb + gid + 8, nb + 2*tig + 1, acc[mt][ntl][3]);
        }
    }
}

// ================= conv3x3 as TF32 implicit GEMM =================
// Per block: out[b][0:128][h][0:64]. K = 256ch*9taps = 2304, chunks of 8ch (K=72).
// A (weights^T, k-major) streamed via cp.async; B fragments read from input slab
// in smem with the (di,dj) shift applied at load time.
__global__ __launch_bounds__(256)
void conv3_tc(const float* __restrict__ xr, const float* __restrict__ Wt,
              const float* __restrict__ bias, float* __restrict__ y2)
{
    extern __shared__ float sm[];
    // A: 2 bufs x 72 x 132 ; I: 2 bufs x 24 x 68
    float* Asm = sm;                       // 2*9504
    float* Ism = sm + 2*9504;              // 2*1632

    const int b = blockIdx.y;
    const int h = blockIdx.x;              // output row 0..63
    const int tid = threadIdx.x;
    const int warp = tid >> 5;
    const int lane = tid & 31;
    const int gid  = lane >> 2;
    const int tig  = lane & 3;
    const int wm   = (warp >> 1) * 32;     // 0,32,64,96
    const int wn   = (warp & 1) * 32;      // 0,32

    float acc[2][4][4];
#pragma unroll
    for (int i = 0; i < 2; i++)
#pragma unroll
        for (int j = 0; j < 4; j++)
#pragma unroll
            for (int q = 0; q < 4; q++) acc[i][j][q] = 0.f;

    const float* xrb = xr + (size_t)b * DM * LSEQ;

    auto ld_chunk = [&](int buf, int c0) {
        float* Ab = Asm + buf*9504;
#pragma unroll
        for (int i = 0; i < 9; ++i) {
            int e  = i*256 + tid;          // 0..2303
            int k  = e >> 5;               // 0..71
            int m4 = (e & 31) << 2;
            cp16((uint32_t)__cvta_generic_to_shared(Ab + k*132 + m4),
                 Wt + (size_t)(c0*9 + k)*128 + m4);
        }
        float* Ib = Ism + buf*1632;
#pragma unroll
        for (int i = 0; i < 2; ++i) {
            int e = i*256 + tid;
            if (e < 384) {
                int row = e >> 4;          // 0..23 = ci*3+di
                int di  = row % 3;
                int ci  = row / 3;
                int x4  = (e & 15) << 2;
                int hh  = h + di - 1;
                int ok  = (hh >= 0 && hh < 64) ? 16 : 0;
                int hc  = ok ? hh : 0;
                cp16z((uint32_t)__cvta_generic_to_shared(Ib + row*68 + x4),
                      xrb + (size_t)(c0 + ci)*LSEQ + hc*64 + x4, ok);
            }
        }
        cp_commit();
    };

    ld_chunk(0, 0);

    for (int c = 0; c < 32; ++c) {
        cp_wait_dyn(0);
        __syncthreads();
        if (c + 1 < 32) ld_chunk((c + 1) & 1, (c + 1) * 8);

        const float* Ab = Asm + (c & 1)*9504;
        const float* Ib = Ism + (c & 1)*1632;

#pragma unroll
        for (int kk = 0; kk < 9; ++kk) {
            const int kb = kk * 8;
            uint32_t afr[2][4], bfr[4][2];
#pragma unroll
            for (int mt = 0; mt < 2; ++mt) {
                int mb = wm + mt*16 + gid;
                afr[mt][0] = f2tf(Ab[(kb + tig    )*132 + mb]);
                afr[mt][1] = f2tf(Ab[(kb + tig    )*132 + mb + 8]);
                afr[mt][2] = f2tf(Ab[(kb + tig + 4)*132 + mb]);
                afr[mt][3] = f2tf(Ab[(kb + tig + 4)*132 + mb + 8]);
            }
            // B fragment: k -> (ci, di, dj); value = in[ci][di][w+dj-1] (0 OOB)
            int k0 = kb + tig, k1 = kb + tig + 4;
            int ci0 = k0 / 9, t0 = k0 - ci0*9, di0 = t0 / 3, dj0 = t0 - di0*3;
            int ci1 = k1 / 9, t1 = k1 - ci1*9, di1 = t1 / 3, dj1 = t1 - di1*3;
            const float* r0 = Ib + (ci0*3 + di0)*68;
            const float* r1 = Ib + (ci1*3 + di1)*68;
#pragma unroll
            for (int ntl = 0; ntl < 4; ++ntl) {
                int w = wn + ntl*8 + gid;
                int x0 = w + dj0 - 1;
                int x1 = w + dj1 - 1;
                float v0 = (x0 >= 0 && x0 < 64) ? r0[x0] : 0.f;
                float v1 = (x1 >= 0 && x1 < 64) ? r1[x1] : 0.f;
                bfr[ntl][0] = f2tf(v0);
                bfr[ntl][1] = f2tf(v1);
            }
#pragma unroll
            for (int mt = 0; mt < 2; ++mt)
#pragma unroll
                for (int ntl = 0; ntl < 4; ++ntl)
                    mma_tf32(acc[mt][ntl], afr[mt], bfr[ntl]);
        }
        __syncthreads();
    }

#pragma unroll
    for (int mt = 0; mt < 2; ++mt) {
        int ob = wm + mt*16;
#pragma unroll
        for (int ntl = 0; ntl < 4; ++ntl) {
            int wb = wn + ntl*8 + 2*tig;
            float b0 = bias[ob + gid];
            float b1 = bias[ob + gid + 8];
            size_t base0 = ((size_t)b*128 + ob + gid    )*LSEQ + h*64;
            size_t base1 = ((size_t)b*128 + ob + gid + 8)*LSEQ + h*64;
            y2[base0 + wb    ] = acc[mt][ntl][0] + b0;
            y2[base0 + wb + 1] = acc[mt][ntl][1] + b0;
            y2[base1 + wb    ] = acc[mt][ntl][2] + b1;
            y2[base1 + wb + 1] = acc[mt][ntl][3] + b1;
        }
    }
}

// ================= small generic 64x64x16 GEMM (x_proj: N=48) =================
template<bool TA, bool TB, class Epi>
__global__ __launch_bounds__(256)
void gemm_k(const float* __restrict__ A, int lda, long sA,
            const float* __restrict__ B, int ldb, long sB,
            int M, int N, int K, Epi epi)
{
    __shared__ float As[16][68];
    __shared__ float Bs[16][68];
    const int tid = threadIdx.x;
    const int bz  = blockIdx.z;
    const float* Ab = A + (size_t)bz * sA;
    const float* Bb = B + (size_t)bz * sB;
    const int m0 = blockIdx.y * 64;
    const int n0 = blockIdx.x * 64;
    const int tx = tid & 15, ty = tid >> 4;

    float acc[4][4];
#pragma unroll
    for (int i = 0; i < 4; i++)
#pragma unroll
        for (int j = 0; j < 4; j++) acc[i][j] = 0.f;

    for (int k0 = 0; k0 < K; k0 += 16) {
        if (TA) {
            int k  = tid >> 4;
            int mq = (tid & 15) << 2;
            float4 v = *reinterpret_cast<const float4*>(Ab + (size_t)(k0 + k)*lda + m0 + mq);
            *reinterpret_cast<float4*>(&As[k][mq]) = v;
        } else {
            int m  = tid >> 2;
            int kq = (tid & 3) << 2;
            float4 v = *reinterpret_cast<const float4*>(Ab + (size_t)(m0 + m)*lda + k0 + kq);
            As[kq+0][m] = v.x; As[kq+1][m] = v.y; As[kq+2][m] = v.z; As[kq+3][m] = v.w;
        }
        if (TB) {
            int nn = tid >> 2;
            int kq = (tid & 3) << 2;
            float4 v = make_float4(0.f,0.f,0.f,0.f);
            if (n0 + nn < N)
                v = *reinterpret_cast<const float4*>(Bb + (size_t)(n0 + nn)*ldb + k0 + kq);
            Bs[kq+0][nn] = v.x; Bs[kq+1][nn] = v.y; Bs[kq+2][nn] = v.z; Bs[kq+3][nn] = v.w;
        } else {
            int k  = tid >> 4;
            int nq = (tid & 15) << 2;
            float4 v = *reinterpret_cast<const float4*>(Bb + (size_t)(k0 + k)*ldb + n0 + nq);
            *reinterpret_cast<float4*>(&Bs[k][nq]) = v;
        }
        __syncthreads();
#pragma unroll
        for (int kk = 0; kk < 16; ++kk) {
            float4 a4 = *reinterpret_cast<const float4*>(&As[kk][ty << 2]);
            float4 b4 = *reinterpret_cast<const float4*>(&Bs[kk][tx << 2]);
            float a[4] = {a4.x, a4.y, a4.z, a4.w};
            float b[4] = {b4.x, b4.y, b4.z, b4.w};
#pragma unroll
            for (int i = 0; i < 4; i++)
#pragma unroll
                for (int j = 0; j < 4; j++) acc[i][j] += a[i] * b[j];
        }
        __syncthreads();
    }
#pragma unroll
    for (int i = 0; i < 4; i++) {
        int mi = m0 + (ty << 2) + i;
#pragma unroll
        for (int j = 0; j < 4; j++) {
            int ni = n0 + (tx << 2) + j;
            if (mi < M && ni < N) epi(bz, mi, ni, acc[i][j]);
        }
    }
}

// ---------------- weight transpose: in (R,C) -> out (C,R) ----------------
__global__ void transp(const float* __restrict__ in, float* __restrict__ out, int R, int C) {
    __shared__ float t[32][33];
    int r0 = blockIdx.y * 32, c0 = blockIdx.x * 32;
    int x = threadIdx.x, y = threadIdx.y;
    for (int i = y; i < 32; i += 8) {
        int r = r0 + i, c = c0 + x;
        t[i][x] = (r < R && c < C) ? in[(size_t)r*C + c] : 0.f;
    }
    __syncthreads();
    for (int i = y; i < 32; i += 8) {
        int c = c0 + i, r = r0 + x;
        if (c < C && r < R) out[(size_t)c*R + r] = t[x][i];
    }
}

// ---------------- epilogues ----------------
struct EpiUp {
    float* xc; const float* up_b;
    __device__ void operator()(int b, int m, int n, float v) const {
        int o = m >> 2, i = (m >> 1) & 1, j = m & 1;
        int h = n >> 5, w = n & 31;
        xc[((size_t)b*DM + o)*LSEQ + (2*h + i)*64 + (2*w + j)] = v + up_b[o];
    }
};
struct EpiXZ {
    float* xi; float* z;
    __device__ void operator()(int b, int m, int n, float v) const {
        if (n < DI) xi[((size_t)b*DI + n)*LSEQ + m] = v;
        else        z [((size_t)b*DI + (n - DI))*LSEQ + m] = v;
    }
};
struct EpiDbc {
    float* dbc;
    __device__ void operator()(int b, int m, int n, float v) const {
        dbc[(size_t)n*(NB*LSEQ) + b*LSEQ + m] = v;
    }
};
struct EpiOut {
    const float* xc; float* xr;
    __device__ void operator()(int b, int m, int n, float v) const {
        size_t idx = ((size_t)b*DM + n)*LSEQ + m;
        xr[idx] = xc[idx] + v;
    }
};

// ---------------- skip concat copy ----------------
__global__ void copy_skip(const float* __restrict__ skip, float* __restrict__ xc) {
    int idx = blockIdx.x * blockDim.x + threadIdx.x;
    int total = NB * 128 * LSEQ;
    if (idx >= total) return;
    int b = idx / (128 * LSEQ);
    int rem = idx - b * (128 * LSEQ);
    xc[((size_t)b*DM + 128)*LSEQ + rem] = skip[idx];
}

// ---------------- depthwise causal conv1d + silu (coalesced) ----------------
__global__ __launch_bounds__(256)
void conv1d_kernel(const float* __restrict__ xi, const float* __restrict__ w,
                   const float* __restrict__ bias, float* __restrict__ u)
{
    __shared__ float s[32][132];
    __shared__ float sw[32][4];
    __shared__ float sb[32];
    int b  = blockIdx.z;
    int d0 = blockIdx.y * 32;
    int l0 = blockIdx.x * 128;
    int tid = threadIdx.x;
    for (int e = tid; e < 32*132; e += 256) {
        int dd = e / 132, li = e - dd*132;
        if (li < 131) {
            int l = l0 - 3 + li;
            s[dd][li] = (l >= 0 && l < LSEQ) ? xi[((size_t)b*DI + d0 + dd)*LSEQ + l] : 0.f;
        }
    }
    if (tid < 128) sw[tid >> 2][tid & 3] = w[(d0 + (tid >> 2))*4 + (tid & 3)];
    if (tid < 32)  sb[tid] = bias[d0 + tid];
    __syncthreads();
#pragma unroll
    for (int it = 0; it < 16; ++it) {
        int idx = it*256 + tid;
        int dd = idx >> 7, li = idx & 127;
        float a = s[dd][li]*sw[dd][0] + s[dd][li+1]*sw[dd][1]
                + s[dd][li+2]*sw[dd][2] + s[dd][li+3]*sw[dd][3] + sb[dd];
        float sv = a / (1.f + __expf(-a));
        u[((size_t)b*DI + d0 + dd)*LSEQ + l0 + li] = sv;
    }
}

// ---------------- dt = softplus(dbc[:,:16] @ dtw^T + dtb), out (b,d,l) ----------------
__global__ __launch_bounds__(256)
void dt_kernel(const float* __restrict__ dbc, const float* __restrict__ dtw,
               const float* __restrict__ dtb, float* __restrict__ dt)
{
    __shared__ float swt[DI*16];
    __shared__ float sbc[16*64];
    __shared__ float sbias[DI];
    int bl0 = blockIdx.x * 64;
    int tid = threadIdx.x;
    for (int i = tid; i < DI*16; i += 256) swt[i] = dtw[i];
    for (int i = tid; i < DI; i += 256) sbias[i] = dtb[i];
    for (int i = tid; i < 16*64; i += 256) {
        int r = i >> 6, li = i & 63;
        sbc[i] = dbc[(size_t)r*(NB*LSEQ) + bl0 + li];
    }
    __syncthreads();
    int b  = bl0 >> 12;
    int l0 = bl0 & (LSEQ - 1);
#pragma unroll 4
    for (int it = 0; it < 128; ++it) {
        int idx = it*256 + tid;
        int d = idx >> 6, li = idx & 63;
        float acc = sbias[d];
#pragma unroll
        for (int r = 0; r < 16; ++r) acc += swt[d*16 + r] * sbc[r*64 + li];
        float sp = (acc > 20.f) ? acc : log1pf(__expf(acc));
        dt[((size_t)b*DI + d)*LSEQ + l0 + li] = sp;
    }
}

// ================= chunked selective scan =================
__global__ __launch_bounds__(128)
void scan_pass1(const float* __restrict__ dt, const float* __restrict__ u,
                const float* __restrict__ dbc, const float* __restrict__ A_log,
                float* __restrict__ S, float* __restrict__ sd)
{
    int lane = threadIdx.x & 31;
    int n    = lane & 15;
    int half = lane >> 4;
    int warp = threadIdx.x >> 5;
    int gch  = blockIdx.y * 8 + warp * 2 + half;
    int c    = blockIdx.x;
    int b = gch >> 9, d = gch & (DI - 1);

    float A = -__expf(A_log[d*DS + n]);
    const float* dtp = dt  + (size_t)gch*LSEQ + c*CT;
    const float* up  = u   + (size_t)gch*LSEQ + c*CT;
    const float* bp  = dbc + (size_t)(16 + n)*(NB*LSEQ) + b*LSEQ + c*CT;

    float h = 0.f, sda = 0.f;
#pragma unroll 8
    for (int l = 0; l < CT; ++l) {
        float dtv = dtp[l], uv = up[l], bn = bp[l];
        float dA = __expf(dtv * A);
        h = dA * h + (dtv * uv) * bn;
        sda += dtv;
    }
    S[((size_t)gch*NCH + c)*DS + n] = h;
    if (n == 0) sd[(size_t)gch*NCH + c] = sda;
}

__global__ __launch_bounds__(128)
void scan_pass2(const float* __restrict__ S, const float* __restrict__ sd,
                const float* __restrict__ A_log, float* __restrict__ hs)
{
    int lane = threadIdx.x & 31;
    int n    = lane & 15;
    int half = lane >> 4;
    int warp = threadIdx.x >> 5;
    int gch  = blockIdx.x * 8 + warp * 2 + half;
    int d = gch & (DI - 1);
    float A = -__expf(A_log[d*DS + n]);
    float h = 0.f;
    for (int c = 0; c < NCH; ++c) {
        size_t idx = ((size_t)gch*NCH + c)*DS + n;
        hs[idx] = h;
        float P = __expf(A * sd[(size_t)gch*NCH + c]);
        h = P * h + S[idx];
    }
}

__global__ __launch_bounds__(128)
void scan_pass3(const float* __restrict__ dt, const float* __restrict__ u,
                const float* __restrict__ dbc, const float* __restrict__ z,
                const float* __restrict__ A_log, const float* __restrict__ Dp,
                const float* __restrict__ hs, float* __restrict__ y)
{
    int lane = threadIdx.x & 31;
    int n    = lane & 15;
    int half = lane >> 4;
    int warp = threadIdx.x >> 5;
    int gch  = blockIdx.y * 8 + warp * 2 + half;
    int c    = blockIdx.x;
    int b = gch >> 9, d = gch & (DI - 1);

    float A  = -__expf(A_log[d*DS + n]);
    float Dv = Dp[d];
    const float* dtp = dt  + (size_t)gch*LSEQ + c*CT;
    const float* up  = u   + (size_t)gch*LSEQ + c*CT;
    const float* zp  = z   + (size_t)gch*LSEQ + c*CT;
    const float* bp  = dbc + (size_t)(16 + n)*(NB*LSEQ) + b*LSEQ + c*CT;
    const float* cp  = dbc + (size_t)(32 + n)*(NB*LSEQ) + b*LSEQ + c*CT;
    float*       yp  = y   + (size_t)gch*LSEQ + c*CT;

    float h = hs[((size_t)gch*NCH + c)*DS + n];
#pragma unroll 4
    for (int l = 0; l < CT; ++l) {
        float dtv = dtp[l], uv = up[l];
        float bn = bp[l], cn = cp[l];
        float dA = __expf(dtv * A);
        h = dA * h + (dtv * uv) * bn;
        float yv = h * cn;
        yv += __shfl_xor_sync(0xffffffffu, yv, 1);
        yv += __shfl_xor_sync(0xffffffffu, yv, 2);
        yv += __shfl_xor_sync(0xffffffffu, yv, 4);
        yv += __shfl_xor_sync(0xffffffffu, yv, 8);
        if (n == 0) {
            float out = yv + uv * Dv;
            float zv = zp[l];
            float sg = zv / (1.f + __expf(-zv));
            yp[l] = out * sg;
        }
    }
}

// ---------------- batchnorm stats + apply + gelu ----------------
__global__ void bn_stats(const float* __restrict__ y2, float* __restrict__ mv) {
    int o = blockIdx.x;
    float s = 0.f, s2 = 0.f;
    for (int i = threadIdx.x; i < NB*LSEQ; i += 256) {
        int b = i >> 12, l = i & (LSEQ - 1);
        float v = y2[((size_t)b*128 + o)*LSEQ + l];
        s += v; s2 += v*v;
    }
    __shared__ float sh0[256], sh1[256];
    sh0[threadIdx.x] = s; sh1[threadIdx.x] = s2;
    __syncthreads();
    for (int st = 128; st > 0; st >>= 1) {
        if (threadIdx.x < st) {
            sh0[threadIdx.x] += sh0[threadIdx.x + st];
            sh1[threadIdx.x] += sh1[threadIdx.x + st];
        }
        __syncthreads();
    }
    if (threadIdx.x == 0) {
        float inv = 1.f / (NB * LSEQ);
        float mu = sh0[0] * inv;
        float var = sh1[0] * inv - mu * mu;
        mv[o] = mu; mv[128 + o] = var;
    }
}

__global__ void bn_apply(const float* __restrict__ y2, const float* __restrict__ mv,
                         const float* __restrict__ gamma, const float* __restrict__ beta,
                         float* __restrict__ out)
{
    int idx = blockIdx.x * blockDim.x + threadIdx.x;
    if (idx >= NB*128*LSEQ) return;
    int o = (idx >> 12) & 127;
    float mu = mv[o], var = mv[128 + o];
    float v = (y2[idx] - mu) * rsqrtf(var + 1e-5f) * gamma[o] + beta[o];
    out[idx] = 0.5f * v * (1.f + erff(v * 0.70710678118654752440f));
}

// ---------------- launch ----------------
extern "C" void kernel_launch(void* const* d_in, const int* in_sizes, int n_in,
                              void* d_out, int out_size)
{
    const float* x        = (const float*)d_in[0];
    const float* skip     = (const float*)d_in[1];
    const float* up_w     = (const float*)d_in[2];
    const float* up_b     = (const float*)d_in[3];
    const float* in_proj  = (const float*)d_in[4];
    const float* c1w      = (const float*)d_in[5];
    const float* c1b      = (const float*)d_in[6];
    const float* xproj    = (const float*)d_in[7];
    const float* dtw      = (const float*)d_in[8];
    const float* dtb      = (const float*)d_in[9];
    const float* A_log    = (const float*)d_in[10];
    const float* Dp       = (const float*)d_in[11];
    const float* outw     = (const float*)d_in[12];
    const float* cw       = (const float*)d_in[13];
    const float* cb       = (const float*)d_in[14];
    const float* bng      = (const float*)d_in[15];
    const float* bnb      = (const float*)d_in[16];
    float* out = (float*)d_out;

    float *xc, *xi, *z, *u, *dbc, *dtv, *y, *xr, *y2, *mv, *S, *hs, *sd;
    float *wt1, *wt2, *wt3, *wt4;
    cudaGetSymbolAddress((void**)&xc,  g_xc);
    cudaGetSymbolAddress((void**)&xi,  g_xi);
    cudaGetSymbolAddress((void**)&z,   g_z);
    cudaGetSymbolAddress((void**)&u,   g_u);
    cudaGetSymbolAddress((void**)&dbc, g_dbc);
    cudaGetSymbolAddress((void**)&dtv, g_dt);
    cudaGetSymbolAddress((void**)&y,   g_y);
    cudaGetSymbolAddress((void**)&xr,  g_xr);
    cudaGetSymbolAddress((void**)&y2,  g_y2);
    cudaGetSymbolAddress((void**)&mv,  g_mv);
    cudaGetSymbolAddress((void**)&S,   g_S);
    cudaGetSymbolAddress((void**)&hs,  g_hs);
    cudaGetSymbolAddress((void**)&sd,  g_sd);
    cudaGetSymbolAddress((void**)&wt1, g_wt1);
    cudaGetSymbolAddress((void**)&wt2, g_wt2);
    cudaGetSymbolAddress((void**)&wt3, g_wt3);
    cudaGetSymbolAddress((void**)&wt4, g_wt4);

    const int C3_SMEM = (2*9504 + 2*1632) * 4;   // 89088 bytes
    cudaFuncSetAttribute(conv3_tc, cudaFuncAttributeMaxDynamicSharedMemorySize, C3_SMEM);

    // 0) one-time weight transposes
    transp<<<dim3(256/32, 1024/32), dim3(32, 8)>>>(in_proj, wt1, 1024, 256);
    transp<<<dim3(512/32,  256/32), dim3(32, 8)>>>(outw,    wt2,  256, 512);
    transp<<<dim3(512/32,        2), dim3(32, 8)>>>(xproj,   wt3,   48, 512);
    transp<<<dim3(2304/32,       4), dim3(32, 8)>>>(cw,      wt4,  128, 2304);

    // 1) upsample GEMM (tf32 TC)
    gemm128_tc<EpiUp><<<dim3(8, 4, NB), 256>>>(
        up_w, 512, 0, x, 1024, (long)256*1024, 512, 1024, 256, EpiUp{xc, up_b});

    // 2) skip concat
    copy_skip<<<(NB*128*LSEQ + 255)/256, 256>>>(skip, xc);

    // 3) in_proj GEMM (tf32 TC)
    gemm128_tc<EpiXZ><<<dim3(8, 32, NB), 256>>>(
        xc, LSEQ, (long)DM*LSEQ, wt1, 1024, 0, LSEQ, 2*DI, DM, EpiXZ{xi, z});

    // 4) depthwise conv1d + silu
    conv1d_kernel<<<dim3(LSEQ/128, DI/32, NB), 256>>>(xi, c1w, c1b, u);

    // 5) x_proj GEMM (fp32)
    gemm_k<true, false, EpiDbc><<<dim3(1, 64, NB), 256>>>(
        u, LSEQ, (long)DI*LSEQ, wt3, 48, 0, LSEQ, 48, DI, EpiDbc{dbc});

    // 6) dt = softplus(dbc[:16]^T @ dtw^T + dtb)
    dt_kernel<<<NB*LSEQ/64, 256>>>(dbc, dtw, dtb, dtv);

    // 7) chunked selective scan
    scan_pass1<<<dim3(NCH, NB*DI/8), 128>>>(dtv, u, dbc, A_log, S, sd);
    scan_pass2<<<NB*DI/8, 128>>>(S, sd, A_log, hs);
    scan_pass3<<<dim3(NCH, NB*DI/8), 128>>>(dtv, u, dbc, z, A_log, Dp, hs, y);

    // 8) out_proj GEMM (tf32 TC) + residual
    gemm128_tc<EpiOut><<<dim3(2, 32, NB), 256>>>(
        y, LSEQ, (long)DI*LSEQ, wt2, 256, 0, LSEQ, DM, DI, EpiOut{xc, xr});

    // 9) 3x3 conv as TF32 implicit GEMM
    conv3_tc<<<dim3(64, NB), 256, C3_SMEM>>>(xr, wt4, cb, y2);

    // 10) batchnorm stats
    bn_stats<<<128, 256>>>(y2, mv);

    // 11) batchnorm apply + gelu
    bn_apply<<<(NB*128*LSEQ + 255)/256, 256>>>(y2, mv, bng, bnb, out);
}

// round 11
// speedup vs baseline: 1.3592x; 1.0203x over previous
#include <cuda_runtime.h>
#include <math.h>
#include <stdint.h>

#define LSEQ 4096
#define DM   256
#define DI   512
#define DS   16
#define NB   2
#define NCH  64   // scan chunks
#define CT   64   // chunk length

// ---------------- scratch (device globals; no runtime alloc allowed) ----------------
__device__ __align__(16) float g_xc [NB*DM*LSEQ];    // (b, c=256, l)
__device__ __align__(16) float g_xi [NB*DI*LSEQ];    // (b, d, l)
__device__ __align__(16) float g_z  [NB*DI*LSEQ];    // (b, d, l)
__device__ __align__(16) float g_u  [NB*DI*LSEQ];    // (b, d, l)
__device__ __align__(16) float g_dbc[48*NB*LSEQ];    // (j=48, b*l)
__device__ __align__(16) float g_dt [NB*DI*LSEQ];    // (b, d, l)
__device__ __align__(16) float g_y  [NB*DI*LSEQ];    // (b, d, l)
__device__ __align__(16) float g_xr [NB*DM*LSEQ];    // (b, c, l)
__device__ __align__(16) float g_y2 [NB*128*LSEQ];   // (b, o, l)
__device__ __align__(16) float g_mv [256];
__device__ __align__(16) float g_S  [NB*DI*NCH*DS];
__device__ __align__(16) float g_hs [NB*DI*NCH*DS];
__device__ __align__(16) float g_sd [NB*DI*NCH];
__device__ __align__(16) float g_wt1[256*1024];      // in_proj_w^T  (k=256, n=1024), tf32-rounded
__device__ __align__(16) float g_wt2[512*256];       // out_proj_w^T (k=512, n=256),  tf32-rounded
__device__ __align__(16) float g_wt3[512*128];       // x_proj_w^T   (k=512, n=128 pad), tf32-rounded
__device__ __align__(16) float g_wt4[2304*128];      // conv_w^T     (k=c*9+t, o=128), tf32-rounded
__device__ __align__(16) float g_upw[256*512];       // up_w tf32-rounded (k=256 rows x m=512)

// ---------------- cp.async helpers ----------------
__device__ __forceinline__ void cp16(uint32_t dst, const float* src) {
    asm volatile("cp.async.cg.shared.global [%0], [%1], 16;\n" :: "r"(dst), "l"(src));
}
__device__ __forceinline__ void cp16z(uint32_t dst, const float* src, int sz) {
    asm volatile("cp.async.cg.shared.global [%0], [%1], 16, %2;\n" :: "r"(dst), "l"(src), "r"(sz));
}
__device__ __forceinline__ void cp_commit() {
    asm volatile("cp.async.commit_group;\n");
}
__device__ __forceinline__ void cp_wait_dyn(int allow) {
    if (allow <= 0)      asm volatile("cp.async.wait_group 0;\n");
    else if (allow == 1) asm volatile("cp.async.wait_group 1;\n");
    else                 asm volatile("cp.async.wait_group 2;\n");
}

// ---------------- tf32 helpers ----------------
__device__ __forceinline__ uint32_t f2tf(float f) {
    uint32_t r;
    asm("cvt.rna.tf32.f32 %0, %1;" : "=r"(r) : "f"(f));
    return r;
}
__device__ __forceinline__ float round_tf(float f) {
    return __uint_as_float(f2tf(f));
}
__device__ __forceinline__ void mma_tf32(float* c, const uint32_t* a, const uint32_t* b) {
    asm volatile(
        "mma.sync.aligned.m16n8k8.row.col.f32.tf32.tf32.f32 "
        "{%0,%1,%2,%3}, {%4,%5,%6,%7}, {%8,%9}, {%0,%1,%2,%3};"
        : "+f"(c[0]), "+f"(c[1]), "+f"(c[2]), "+f"(c[3])
        : "r"(a[0]), "r"(a[1]), "r"(a[2]), "r"(a[3]), "r"(b[0]), "r"(b[1]));
}

// ================= 128x128x8, 4-stage cp.async, TF32 tensor-core GEMM =================
// CA/CB: apply rna tf32 conversion to A/B fragments (false = operand pre-rounded).
template<bool CA, bool CB, class Epi>
__global__ __launch_bounds__(256)
void gemm128_tc(const float* __restrict__ A, int lda, long sA,
                const float* __restrict__ B, int ldb, long sB,
                int M, int N, int K, Epi epi)
{
    __shared__ float As[4][8][132];
    __shared__ float Bs[4][8][132];
    const int tid = threadIdx.x;
    const int bz  = blockIdx.z;
    const float* Ab = A + (size_t)bz * sA;
    const float* Bb = B + (size_t)bz * sB;
    const int m0 = blockIdx.y * 128;
    const int n0 = blockIdx.x * 128;

    const int warp = tid >> 5;
    const int lane = tid & 31;
    const int gid  = lane >> 2;
    const int tig  = lane & 3;
    const int wm   = (warp >> 2) * 64;
    const int wn   = (warp & 3) * 32;

    const int ak = tid >> 5;
    const int am = (tid & 31) << 2;

    float acc[4][4][4];
#pragma unroll
    for (int i = 0; i < 4; i++)
#pragma unroll
        for (int j = 0; j < 4; j++)
#pragma unroll
            for (int q = 0; q < 4; q++) acc[i][j][q] = 0.f;

    const int nt = K >> 3;

    auto ldtile = [&](int st, int k0) {
        uint32_t da = (uint32_t)__cvta_generic_to_shared(&As[st][ak][am]);
        uint32_t db = (uint32_t)__cvta_generic_to_shared(&Bs[st][ak][am]);
        cp16(da, Ab + (size_t)(k0 + ak)*lda + m0 + am);
        cp16(db, Bb + (size_t)(k0 + ak)*ldb + n0 + am);
        cp_commit();
    };

    ldtile(0, 0);
    ldtile(1, 8);
    ldtile(2, 16);

    for (int kt = 0; kt < nt; ++kt) {
        int rem = nt - 1 - kt;
        cp_wait_dyn(rem > 2 ? 2 : rem);
        __syncthreads();
        if (kt + 3 < nt) ldtile((kt + 3) & 3, (kt + 3) << 3);

        const int st = kt & 3;
        uint32_t afr[4][4], bfr[4][2];
#pragma unroll
        for (int mt = 0; mt < 4; ++mt) {
            int mb = wm + mt*16 + gid;
            if (CA) {
                afr[mt][0] = f2tf(As[st][tig  ][mb]);
                afr[mt][1] = f2tf(As[st][tig  ][mb + 8]);
                afr[mt][2] = f2tf(As[st][tig+4][mb]);
                afr[mt][3] = f2tf(As[st][tig+4][mb + 8]);
            } else {
                afr[mt][0] = __float_as_uint(As[st][tig  ][mb]);
                afr[mt][1] = __float_as_uint(As[st][tig  ][mb + 8]);
                afr[mt][2] = __float_as_uint(As[st][tig+4][mb]);
                afr[mt][3] = __float_as_uint(As[st][tig+4][mb + 8]);
            }
        }
#pragma unroll
        for (int ntl = 0; ntl < 4; ++ntl) {
            int nb = wn + ntl*8 + gid;
            if (CB) {
                bfr[ntl][0] = f2tf(Bs[st][tig  ][nb]);
                bfr[ntl][1] = f2tf(Bs[st][tig+4][nb]);
            } else {
                bfr[ntl][0] = __float_as_uint(Bs[st][tig  ][nb]);
                bfr[ntl][1] = __float_as_uint(Bs[st][tig+4][nb]);
            }
        }
#pragma unroll
        for (int mt = 0; mt < 4; ++mt)
#pragma unroll
            for (int ntl = 0; ntl < 4; ++ntl)
                mma_tf32(acc[mt][ntl], afr[mt], bfr[ntl]);
    }

#pragma unroll
    for (int mt = 0; mt < 4; ++mt) {
        int mb = m0 + wm + mt*16;
#pragma unroll
        for (int ntl = 0; ntl < 4; ++ntl) {
            int nb = n0 + wn + ntl*8;
            epi(bz, mb + gid,     nb + 2*tig,     acc[mt][ntl][0]);
            epi(bz, mb + gid,     nb + 2*tig + 1, acc[mt][ntl][1]);
            epi(bz, mb + gid + 8, nb + 2*tig,     acc[mt][ntl][2]);
            epi(bz, mb + gid + 8, nb + 2*tig + 1, acc[mt][ntl][3]);
        }
    }
}

// ================= conv3x3 as TF32 implicit GEMM =================
// A (weights^T, pre-rounded tf32) streamed via cp.async; B fragments from input slab.
__global__ __launch_bounds__(256)
void conv3_tc(const float* __restrict__ xr, const float* __restrict__ Wt,
              const float* __restrict__ bias, float* __restrict__ y2)
{
    extern __shared__ float sm[];
    float* Asm = sm;                       // 2*9504
    float* Ism = sm + 2*9504;              // 2*1632

    const int b = blockIdx.y;
    const int h = blockIdx.x;              // output row 0..63
    const int tid = threadIdx.x;
    const int warp = tid >> 5;
    const int lane = tid & 31;
    const int gid  = lane >> 2;
    const int tig  = lane & 3;
    const int wm   = (warp >> 1) * 32;     // 0,32,64,96
    const int wn   = (warp & 1) * 32;      // 0,32

    float acc[2][4][4];
#pragma unroll
    for (int i = 0; i < 2; i++)
#pragma unroll
        for (int j = 0; j < 4; j++)
#pragma unroll
            for (int q = 0; q < 4; q++) acc[i][j][q] = 0.f;

    const float* xrb = xr + (size_t)b * DM * LSEQ;

    auto ld_chunk = [&](int buf, int c0) {
        float* Ab = Asm + buf*9504;
#pragma unroll
        for (int i = 0; i < 9; ++i) {
            int e  = i*256 + tid;
            int k  = e >> 5;
            int m4 = (e & 31) << 2;
            cp16((uint32_t)__cvta_generic_to_shared(Ab + k*132 + m4),
                 Wt + (size_t)(c0*9 + k)*128 + m4);
        }
        float* Ib = Ism + buf*1632;
#pragma unroll
        for (int i = 0; i < 2; ++i) {
            int e = i*256 + tid;
            if (e < 384) {
                int row = e >> 4;
                int di  = row % 3;
                int ci  = row / 3;
                int x4  = (e & 15) << 2;
                int hh  = h + di - 1;
                int ok  = (hh >= 0 && hh < 64) ? 16 : 0;
                int hc  = ok ? hh : 0;
                cp16z((uint32_t)__cvta_generic_to_shared(Ib + row*68 + x4),
                      xrb + (size_t)(c0 + ci)*LSEQ + hc*64 + x4, ok);
            }
        }
        cp_commit();
    };

    ld_chunk(0, 0);

    for (int c = 0; c < 32; ++c) {
        cp_wait_dyn(0);
        __syncthreads();
        if (c + 1 < 32) ld_chunk((c + 1) & 1, (c + 1) * 8);

        const float* Ab = Asm + (c & 1)*9504;
        const float* Ib = Ism + (c & 1)*1632;

#pragma unroll
        for (int kk = 0; kk < 9; ++kk) {
            const int kb = kk * 8;
            uint32_t afr[2][4], bfr[4][2];
#pragma unroll
            for (int mt = 0; mt < 2; ++mt) {
                int mb = wm + mt*16 + gid;
                afr[mt][0] = __float_as_uint(Ab[(kb + tig    )*132 + mb]);
                afr[mt][1] = __float_as_uint(Ab[(kb + tig    )*132 + mb + 8]);
                afr[mt][2] = __float_as_uint(Ab[(kb + tig + 4)*132 + mb]);
                afr[mt][3] = __float_as_uint(Ab[(kb + tig + 4)*132 + mb + 8]);
            }
            int k0 = kb + tig, k1 = kb + tig + 4;
            int ci0 = k0 / 9, t0 = k0 - ci0*9, di0 = t0 / 3, dj0 = t0 - di0*3;
            int ci1 = k1 / 9, t1 = k1 - ci1*9, di1 = t1 / 3, dj1 = t1 - di1*3;
            const float* r0 = Ib + (ci0*3 + di0)*68;
            const float* r1 = Ib + (ci1*3 + di1)*68;
#pragma unroll
            for (int ntl = 0; ntl < 4; ++ntl) {
                int w = wn + ntl*8 + gid;
                int x0 = w + dj0 - 1;
                int x1 = w + dj1 - 1;
                float v0 = (x0 >= 0 && x0 < 64) ? r0[x0] : 0.f;
                float v1 = (x1 >= 0 && x1 < 64) ? r1[x1] : 0.f;
                bfr[ntl][0] = f2tf(v0);
                bfr[ntl][1] = f2tf(v1);
            }
#pragma unroll
            for (int mt = 0; mt < 2; ++mt)
#pragma unroll
                for (int ntl = 0; ntl < 4; ++ntl)
                    mma_tf32(acc[mt][ntl], afr[mt], bfr[ntl]);
        }
        __syncthreads();
    }

#pragma unroll
    for (int mt = 0; mt < 2; ++mt) {
        int ob = wm + mt*16;
#pragma unroll
        for (int ntl = 0; ntl < 4; ++ntl) {
            int wb = wn + ntl*8 + 2*tig;
            float b0 = bias[ob + gid];
            float b1 = bias[ob + gid + 8];
            size_t base0 = ((size_t)b*128 + ob + gid    )*LSEQ + h*64;
            size_t base1 = ((size_t)b*128 + ob + gid + 8)*LSEQ + h*64;
            y2[base0 + wb    ] = acc[mt][ntl][0] + b0;
            y2[base0 + wb + 1] = acc[mt][ntl][1] + b0;
            y2[base1 + wb    ] = acc[mt][ntl][2] + b1;
            y2[base1 + wb + 1] = acc[mt][ntl][3] + b1;
        }
    }
}

// ---------------- weight transpose+round: in (R,C) -> out (C,Rp), tf32-rounded, zero pad ----------------
__global__ void transp(const float* __restrict__ in, float* __restrict__ out,
                       int R, int C, int Rp) {
    __shared__ float t[32][33];
    int r0 = blockIdx.y * 32, c0 = blockIdx.x * 32;
    int x = threadIdx.x, y = threadIdx.y;
    for (int i = y; i < 32; i += 8) {
        int r = r0 + i, c = c0 + x;
        t[i][x] = (r < R && c < C) ? round_tf(in[(size_t)r*C + c]) : 0.f;
    }
    __syncthreads();
    for (int i = y; i < 32; i += 8) {
        int c = c0 + i, r = r0 + x;
        if (c < C && r < Rp) out[(size_t)c*Rp + r] = t[x][i];
    }
}

// ---------------- elementwise tf32 round-copy (for up_w) ----------------
__global__ void round_copy(const float* __restrict__ in, float* __restrict__ out, int n) {
    int idx = blockIdx.x * blockDim.x + threadIdx.x;
    if (idx < n) out[idx] = round_tf(in[idx]);
}

// ---------------- epilogues ----------------
struct EpiUp {
    float* xc; const float* up_b;
    __device__ void operator()(int b, int m, int n, float v) const {
        int o = m >> 2, i = (m >> 1) & 1, j = m & 1;
        int h = n >> 5, w = n & 31;
        xc[((size_t)b*DM + o)*LSEQ + (2*h + i)*64 + (2*w + j)] = v + up_b[o];
    }
};
struct EpiXZ {
    float* xi; float* z;
    __device__ void operator()(int b, int m, int n, float v) const {
        if (n < DI) xi[((size_t)b*DI + n)*LSEQ + m] = v;
        else        z [((size_t)b*DI + (n - DI))*LSEQ + m] = v;
    }
};
struct EpiDbc {
    float* dbc;
    __device__ void operator()(int b, int m, int n, float v) const {
        if (n < 48) dbc[(size_t)n*(NB*LSEQ) + b*LSEQ + m] = v;
    }
};
struct EpiOut {
    const float* xc; float* xr;
    __device__ void operator()(int b, int m, int n, float v) const {
        size_t idx = ((size_t)b*DM + n)*LSEQ + m;
        xr[idx] = xc[idx] + v;
    }
};

// ---------------- skip concat copy ----------------
__global__ void copy_skip(const float* __restrict__ skip, float* __restrict__ xc) {
    int idx = blockIdx.x * blockDim.x + threadIdx.x;
    int total = NB * 128 * LSEQ;
    if (idx >= total) return;
    int b = idx / (128 * LSEQ);
    int rem = idx - b * (128 * LSEQ);
    xc[((size_t)b*DM + 128)*LSEQ + rem] = skip[idx];
}

// ---------------- depthwise causal conv1d + silu (coalesced) ----------------
__global__ __launch_bounds__(256)
void conv1d_kernel(const float* __restrict__ xi, const float* __restrict__ w,
                   const float* __restrict__ bias, float* __restrict__ u)
{
    __shared__ float s[32][132];
    __shared__ float sw[32][4];
    __shared__ float sb[32];
    int b  = blockIdx.z;
    int d0 = blockIdx.y * 32;
    int l0 = blockIdx.x * 128;
    int tid = threadIdx.x;
    for (int e = tid; e < 32*132; e += 256) {
        int dd = e / 132, li = e - dd*132;
        if (li < 131) {
            int l = l0 - 3 + li;
            s[dd][li] = (l >= 0 && l < LSEQ) ? xi[((size_t)b*DI + d0 + dd)*LSEQ + l] : 0.f;
        }
    }
    if (tid < 128) sw[tid >> 2][tid & 3] = w[(d0 + (tid >> 2))*4 + (tid & 3)];
    if (tid < 32)  sb[tid] = bias[d0 + tid];
    __syncthreads();
#pragma unroll
    for (int it = 0; it < 16; ++it) {
        int idx = it*256 + tid;
        int dd = idx >> 7, li = idx & 127;
        float a = s[dd][li]*sw[dd][0] + s[dd][li+1]*sw[dd][1]
                + s[dd][li+2]*sw[dd][2] + s[dd][li+3]*sw[dd][3] + sb[dd];
        float sv = a / (1.f + __expf(-a));
        u[((size_t)b*DI + d0 + dd)*LSEQ + l0 + li] = sv;
    }
}

// ---------------- dt = softplus(dbc[:,:16] @ dtw^T + dtb), out (b,d,l) ----------------
__global__ __launch_bounds__(256)
void dt_kernel(const float* __restrict__ dbc, const float* __restrict__ dtw,
               const float* __restrict__ dtb, float* __restrict__ dt)
{
    __shared__ float swt[DI*16];
    __shared__ float sbc[16*64];
    __shared__ float sbias[DI];
    int bl0 = blockIdx.x * 64;
    int tid = threadIdx.x;
    for (int i = tid; i < DI*16; i += 256) swt[i] = dtw[i];
    for (int i = tid; i < DI; i += 256) sbias[i] = dtb[i];
    for (int i = tid; i < 16*64; i += 256) {
        int r = i >> 6, li = i & 63;
        sbc[i] = dbc[(size_t)r*(NB*LSEQ) + bl0 + li];
    }
    __syncthreads();
    int b  = bl0 >> 12;
    int l0 = bl0 & (LSEQ - 1);
#pragma unroll 4
    for (int it = 0; it < 128; ++it) {
        int idx = it*256 + tid;
        int d = idx >> 6, li = idx & 63;
        float acc = sbias[d];
#pragma unroll
        for (int r = 0; r < 16; ++r) acc += swt[d*16 + r] * sbc[r*64 + li];
        float sp = (acc > 20.f) ? acc : log1pf(__expf(acc));
        dt[((size_t)b*DI + d)*LSEQ + l0 + li] = sp;
    }
}

// ================= chunked selective scan =================
__global__ __launch_bounds__(128)
void scan_pass1(const float* __restrict__ dt, const float* __restrict__ u,
                const float* __restrict__ dbc, const float* __restrict__ A_log,
                float* __restrict__ S, float* __restrict__ sd)
{
    int lane = threadIdx.x & 31;
    int n    = lane & 15;
    int half = lane >> 4;
    int warp = threadIdx.x >> 5;
    int gch  = blockIdx.y * 8 + warp * 2 + half;
    int c    = blockIdx.x;
    int b = gch >> 9, d = gch & (DI - 1);

    float A = -__expf(A_log[d*DS + n]);
    const float* dtp = dt  + (size_t)gch*LSEQ + c*CT;
    const float* up  = u   + (size_t)gch*LSEQ + c*CT;
    const float* bp  = dbc + (size_t)(16 + n)*(NB*LSEQ) + b*LSEQ + c*CT;

    float h = 0.f, sda = 0.f;
#pragma unroll 8
    for (int l = 0; l < CT; ++l) {
        float dtv = dtp[l], uv = up[l], bn = bp[l];
        float dA = __expf(dtv * A);
        h = dA * h + (dtv * uv) * bn;
        sda += dtv;
    }
    S[((size_t)gch*NCH + c)*DS + n] = h;
    if (n == 0) sd[(size_t)gch*NCH + c] = sda;
}

__global__ __launch_bounds__(128)
void scan_pass2(const float* __restrict__ S, const float* __restrict__ sd,
                const float* __restrict__ A_log, float* __restrict__ hs)
{
    int lane = threadIdx.x & 31;
    int n    = lane & 15;
    int half = lane >> 4;
    int warp = threadIdx.x >> 5;
    int gch  = blockIdx.x * 8 + warp * 2 + half;
    int d = gch & (DI - 1);
    float A = -__expf(A_log[d*DS + n]);
    float h = 0.f;
    for (int c = 0; c < NCH; ++c) {
        size_t idx = ((size_t)gch*NCH + c)*DS + n;
        hs[idx] = h;
        float P = __expf(A * sd[(size_t)gch*NCH + c]);
        h = P * h + S[idx];
    }
}

__global__ __launch_bounds__(128)
void scan_pass3(const float* __restrict__ dt, const float* __restrict__ u,
                const float* __restrict__ dbc, const float* __restrict__ z,
                const float* __restrict__ A_log, const float* __restrict__ Dp,
                const float* __restrict__ hs, float* __restrict__ y)
{
    int lane = threadIdx.x & 31;
    int n    = lane & 15;
    int half = lane >> 4;
    int warp = threadIdx.x >> 5;
    int gch  = blockIdx.y * 8 + warp * 2 + half;
    int c    = blockIdx.x;
    int b = gch >> 9, d = gch & (DI - 1);

    float A  = -__expf(A_log[d*DS + n]);
    float Dv = Dp[d];
    const float* dtp = dt  + (size_t)gch*LSEQ + c*CT;
    const float* up  = u   + (size_t)gch*LSEQ + c*CT;
    const float* zp  = z   + (size_t)gch*LSEQ + c*CT;
    const float* bp  = dbc + (size_t)(16 + n)*(NB*LSEQ) + b*LSEQ + c*CT;
    const float* cp  = dbc + (size_t)(32 + n)*(NB*LSEQ) + b*LSEQ + c*CT;
    float*       yp  = y   + (size_t)gch*LSEQ + c*CT;

    float h = hs[((size_t)gch*NCH + c)*DS + n];
#pragma unroll 4
    for (int l = 0; l < CT; ++l) {
        float dtv = dtp[l], uv = up[l];
        float bn = bp[l], cn = cp[l];
        float dA = __expf(dtv * A);
        h = dA * h + (dtv * uv) * bn;
        float yv = h * cn;
        yv += __shfl_xor_sync(0xffffffffu, yv, 1);
        yv += __shfl_xor_sync(0xffffffffu, yv, 2);
        yv += __shfl_xor_sync(0xffffffffu, yv, 4);
        yv += __shfl_xor_sync(0xffffffffu, yv, 8);
        if (n == 0) {
            float out = yv + uv * Dv;
            float zv = zp[l];
            float sg = zv / (1.f + __expf(-zv));
            yp[l] = out * sg;
        }
    }
}

// ---------------- batchnorm stats + apply + gelu ----------------
__global__ void bn_stats(const float* __restrict__ y2, float* __restrict__ mv) {
    int o = blockIdx.x;
    float s = 0.f, s2 = 0.f;
    for (int i = threadIdx.x; i < NB*LSEQ; i += 256) {
        int b = i >> 12, l = i & (LSEQ - 1);
        float v = y2[((size_t)b*128 + o)*LSEQ + l];
        s += v; s2 += v*v;
    }
    __shared__ float sh0[256], sh1[256];
    sh0[threadIdx.x] = s; sh1[threadIdx.x] = s2;
    __syncthreads();
    for (int st = 128; st > 0; st >>= 1) {
        if (threadIdx.x < st) {
            sh0[threadIdx.x] += sh0[threadIdx.x + st];
            sh1[threadIdx.x] += sh1[threadIdx.x + st];
        }
        __syncthreads();
    }
    if (threadIdx.x == 0) {
        float inv = 1.f / (NB * LSEQ);
        float mu = sh0[0] * inv;
        float var = sh1[0] * inv - mu * mu;
        mv[o] = mu; mv[128 + o] = var;
    }
}

__global__ void bn_apply(const float* __restrict__ y2, const float* __restrict__ mv,
                         const float* __restrict__ gamma, const float* __restrict__ beta,
                         float* __restrict__ out)
{
    int idx = blockIdx.x * blockDim.x + threadIdx.x;
    if (idx >= NB*128*LSEQ) return;
    int o = (idx >> 12) & 127;
    float mu = mv[o], var = mv[128 + o];
    float v = (y2[idx] - mu) * rsqrtf(var + 1e-5f) * gamma[o] + beta[o];
    out[idx] = 0.5f * v * (1.f + erff(v * 0.70710678118654752440f));
}

// ---------------- launch ----------------
extern "C" void kernel_launch(void* const* d_in, const int* in_sizes, int n_in,
                              void* d_out, int out_size)
{
    const float* x        = (const float*)d_in[0];
    const float* skip     = (const float*)d_in[1];
    const float* up_w     = (const float*)d_in[2];
    const float* up_b     = (const float*)d_in[3];
    const float* in_proj  = (const float*)d_in[4];
    const float* c1w      = (const float*)d_in[5];
    const float* c1b      = (const float*)d_in[6];
    const float* xproj    = (const float*)d_in[7];
    const float* dtw      = (const float*)d_in[8];
    const float* dtb      = (const float*)d_in[9];
    const float* A_log    = (const float*)d_in[10];
    const float* Dp       = (const float*)d_in[11];
    const float* outw     = (const float*)d_in[12];
    const float* cw       = (const float*)d_in[13];
    const float* cb       = (const float*)d_in[14];
    const float* bng      = (const float*)d_in[15];
    const float* bnb      = (const float*)d_in[16];
    float* out = (float*)d_out;

    float *xc, *xi, *z, *u, *dbc, *dtv, *y, *xr, *y2, *mv, *S, *hs, *sd;
    float *wt1, *wt2, *wt3, *wt4, *upw;
    cudaGetSymbolAddress((void**)&xc,  g_xc);
    cudaGetSymbolAddress((void**)&xi,  g_xi);
    cudaGetSymbolAddress((void**)&z,   g_z);
    cudaGetSymbolAddress((void**)&u,   g_u);
    cudaGetSymbolAddress((void**)&dbc, g_dbc);
    cudaGetSymbolAddress((void**)&dtv, g_dt);
    cudaGetSymbolAddress((void**)&y,   g_y);
    cudaGetSymbolAddress((void**)&xr,  g_xr);
    cudaGetSymbolAddress((void**)&y2,  g_y2);
    cudaGetSymbolAddress((void**)&mv,  g_mv);
    cudaGetSymbolAddress((void**)&S,   g_S);
    cudaGetSymbolAddress((void**)&hs,  g_hs);
    cudaGetSymbolAddress((void**)&sd,  g_sd);
    cudaGetSymbolAddress((void**)&wt1, g_wt1);
    cudaGetSymbolAddress((void**)&wt2, g_wt2);
    cudaGetSymbolAddress((void**)&wt3, g_wt3);
    cudaGetSymbolAddress((void**)&wt4, g_wt4);
    cudaGetSymbolAddress((void**)&upw, g_upw);

    const int C3_SMEM = (2*9504 + 2*1632) * 4;   // 89088 bytes
    cudaFuncSetAttribute(conv3_tc, cudaFuncAttributeMaxDynamicSharedMemorySize, C3_SMEM);

    // 0) one-time weight prep: transpose + round to tf32 (+ zero pad for x_proj)
    transp<<<dim3(256/32, 1024/32), dim3(32, 8)>>>(in_proj, wt1, 1024, 256, 1024);
    transp<<<dim3(512/32,  256/32), dim3(32, 8)>>>(outw,    wt2,  256, 512,  256);
    transp<<<dim3(512/32,        4), dim3(32, 8)>>>(xproj,   wt3,   48, 512,  128);
    transp<<<dim3(2304/32,       4), dim3(32, 8)>>>(cw,      wt4,  128, 2304, 128);
    round_copy<<<(256*512 + 255)/256, 256>>>(up_w, upw, 256*512);

    // 1) upsample GEMM (tf32 TC): A = pre-rounded up_w, B = x (cvt in-kernel)
    gemm128_tc<false, true, EpiUp><<<dim3(8, 4, NB), 256>>>(
        upw, 512, 0, x, 1024, (long)256*1024, 512, 1024, 256, EpiUp{xc, up_b});

    // 2) skip concat
    copy_skip<<<(NB*128*LSEQ + 255)/256, 256>>>(skip, xc);

    // 3) in_proj GEMM (tf32 TC): A = xc (cvt), B = wt1 (pre-rounded)
    gemm128_tc<true, false, EpiXZ><<<dim3(8, 32, NB), 256>>>(
        xc, LSEQ, (long)DM*LSEQ, wt1, 1024, 0, LSEQ, 2*DI, DM, EpiXZ{xi, z});

    // 4) depthwise conv1d + silu
    conv1d_kernel<<<dim3(LSEQ/128, DI/32, NB), 256>>>(xi, c1w, c1b, u);

    // 5) x_proj GEMM (tf32 TC, N padded 48->128): A = u (cvt), B = wt3 (pre-rounded)
    gemm128_tc<true, false, EpiDbc><<<dim3(1, 32, NB), 256>>>(
        u, LSEQ, (long)DI*LSEQ, wt3, 128, 0, LSEQ, 128, DI, EpiDbc{dbc});

    // 6) dt = softplus(dbc[:16]^T @ dtw^T + dtb)
    dt_kernel<<<NB*LSEQ/64, 256>>>(dbc, dtw, dtb, dtv);

    // 7) chunked selective scan
    scan_pass1<<<dim3(NCH, NB*DI/8), 128>>>(dtv, u, dbc, A_log, S, sd);
    scan_pass2<<<NB*DI/8, 128>>>(S, sd, A_log, hs);
    scan_pass3<<<dim3(NCH, NB*DI/8), 128>>>(dtv, u, dbc, z, A_log, Dp, hs, y);

    // 8) out_proj GEMM (tf32 TC) + residual: A = y (cvt), B = wt2 (pre-rounded)
    gemm128_tc<true, false, EpiOut><<<dim3(2, 32, NB), 256>>>(
        y, LSEQ, (long)DI*LSEQ, wt2, 256, 0, LSEQ, DM, DI, EpiOut{xc, xr});

    // 9) 3x3 conv as TF32 implicit GEMM (weights pre-rounded)
    conv3_tc<<<dim3(64, NB), 256, C3_SMEM>>>(xr, wt4, cb, y2);

    // 10) batchnorm stats
    bn_stats<<<128, 256>>>(y2, mv);

    // 11) batchnorm apply + gelu
    bn_apply<<<(NB*128*LSEQ + 255)/256, 256>>>(y2, mv, bng, bnb, out);
}

// round 13
// speedup vs baseline: 1.3885x; 1.0216x over previous
#include <cuda_runtime.h>
#include <math.h>
#include <stdint.h>

#define LSEQ 4096
#define DM   256
#define DI   512
#define DS   16
#define NB   2
#define NCH  64   // scan chunks
#define CT   64   // chunk length

// ---------------- scratch (device globals; no runtime alloc allowed) ----------------
__device__ __align__(16) float g_xc [NB*DM*LSEQ];    // (b, c=256, l)
__device__ __align__(16) float g_xi [NB*DI*LSEQ];    // (b, d, l)
__device__ __align__(16) float g_z  [NB*DI*LSEQ];    // (b, d, l)
__device__ __align__(16) float g_u  [NB*DI*LSEQ];    // (b, d, l)
__device__ __align__(16) float g_dbc[48*NB*LSEQ];    // (j=48, b*l)
__device__ __align__(16) float g_dt [NB*DI*LSEQ];    // (b, d, l)
__device__ __align__(16) float g_y  [NB*DI*LSEQ];    // (b, d, l)
__device__ __align__(16) float g_xr [NB*DM*LSEQ];    // (b, c, l)
__device__ __align__(16) float g_y2 [NB*128*LSEQ];   // (b, o, l)
__device__ __align__(16) float g_mv [256];
__device__ __align__(16) float g_S  [NB*DI*NCH*DS];
__device__ __align__(16) float g_hs [NB*DI*NCH*DS];
__device__ __align__(16) float g_sd [NB*DI*NCH];
__device__ __align__(16) float g_wt1[256*1024];      // in_proj_w^T  (k=256, n=1024), tf32-rounded
__device__ __align__(16) float g_wt2[512*256];       // out_proj_w^T (k=512, n=256),  tf32-rounded
__device__ __align__(16) float g_wt3[512*128];       // x_proj_w^T   (k=512, n=128 pad), tf32-rounded
__device__ __align__(16) float g_wt4[2304*128];      // conv_w^T     (k=c*9+t, o=128), tf32-rounded
__device__ __align__(16) float g_upw[256*512];       // up_w tf32-rounded (k=256 rows x m=512)

// ---------------- cp.async helpers ----------------
__device__ __forceinline__ void cp16(uint32_t dst, const float* src) {
    asm volatile("cp.async.cg.shared.global [%0], [%1], 16;\n" :: "r"(dst), "l"(src));
}
__device__ __forceinline__ void cp16z(uint32_t dst, const float* src, int sz) {
    asm volatile("cp.async.cg.shared.global [%0], [%1], 16, %2;\n" :: "r"(dst), "l"(src), "r"(sz));
}
__device__ __forceinline__ void cp_commit() {
    asm volatile("cp.async.commit_group;\n");
}
__device__ __forceinline__ void cp_wait_dyn(int allow) {
    if (allow <= 0)      asm volatile("cp.async.wait_group 0;\n");
    else                 asm volatile("cp.async.wait_group 1;\n");
}

// ---------------- tf32 helpers ----------------
__device__ __forceinline__ uint32_t f2tf(float f) {
    uint32_t r;
    asm("cvt.rna.tf32.f32 %0, %1;" : "=r"(r) : "f"(f));
    return r;
}
__device__ __forceinline__ float round_tf(float f) {
    return __uint_as_float(f2tf(f));
}
__device__ __forceinline__ void mma_tf32(float* c, const uint32_t* a, const uint32_t* b) {
    asm volatile(
        "mma.sync.aligned.m16n8k8.row.col.f32.tf32.tf32.f32 "
        "{%0,%1,%2,%3}, {%4,%5,%6,%7}, {%8,%9}, {%0,%1,%2,%3};"
        : "+f"(c[0]), "+f"(c[1]), "+f"(c[2]), "+f"(c[3])
        : "r"(a[0]), "r"(a[1]), "r"(a[2]), "r"(a[3]), "r"(b[0]), "r"(b[1]));
}

// ================= 128x128x16, 3-stage cp.async, TF32 tensor-core GEMM =================
// CA/CB: apply rna tf32 conversion to A/B fragments (false = operand pre-rounded).
// A k-major (A[k*lda+m]), B k-major (B[k*ldb+n]). M%128==0, N%128==0, K%16==0, K/16 >= 2.
// Dynamic smem: 2 * 3 * 16 * 132 floats = 50688 bytes.
#define GT_SMEM (2*3*16*132*4)
template<bool CA, bool CB, class Epi>
__global__ __launch_bounds__(256)
void gemm128_tc(const float* __restrict__ A, int lda, long sA,
                const float* __restrict__ B, int ldb, long sB,
                int M, int N, int K, Epi epi)
{
    extern __shared__ float smg[];
    float* Asm = smg;                 // [3][16][132]
    float* Bsm = smg + 3*16*132;
    const int tid = threadIdx.x;
    const int bz  = blockIdx.z;
    const float* Ab = A + (size_t)bz * sA;
    const float* Bb = B + (size_t)bz * sB;
    const int m0 = blockIdx.y * 128;
    const int n0 = blockIdx.x * 128;

    const int warp = tid >> 5;
    const int lane = tid & 31;
    const int gid  = lane >> 2;
    const int tig  = lane & 3;
    const int wm   = (warp >> 2) * 64;
    const int wn   = (warp & 3) * 32;

    float acc[4][4][4];
#pragma unroll
    for (int i = 0; i < 4; i++)
#pragma unroll
        for (int j = 0; j < 4; j++)
#pragma unroll
            for (int q = 0; q < 4; q++) acc[i][j][q] = 0.f;

    const int nt = K >> 4;

    auto ldtile = [&](int st, int k0) {
#pragma unroll
        for (int i = 0; i < 2; ++i) {
            int e  = i*256 + tid;          // 0..511
            int kr = e >> 5;               // 0..15
            int m4 = (e & 31) << 2;
            cp16((uint32_t)__cvta_generic_to_shared(Asm + (st*16 + kr)*132 + m4),
                 Ab + (size_t)(k0 + kr)*lda + m0 + m4);
            cp16((uint32_t)__cvta_generic_to_shared(Bsm + (st*16 + kr)*132 + m4),
                 Bb + (size_t)(k0 + kr)*ldb + n0 + m4);
        }
        cp_commit();
    };

    ldtile(0, 0);
    ldtile(1, 16);

    for (int kt = 0; kt < nt; ++kt) {
        cp_wait_dyn((kt + 1 < nt) ? 1 : 0);
        __syncthreads();
        if (kt + 2 < nt) {
            int st2 = (kt + 2) % 3;
            ldtile(st2, (kt + 2) << 4);
        }
        const int st = kt % 3;
        const float* As = Asm + st*16*132;
        const float* Bs = Bsm + st*16*132;

#pragma unroll
        for (int kb = 0; kb < 16; kb += 8) {
            uint32_t afr[4][4], bfr[4][2];
#pragma unroll
            for (int mt = 0; mt < 4; ++mt) {
                int mb = wm + mt*16 + gid;
                if (CA) {
                    afr[mt][0] = f2tf(As[(kb + tig    )*132 + mb]);
                    afr[mt][1] = f2tf(As[(kb + tig    )*132 + mb + 8]);
                    afr[mt][2] = f2tf(As[(kb + tig + 4)*132 + mb]);
                    afr[mt][3] = f2tf(As[(kb + tig + 4)*132 + mb + 8]);
                } else {
                    afr[mt][0] = __float_as_uint(As[(kb + tig    )*132 + mb]);
                    afr[mt][1] = __float_as_uint(As[(kb + tig    )*132 + mb + 8]);
                    afr[mt][2] = __float_as_uint(As[(kb + tig + 4)*132 + mb]);
                    afr[mt][3] = __float_as_uint(As[(kb + tig + 4)*132 + mb + 8]);
                }
            }
#pragma unroll
            for (int ntl = 0; ntl < 4; ++ntl) {
                int nb = wn + ntl*8 + gid;
                if (CB) {
                    bfr[ntl][0] = f2tf(Bs[(kb + tig    )*132 + nb]);
                    bfr[ntl][1] = f2tf(Bs[(kb + tig + 4)*132 + nb]);
                } else {
                    bfr[ntl][0] = __float_as_uint(Bs[(kb + tig    )*132 + nb]);
                    bfr[ntl][1] = __float_as_uint(Bs[(kb + tig + 4)*132 + nb]);
                }
            }
#pragma unroll
            for (int mt = 0; mt < 4; ++mt)
#pragma unroll
                for (int ntl = 0; ntl < 4; ++ntl)
                    mma_tf32(acc[mt][ntl], afr[mt], bfr[ntl]);
        }
    }

#pragma unroll
    for (int mt = 0; mt < 4; ++mt) {
        int mb = m0 + wm + mt*16;
#pragma unroll
        for (int ntl = 0; ntl < 4; ++ntl) {
            int nb = n0 + wn + ntl*8;
            epi(bz, mb + gid,     nb + 2*tig,     acc[mt][ntl][0]);
            epi(bz, mb + gid,     nb + 2*tig + 1, acc[mt][ntl][1]);
            epi(bz, mb + gid + 8, nb + 2*tig,     acc[mt][ntl][2]);
            epi(bz, mb + gid + 8, nb + 2*tig + 1, acc[mt][ntl][3]);
        }
    }
}

// ================= conv3x3 as TF32 implicit GEMM, 64 out-ch per block =================
// grid (64 rows, 2 channel-halves, NB). Dyn smem: 2*72*68 + 2*24*68 floats = 52224 B.
#define C3_SMEM ((2*72*68 + 2*24*68)*4)
__global__ __launch_bounds__(256)
void conv3_tc(const float* __restrict__ xr, const float* __restrict__ Wt,
              const float* __restrict__ bias, float* __restrict__ y2)
{
    extern __shared__ float sm[];
    float* Asm = sm;                       // 2 bufs x 72 x 68
    float* Ism = sm + 2*72*68;             // 2 bufs x 24 x 68

    const int b  = blockIdx.z;
    const int oh = blockIdx.y;             // 0/1 -> channels 0..63 / 64..127
    const int h  = blockIdx.x;             // output row 0..63
    const int tid = threadIdx.x;
    const int warp = tid >> 5;
    const int lane = tid & 31;
    const int gid  = lane >> 2;
    const int tig  = lane & 3;
    const int wm   = (warp >> 1) * 16;     // 0,16,32,48
    const int wn   = (warp & 1) * 32;      // 0,32

    float acc[4][4];
#pragma unroll
    for (int j = 0; j < 4; j++)
#pragma unroll
        for (int q = 0; q < 4; q++) acc[j][q] = 0.f;

    const float* xrb = xr + (size_t)b * DM * LSEQ;

    auto ld_chunk = [&](int buf, int c0) {
        float* Ab = Asm + buf*72*68;
#pragma unroll
        for (int i = 0; i < 5; ++i) {
            int e = i*256 + tid;           // need 1152 float4
            if (e < 1152) {
                int k  = e >> 4;           // 0..71
                int m4 = (e & 15) << 2;    // 0..60
                cp16((uint32_t)__cvta_generic_to_shared(Ab + k*68 + m4),
                     Wt + (size_t)(c0*9 + k)*128 + oh*64 + m4);
            }
        }
        float* Ib = Ism + buf*24*68;
#pragma unroll
        for (int i = 0; i < 2; ++i) {
            int e = i*256 + tid;
            if (e < 384) {
                int row = e >> 4;          // 0..23 = ci*3+di
                int di  = row % 3;
                int ci  = row / 3;
                int x4  = (e & 15) << 2;
                int hh  = h + di - 1;
                int ok  = (hh >= 0 && hh < 64) ? 16 : 0;
                int hc  = ok ? hh : 0;
                cp16z((uint32_t)__cvta_generic_to_shared(Ib + row*68 + x4),
                      xrb + (size_t)(c0 + ci)*LSEQ + hc*64 + x4, ok);
            }
        }
        cp_commit();
    };

    ld_chunk(0, 0);

    for (int c = 0; c < 32; ++c) {
        cp_wait_dyn(0);
        __syncthreads();
        if (c + 1 < 32) ld_chunk((c + 1) & 1, (c + 1) * 8);

        const float* Ab = Asm + (c & 1)*72*68;
        const float* Ib = Ism + (c & 1)*24*68;

#pragma unroll
        for (int kk = 0; kk < 9; ++kk) {
            const int kb = kk * 8;
            uint32_t afr[4], bfr[4][2];
            {
                int mb = wm + gid;
                afr[0] = __float_as_uint(Ab[(kb + tig    )*68 + mb]);
                afr[1] = __float_as_uint(Ab[(kb + tig    )*68 + mb + 8]);
                afr[2] = __float_as_uint(Ab[(kb + tig + 4)*68 + mb]);
                afr[3] = __float_as_uint(Ab[(kb + tig + 4)*68 + mb + 8]);
            }
            int k0 = kb + tig, k1 = kb + tig + 4;
            int ci0 = k0 / 9, t0 = k0 - ci0*9, di0 = t0 / 3, dj0 = t0 - di0*3;
            int ci1 = k1 / 9, t1 = k1 - ci1*9, di1 = t1 / 3, dj1 = t1 - di1*3;
            const float* r0 = Ib + (ci0*3 + di0)*68;
            const float* r1 = Ib + (ci1*3 + di1)*68;
#pragma unroll
            for (int ntl = 0; ntl < 4; ++ntl) {
                int w = wn + ntl*8 + gid;
                int x0 = w + dj0 - 1;
                int x1 = w + dj1 - 1;
                float v0 = (x0 >= 0 && x0 < 64) ? r0[x0] : 0.f;
                float v1 = (x1 >= 0 && x1 < 64) ? r1[x1] : 0.f;
                bfr[ntl][0] = f2tf(v0);
                bfr[ntl][1] = f2tf(v1);
            }
#pragma unroll
            for (int ntl = 0; ntl < 4; ++ntl)
                mma_tf32(acc[ntl], afr, bfr[ntl]);
        }
        __syncthreads();
    }

    {
        int o0 = oh*64 + wm;
        float b0 = bias[o0 + gid];
        float b1 = bias[o0 + gid + 8];
        size_t base0 = ((size_t)b*128 + o0 + gid    )*LSEQ + h*64;
        size_t base1 = ((size_t)b*128 + o0 + gid + 8)*LSEQ + h*64;
#pragma unroll
        for (int ntl = 0; ntl < 4; ++ntl) {
            int wb = wn + ntl*8 + 2*tig;
            y2[base0 + wb    ] = acc[ntl][0] + b0;
            y2[base0 + wb + 1] = acc[ntl][1] + b0;
            y2[base1 + wb    ] = acc[ntl][2] + b1;
            y2[base1 + wb + 1] = acc[ntl][3] + b1;
        }
    }
}

// ---------------- merged prep: all weight transposes+rounds, up_w round, skip copy ----------------
__device__ __forceinline__ void transp_tile(const float* __restrict__ in, float* __restrict__ out,
                                            int R, int C, int Rp, int bx, int by)
{
    __shared__ float t[32][33];
    int r0 = by * 32, c0 = bx * 32;
    int x = threadIdx.x & 31, y = (threadIdx.x >> 5) ;
    // 256 threads: x 0..31, y 0..7
    for (int i = y; i < 32; i += 8) {
        int r = r0 + i, c = c0 + x;
        t[i][x] = (r < R && c < C) ? round_tf(in[(size_t)r*C + c]) : 0.f;
    }
    __syncthreads();
    for (int i = y; i < 32; i += 8) {
        int c = c0 + i, r = r0 + x;
        if (c < C && r < Rp) out[(size_t)c*Rp + r] = t[x][i];
    }
}

__global__ __launch_bounds__(256)
void prep_kernel(const float* __restrict__ in_proj, const float* __restrict__ outw,
                 const float* __restrict__ xproj,   const float* __restrict__ cw,
                 const float* __restrict__ up_w,    const float* __restrict__ skip,
                 float* __restrict__ wt1, float* __restrict__ wt2,
                 float* __restrict__ wt3, float* __restrict__ wt4,
                 float* __restrict__ upw, float* __restrict__ xc)
{
    int bid = blockIdx.x;
    if (bid < 256) {                 // wt1: in_proj (1024x256) -> (256,1024)
        transp_tile(in_proj, wt1, 1024, 256, 1024, bid & 7, bid >> 3);
    } else if (bid < 384) {          // wt2: outw (256x512) -> (512,256)
        int id = bid - 256;
        transp_tile(outw, wt2, 256, 512, 256, id & 15, id >> 4);
    } else if (bid < 448) {          // wt3: xproj (48x512) -> (512,128 pad)
        int id = bid - 384;
        transp_tile(xproj, wt3, 48, 512, 128, id & 15, id >> 4);
    } else if (bid < 736) {          // wt4: cw (128x2304) -> (2304,128)
        int id = bid - 448;
        transp_tile(cw, wt4, 128, 2304, 128, id % 72, id / 72);
    } else if (bid < 1248) {         // upw round copy: 512 blocks x 256 = 131072
        int idx = (bid - 736) * 256 + threadIdx.x;
        upw[idx] = round_tf(up_w[idx]);
    } else {                         // skip copy (float4): 1024 blocks x 256 = 262144
        int idx = (bid - 1248) * 256 + threadIdx.x;
        const float4* s4 = reinterpret_cast<const float4*>(skip);
        float4* x4 = reinterpret_cast<float4*>(xc);
        int b = idx >> 17;           // 131072 float4 per batch
        int rem = idx & 131071;
        x4[(size_t)(b*256 + 128)*1024 + rem] = s4[(size_t)b*131072 + rem];
    }
}

// ---------------- epilogues ----------------
struct EpiUp {
    float* xc; const float* up_b;
    __device__ void operator()(int b, int m, int n, float v) const {
        int o = m >> 2, i = (m >> 1) & 1, j = m & 1;
        int h = n >> 5, w = n & 31;
        xc[((size_t)b*DM + o)*LSEQ + (2*h + i)*64 + (2*w + j)] = v + up_b[o];
    }
};
struct EpiXZ {
    float* xi; float* z;
    __device__ void operator()(int b, int m, int n, float v) const {
        if (n < DI) xi[((size_t)b*DI + n)*LSEQ + m] = v;
        else        z [((size_t)b*DI + (n - DI))*LSEQ + m] = v;
    }
};
struct EpiDbc {
    float* dbc;
    __device__ void operator()(int b, int m, int n, float v) const {
        if (n < 48) dbc[(size_t)n*(NB*LSEQ) + b*LSEQ + m] = v;
    }
};
struct EpiOut {
    const float* xc; float* xr;
    __device__ void operator()(int b, int m, int n, float v) const {
        size_t idx = ((size_t)b*DM + n)*LSEQ + m;
        xr[idx] = xc[idx] + v;
    }
};

// ---------------- depthwise causal conv1d + silu (coalesced) ----------------
__global__ __launch_bounds__(256)
void conv1d_kernel(const float* __restrict__ xi, const float* __restrict__ w,
                   const float* __restrict__ bias, float* __restrict__ u)
{
    __shared__ float s[32][132];
    __shared__ float sw[32][4];
    __shared__ float sb[32];
    int b  = blockIdx.z;
    int d0 = blockIdx.y * 32;
    int l0 = blockIdx.x * 128;
    int tid = threadIdx.x;
    for (int e = tid; e < 32*132; e += 256) {
        int dd = e / 132, li = e - dd*132;
        if (li < 131) {
            int l = l0 - 3 + li;
            s[dd][li] = (l >= 0 && l < LSEQ) ? xi[((size_t)b*DI + d0 + dd)*LSEQ + l] : 0.f;
        }
    }
    if (tid < 128) sw[tid >> 2][tid & 3] = w[(d0 + (tid >> 2))*4 + (tid & 3)];
    if (tid < 32)  sb[tid] = bias[d0 + tid];
    __syncthreads();
#pragma unroll
    for (int it = 0; it < 16; ++it) {
        int idx = it*256 + tid;
        int dd = idx >> 7, li = idx & 127;
        float a = s[dd][li]*sw[dd][0] + s[dd][li+1]*sw[dd][1]
                + s[dd][li+2]*sw[dd][2] + s[dd][li+3]*sw[dd][3] + sb[dd];
        float sv = a / (1.f + __expf(-a));
        u[((size_t)b*DI + d0 + dd)*LSEQ + l0 + li] = sv;
    }
}

// ---------------- dt = softplus(dbc[:,:16] @ dtw^T + dtb), out (b,d,l) ----------------
__global__ __launch_bounds__(256)
void dt_kernel(const float* __restrict__ dbc, const float* __restrict__ dtw,
               const float* __restrict__ dtb, float* __restrict__ dt)
{
    __shared__ float swt[DI*16];
    __shared__ float sbc[16*64];
    __shared__ float sbias[DI];
    int bl0 = blockIdx.x * 64;
    int tid = threadIdx.x;
    for (int i = tid; i < DI*16; i += 256) swt[i] = dtw[i];
    for (int i = tid; i < DI; i += 256) sbias[i] = dtb[i];
    for (int i = tid; i < 16*64; i += 256) {
        int r = i >> 6, li = i & 63;
        sbc[i] = dbc[(size_t)r*(NB*LSEQ) + bl0 + li];
    }
    __syncthreads();
    int b  = bl0 >> 12;
    int l0 = bl0 & (LSEQ - 1);
#pragma unroll 4
    for (int it = 0; it < 128; ++it) {
        int idx = it*256 + tid;
        int d = idx >> 6, li = idx & 63;
        float acc = sbias[d];
#pragma unroll
        for (int r = 0; r < 16; ++r) acc += swt[d*16 + r] * sbc[r*64 + li];
        float sp = (acc > 20.f) ? acc : log1pf(__expf(acc));
        dt[((size_t)b*DI + d)*LSEQ + l0 + li] = sp;
    }
}

// ================= chunked selective scan =================
__global__ __launch_bounds__(128)
void scan_pass1(const float* __restrict__ dt, const float* __restrict__ u,
                const float* __restrict__ dbc, const float* __restrict__ A_log,
                float* __restrict__ S, float* __restrict__ sd)
{
    int lane = threadIdx.x & 31;
    int n    = lane & 15;
    int half = lane >> 4;
    int warp = threadIdx.x >> 5;
    int gch  = blockIdx.y * 8 + warp * 2 + half;
    int c    = blockIdx.x;
    int b = gch >> 9, d = gch & (DI - 1);

    float A = -__expf(A_log[d*DS + n]);
    const float* dtp = dt  + (size_t)gch*LSEQ + c*CT;
    const float* up  = u   + (size_t)gch*LSEQ + c*CT;
    const float* bp  = dbc + (size_t)(16 + n)*(NB*LSEQ) + b*LSEQ + c*CT;

    float h = 0.f, sda = 0.f;
#pragma unroll 8
    for (int l = 0; l < CT; ++l) {
        float dtv = dtp[l], uv = up[l], bn = bp[l];
        float dA = __expf(dtv * A);
        h = dA * h + (dtv * uv) * bn;
        sda += dtv;
    }
    S[((size_t)gch*NCH + c)*DS + n] = h;
    if (n == 0) sd[(size_t)gch*NCH + c] = sda;
}

__global__ __launch_bounds__(128)
void scan_pass2(const float* __restrict__ S, const float* __restrict__ sd,
                const float* __restrict__ A_log, float* __restrict__ hs)
{
    int lane = threadIdx.x & 31;
    int n    = lane & 15;
    int half = lane >> 4;
    int warp = threadIdx.x >> 5;
    int gch  = blockIdx.x * 8 + warp * 2 + half;
    int d = gch & (DI - 1);
    float A = -__expf(A_log[d*DS + n]);
    float h = 0.f;
    for (int c = 0; c < NCH; ++c) {
        size_t idx = ((size_t)gch*NCH + c)*DS + n;
        hs[idx] = h;
        float P = __expf(A * sd[(size_t)gch*NCH + c]);
        h = P * h + S[idx];
    }
}

__global__ __launch_bounds__(128)
void scan_pass3(const float* __restrict__ dt, const float* __restrict__ u,
                const float* __restrict__ dbc, const float* __restrict__ z,
                const float* __restrict__ A_log, const float* __restrict__ Dp,
                const float* __restrict__ hs, float* __restrict__ y)
{
    int lane = threadIdx.x & 31;
    int n    = lane & 15;
    int half = lane >> 4;
    int warp = threadIdx.x >> 5;
    int gch  = blockIdx.y * 8 + warp * 2 + half;
    int c    = blockIdx.x;
    int b = gch >> 9, d = gch & (DI - 1);

    float A  = -__expf(A_log[d*DS + n]);
    float Dv = Dp[d];
    const float* dtp = dt  + (size_t)gch*LSEQ + c*CT;
    const float* up  = u   + (size_t)gch*LSEQ + c*CT;
    const float* zp  = z   + (size_t)gch*LSEQ + c*CT;
    const float* bp  = dbc + (size_t)(16 + n)*(NB*LSEQ) + b*LSEQ + c*CT;
    const float* cp  = dbc + (size_t)(32 + n)*(NB*LSEQ) + b*LSEQ + c*CT;
    float*       yp  = y   + (size_t)gch*LSEQ + c*CT;

    float h = hs[((size_t)gch*NCH + c)*DS + n];
#pragma unroll 4
    for (int l = 0; l < CT; ++l) {
        float dtv = dtp[l], uv = up[l];
        float bn = bp[l], cn = cp[l];
        float dA = __expf(dtv * A);
        h = dA * h + (dtv * uv) * bn;
        float yv = h * cn;
        yv += __shfl_xor_sync(0xffffffffu, yv, 1);
        yv += __shfl_xor_sync(0xffffffffu, yv, 2);
        yv += __shfl_xor_sync(0xffffffffu, yv, 4);
        yv += __shfl_xor_sync(0xffffffffu, yv, 8);
        if (n == 0) {
            float out = yv + uv * Dv;
            float zv = zp[l];
            float sg = zv / (1.f + __expf(-zv));
            yp[l] = out * sg;
        }
    }
}

// ---------------- batchnorm stats + apply + gelu ----------------
__global__ void bn_stats(const float* __restrict__ y2, float* __restrict__ mv) {
    int o = blockIdx.x;
    float s = 0.f, s2 = 0.f;
    for (int i = threadIdx.x; i < NB*LSEQ; i += 256) {
        int b = i >> 12, l = i & (LSEQ - 1);
        float v = y2[((size_t)b*128 + o)*LSEQ + l];
        s += v; s2 += v*v;
    }
    __shared__ float sh0[256], sh1[256];
    sh0[threadIdx.x] = s; sh1[threadIdx.x] = s2;
    __syncthreads();
    for (int st = 128; st > 0; st >>= 1) {
        if (threadIdx.x < st) {
            sh0[threadIdx.x] += sh0[threadIdx.x + st];
            sh1[threadIdx.x] += sh1[threadIdx.x + st];
        }
        __syncthreads();
    }
    if (threadIdx.x == 0) {
        float inv = 1.f / (NB * LSEQ);
        float mu = sh0[0] * inv;
        float var = sh1[0] * inv - mu * mu;
        mv[o] = mu; mv[128 + o] = var;
    }
}

__global__ void bn_apply(const float* __restrict__ y2, const float* __restrict__ mv,
                         const float* __restrict__ gamma, const float* __restrict__ beta,
                         float* __restrict__ out)
{
    int idx = blockIdx.x * blockDim.x + threadIdx.x;
    if (idx >= NB*128*LSEQ) return;
    int o = (idx >> 12) & 127;
    float mu = mv[o], var = mv[128 + o];
    float v = (y2[idx] - mu) * rsqrtf(var + 1e-5f) * gamma[o] + beta[o];
    out[idx] = 0.5f * v * (1.f + erff(v * 0.70710678118654752440f));
}

// ---------------- launch ----------------
extern "C" void kernel_launch(void* const* d_in, const int* in_sizes, int n_in,
                              void* d_out, int out_size)
{
    const float* x        = (const float*)d_in[0];
    const float* skip     = (const float*)d_in[1];
    const float* up_w     = (const float*)d_in[2];
    const float* up_b     = (const float*)d_in[3];
    const float* in_proj  = (const float*)d_in[4];
    const float* c1w      = (const float*)d_in[5];
    const float* c1b      = (const float*)d_in[6];
    const float* xproj    = (const float*)d_in[7];
    const float* dtw      = (const float*)d_in[8];
    const float* dtb      = (const float*)d_in[9];
    const float* A_log    = (const float*)d_in[10];
    const float* Dp       = (const float*)d_in[11];
    const float* outw     = (const float*)d_in[12];
    const float* cw       = (const float*)d_in[13];
    const float* cb       = (const float*)d_in[14];
    const float* bng      = (const float*)d_in[15];
    const float* bnb      = (const float*)d_in[16];
    float* out = (float*)d_out;

    float *xc, *xi, *z, *u, *dbc, *dtv, *y, *xr, *y2, *mv, *S, *hs, *sd;
    float *wt1, *wt2, *wt3, *wt4, *upw;
    cudaGetSymbolAddress((void**)&xc,  g_xc);
    cudaGetSymbolAddress((void**)&xi,  g_xi);
    cudaGetSymbolAddress((void**)&z,   g_z);
    cudaGetSymbolAddress((void**)&u,   g_u);
    cudaGetSymbolAddress((void**)&dbc, g_dbc);
    cudaGetSymbolAddress((void**)&dtv, g_dt);
    cudaGetSymbolAddress((void**)&y,   g_y);
    cudaGetSymbolAddress((void**)&xr,  g_xr);
    cudaGetSymbolAddress((void**)&y2,  g_y2);
    cudaGetSymbolAddress((void**)&mv,  g_mv);
    cudaGetSymbolAddress((void**)&S,   g_S);
    cudaGetSymbolAddress((void**)&hs,  g_hs);
    cudaGetSymbolAddress((void**)&sd,  g_sd);
    cudaGetSymbolAddress((void**)&wt1, g_wt1);
    cudaGetSymbolAddress((void**)&wt2, g_wt2);
    cudaGetSymbolAddress((void**)&wt3, g_wt3);
    cudaGetSymbolAddress((void**)&wt4, g_wt4);
    cudaGetSymbolAddress((void**)&upw, g_upw);

    cudaFuncSetAttribute(conv3_tc, cudaFuncAttributeMaxDynamicSharedMemorySize, C3_SMEM);
    cudaFuncSetAttribute(gemm128_tc<false, true,  EpiUp >, cudaFuncAttributeMaxDynamicSharedMemorySize, GT_SMEM);
    cudaFuncSetAttribute(gemm128_tc<true,  false, EpiXZ >, cudaFuncAttributeMaxDynamicSharedMemorySize, GT_SMEM);
    cudaFuncSetAttribute(gemm128_tc<true,  false, EpiDbc>, cudaFuncAttributeMaxDynamicSharedMemorySize, GT_SMEM);
    cudaFuncSetAttribute(gemm128_tc<true,  false, EpiOut>, cudaFuncAttributeMaxDynamicSharedMemorySize, GT_SMEM);

    // 0) merged prep: weight transposes/rounds + up_w round + skip concat copy
    prep_kernel<<<2272, 256>>>(in_proj, outw, xproj, cw, up_w, skip,
                               wt1, wt2, wt3, wt4, upw, xc);

    // 1) upsample GEMM (tf32 TC): A = pre-rounded up_w, B = x (cvt in-kernel)
    gemm128_tc<false, true, EpiUp><<<dim3(8, 4, NB), 256, GT_SMEM>>>(
        upw, 512, 0, x, 1024, (long)256*1024, 512, 1024, 256, EpiUp{xc, up_b});

    // 2) in_proj GEMM (tf32 TC): A = xc (cvt), B = wt1 (pre-rounded)
    gemm128_tc<true, false, EpiXZ><<<dim3(8, 32, NB), 256, GT_SMEM>>>(
        xc, LSEQ, (long)DM*LSEQ, wt1, 1024, 0, LSEQ, 2*DI, DM, EpiXZ{xi, z});

    // 3) depthwise conv1d + silu
    conv1d_kernel<<<dim3(LSEQ/128, DI/32, NB), 256>>>(xi, c1w, c1b, u);

    // 4) x_proj GEMM (tf32 TC, N padded 48->128): A = u (cvt), B = wt3 (pre-rounded)
    gemm128_tc<true, false, EpiDbc><<<dim3(1, 32, NB), 256, GT_SMEM>>>(
        u, LSEQ, (long)DI*LSEQ, wt3, 128, 0, LSEQ, 128, DI, EpiDbc{dbc});

    // 5) dt = softplus(dbc[:16]^T @ dtw^T + dtb)
    dt_kernel<<<NB*LSEQ/64, 256>>>(dbc, dtw, dtb, dtv);

    // 6) chunked selective scan
    scan_pass1<<<dim3(NCH, NB*DI/8), 128>>>(dtv, u, dbc, A_log, S, sd);
    scan_pass2<<<NB*DI/8, 128>>>(S, sd, A_log, hs);
    scan_pass3<<<dim3(NCH, NB*DI/8), 128>>>(dtv, u, dbc, z, A_log, Dp, hs, y);

    // 7) out_proj GEMM (tf32 TC) + residual
    gemm128_tc<true, false, EpiOut><<<dim3(2, 32, NB), 256, GT_SMEM>>>(
        y, LSEQ, (long)DI*LSEQ, wt2, 256, 0, LSEQ, DM, DI, EpiOut{xc, xr});

    // 8) 3x3 conv as TF32 implicit GEMM, 64-channel split (256 blocks)
    conv3_tc<<<dim3(64, 2, NB), 256, C3_SMEM>>>(xr, wt4, cb, y2);

    // 9) batchnorm stats
    bn_stats<<<128, 256>>>(y2, mv);

    // 10) batchnorm apply + gelu
    bn_apply<<<(NB*128*LSEQ + 255)/256, 256>>>(y2, mv, bng, bnb, out);
}

// round 14
// speedup vs baseline: 1.4089x; 1.0147x over previous
#include <cuda_runtime.h>
#include <math.h>
#include <stdint.h>

#define LSEQ 4096
#define DM   256
#define DI   512
#define DS   16
#define NB   2
#define NCH  64   // scan chunks
#define CT   64   // chunk length

// ---------------- scratch (device globals; no runtime alloc allowed) ----------------
__device__ __align__(16) float g_xc [NB*DM*LSEQ];    // (b, c=256, l)
__device__ __align__(16) float g_xi [NB*DI*LSEQ];    // (b, d, l)
__device__ __align__(16) float g_z  [NB*DI*LSEQ];    // (b, d, l)
__device__ __align__(16) float g_u  [NB*DI*LSEQ];    // (b, d, l)
__device__ __align__(16) float g_dbc[48*NB*LSEQ];    // (j=48, b*l)
__device__ __align__(16) float g_dt [NB*DI*LSEQ];    // (b, d, l)
__device__ __align__(16) float g_y  [NB*DI*LSEQ];    // (b, d, l)
__device__ __align__(16) float g_xr [NB*DM*LSEQ];    // (b, c, l)
__device__ __align__(16) float g_y2 [NB*128*LSEQ];   // (b, o, l)
__device__ __align__(16) float g_mv [256];
__device__ __align__(16) float g_S  [NB*DI*NCH*DS];
__device__ __align__(16) float g_hs [NB*DI*NCH*DS];
__device__ __align__(16) float g_sd [NB*DI*NCH];
__device__ __align__(16) float g_wt1[256*1024];      // in_proj_w^T  (k=256, n=1024), tf32-rounded
__device__ __align__(16) float g_wt2[512*256];       // out_proj_w^T (k=512, n=256),  tf32-rounded
__device__ __align__(16) float g_wt3[512*128];       // x_proj_w^T   (k=512, n=128 pad), tf32-rounded
__device__ __align__(16) float g_wt4[2304*128];      // conv_w^T     (k=c*9+t, o=128), tf32-rounded
__device__ __align__(16) float g_upw[256*512];       // up_w tf32-rounded (k=256 rows x m=512)

// ---------------- cp.async helpers ----------------
__device__ __forceinline__ void cp16(uint32_t dst, const float* src) {
    asm volatile("cp.async.cg.shared.global [%0], [%1], 16;\n" :: "r"(dst), "l"(src));
}
__device__ __forceinline__ void cp16z(uint32_t dst, const float* src, int sz) {
    asm volatile("cp.async.cg.shared.global [%0], [%1], 16, %2;\n" :: "r"(dst), "l"(src), "r"(sz));
}
__device__ __forceinline__ void cp_commit() {
    asm volatile("cp.async.commit_group;\n");
}
__device__ __forceinline__ void cp_wait_dyn(int allow) {
    if (allow <= 0)      asm volatile("cp.async.wait_group 0;\n");
    else                 asm volatile("cp.async.wait_group 1;\n");
}

// ---------------- tf32 helpers ----------------
__device__ __forceinline__ uint32_t f2tf(float f) {
    uint32_t r;
    asm("cvt.rna.tf32.f32 %0, %1;" : "=r"(r) : "f"(f));
    return r;
}
__device__ __forceinline__ float round_tf(float f) {
    return __uint_as_float(f2tf(f));
}
__device__ __forceinline__ void mma_tf32(float* c, const uint32_t* a, const uint32_t* b) {
    asm volatile(
        "mma.sync.aligned.m16n8k8.row.col.f32.tf32.tf32.f32 "
        "{%0,%1,%2,%3}, {%4,%5,%6,%7}, {%8,%9}, {%0,%1,%2,%3};"
        : "+f"(c[0]), "+f"(c[1]), "+f"(c[2]), "+f"(c[3])
        : "r"(a[0]), "r"(a[1]), "r"(a[2]), "r"(a[3]), "r"(b[0]), "r"(b[1]));
}

// ================= 128x128x16, 3-stage cp.async, TF32 tensor-core GEMM =================
// CA/CB: apply rna tf32 conversion to A/B fragments (false = operand pre-rounded).
// A k-major (A[k*lda+m]), B k-major (B[k*ldb+n]). M%128==0, N%128==0, K%16==0, K/16 >= 2.
// Epi::STAGED: smem-staged, fully-coalesced row stores (Epi::store_row).
#define GT_SMEM (2*3*16*132*4)
template<bool CA, bool CB, class Epi>
__global__ __launch_bounds__(256)
void gemm128_tc(const float* __restrict__ A, int lda, long sA,
                const float* __restrict__ B, int ldb, long sB,
                int M, int N, int K, Epi epi)
{
    extern __shared__ float smg[];
    float* Asm = smg;                 // [3][16][132]
    float* Bsm = smg + 3*16*132;
    const int tid = threadIdx.x;
    const int bz  = blockIdx.z;
    const float* Ab = A + (size_t)bz * sA;
    const float* Bb = B + (size_t)bz * sB;
    const int m0 = blockIdx.y * 128;
    const int n0 = blockIdx.x * 128;

    const int warp = tid >> 5;
    const int lane = tid & 31;
    const int gid  = lane >> 2;
    const int tig  = lane & 3;
    const int wm   = (warp >> 2) * 64;
    const int wn   = (warp & 3) * 32;

    float acc[4][4][4];
#pragma unroll
    for (int i = 0; i < 4; i++)
#pragma unroll
        for (int j = 0; j < 4; j++)
#pragma unroll
            for (int q = 0; q < 4; q++) acc[i][j][q] = 0.f;

    const int nt = K >> 4;

    auto ldtile = [&](int st, int k0) {
#pragma unroll
        for (int i = 0; i < 2; ++i) {
            int e  = i*256 + tid;          // 0..511
            int kr = e >> 5;               // 0..15
            int m4 = (e & 31) << 2;
            cp16((uint32_t)__cvta_generic_to_shared(Asm + (st*16 + kr)*132 + m4),
                 Ab + (size_t)(k0 + kr)*lda + m0 + m4);
            cp16((uint32_t)__cvta_generic_to_shared(Bsm + (st*16 + kr)*132 + m4),
                 Bb + (size_t)(k0 + kr)*ldb + n0 + m4);
        }
        cp_commit();
    };

    ldtile(0, 0);
    ldtile(1, 16);

    for (int kt = 0; kt < nt; ++kt) {
        cp_wait_dyn((kt + 1 < nt) ? 1 : 0);
        __syncthreads();
        if (kt + 2 < nt) {
            int st2 = (kt + 2) % 3;
            ldtile(st2, (kt + 2) << 4);
        }
        const int st = kt % 3;
        const float* As = Asm + st*16*132;
        const float* Bs = Bsm + st*16*132;

#pragma unroll
        for (int kb = 0; kb < 16; kb += 8) {
            uint32_t afr[4][4], bfr[4][2];
#pragma unroll
            for (int mt = 0; mt < 4; ++mt) {
                int mb = wm + mt*16 + gid;
                if (CA) {
                    afr[mt][0] = f2tf(As[(kb + tig    )*132 + mb]);
                    afr[mt][1] = f2tf(As[(kb + tig    )*132 + mb + 8]);
                    afr[mt][2] = f2tf(As[(kb + tig + 4)*132 + mb]);
                    afr[mt][3] = f2tf(As[(kb + tig + 4)*132 + mb + 8]);
                } else {
                    afr[mt][0] = __float_as_uint(As[(kb + tig    )*132 + mb]);
                    afr[mt][1] = __float_as_uint(As[(kb + tig    )*132 + mb + 8]);
                    afr[mt][2] = __float_as_uint(As[(kb + tig + 4)*132 + mb]);
                    afr[mt][3] = __float_as_uint(As[(kb + tig + 4)*132 + mb + 8]);
                }
            }
#pragma unroll
            for (int ntl = 0; ntl < 4; ++ntl) {
                int nb = wn + ntl*8 + gid;
                if (CB) {
                    bfr[ntl][0] = f2tf(Bs[(kb + tig    )*132 + nb]);
                    bfr[ntl][1] = f2tf(Bs[(kb + tig + 4)*132 + nb]);
                } else {
                    bfr[ntl][0] = __float_as_uint(Bs[(kb + tig    )*132 + nb]);
                    bfr[ntl][1] = __float_as_uint(Bs[(kb + tig + 4)*132 + nb]);
                }
            }
#pragma unroll
            for (int mt = 0; mt < 4; ++mt)
#pragma unroll
                for (int ntl = 0; ntl < 4; ++ntl)
                    mma_tf32(acc[mt][ntl], afr[mt], bfr[ntl]);
        }
    }

    if (Epi::STAGED) {
        // smem-staged coalesced epilogue: two 64-row halves of the n-dimension
        float* stage = smg;   // 64 x 132 floats = 33792 B <= GT_SMEM
        __syncthreads();
#pragma unroll
        for (int half = 0; half < 2; ++half) {
            if (((warp & 3) >> 1) == half) {
                int wns = wn - half*64;    // 0 or 32
#pragma unroll
                for (int mt = 0; mt < 4; ++mt)
#pragma unroll
                    for (int ntl = 0; ntl < 4; ++ntl) {
                        int nl = wns + ntl*8 + 2*tig;
                        int mm = wm + mt*16 + gid;
                        stage[(nl    )*132 + mm    ] = acc[mt][ntl][0];
                        stage[(nl + 1)*132 + mm    ] = acc[mt][ntl][1];
                        stage[(nl    )*132 + mm + 8] = acc[mt][ntl][2];
                        stage[(nl + 1)*132 + mm + 8] = acc[mt][ntl][3];
                    }
            }
            __syncthreads();
#pragma unroll
            for (int rr = 0; rr < 8; ++rr) {
                int nl = warp*8 + rr;
                float4 v = *reinterpret_cast<float4*>(stage + nl*132 + (lane << 2));
                epi.store_row(bz, n0 + half*64 + nl, m0 + (lane << 2), v);
            }
            __syncthreads();
        }
    } else {
#pragma unroll
        for (int mt = 0; mt < 4; ++mt) {
            int mb = m0 + wm + mt*16;
#pragma unroll
            for (int ntl = 0; ntl < 4; ++ntl) {
                int nb = n0 + wn + ntl*8;
                epi(bz, mb + gid,     nb + 2*tig,     acc[mt][ntl][0]);
                epi(bz, mb + gid,     nb + 2*tig + 1, acc[mt][ntl][1]);
                epi(bz, mb + gid + 8, nb + 2*tig,     acc[mt][ntl][2]);
                epi(bz, mb + gid + 8, nb + 2*tig + 1, acc[mt][ntl][3]);
            }
        }
    }
}

// ================= conv3x3 as TF32 implicit GEMM, 64 out-ch per block =================
// grid (64 rows, 2 channel-halves, NB). Dyn smem: 2*72*68 + 2*24*68 floats = 52224 B.
#define C3_SMEM ((2*72*68 + 2*24*68)*4)
__global__ __launch_bounds__(256)
void conv3_tc(const float* __restrict__ xr, const float* __restrict__ Wt,
              const float* __restrict__ bias, float* __restrict__ y2)
{
    extern __shared__ float sm[];
    float* Asm = sm;                       // 2 bufs x 72 x 68
    float* Ism = sm + 2*72*68;             // 2 bufs x 24 x 68

    const int b  = blockIdx.z;
    const int oh = blockIdx.y;             // 0/1 -> channels 0..63 / 64..127
    const int h  = blockIdx.x;             // output row 0..63
    const int tid = threadIdx.x;
    const int warp = tid >> 5;
    const int lane = tid & 31;
    const int gid  = lane >> 2;
    const int tig  = lane & 3;
    const int wm   = (warp >> 1) * 16;     // 0,16,32,48
    const int wn   = (warp & 1) * 32;      // 0,32

    float acc[4][4];
#pragma unroll
    for (int j = 0; j < 4; j++)
#pragma unroll
        for (int q = 0; q < 4; q++) acc[j][q] = 0.f;

    const float* xrb = xr + (size_t)b * DM * LSEQ;

    auto ld_chunk = [&](int buf, int c0) {
        float* Ab = Asm + buf*72*68;
#pragma unroll
        for (int i = 0; i < 5; ++i) {
            int e = i*256 + tid;           // need 1152 float4
            if (e < 1152) {
                int k  = e >> 4;           // 0..71
                int m4 = (e & 15) << 2;    // 0..60
                cp16((uint32_t)__cvta_generic_to_shared(Ab + k*68 + m4),
                     Wt + (size_t)(c0*9 + k)*128 + oh*64 + m4);
            }
        }
        float* Ib = Ism + buf*24*68;
#pragma unroll
        for (int i = 0; i < 2; ++i) {
            int e = i*256 + tid;
            if (e < 384) {
                int row = e >> 4;          // 0..23 = ci*3+di
                int di  = row % 3;
                int ci  = row / 3;
                int x4  = (e & 15) << 2;
                int hh  = h + di - 1;
                int ok  = (hh >= 0 && hh < 64) ? 16 : 0;
                int hc  = ok ? hh : 0;
                cp16z((uint32_t)__cvta_generic_to_shared(Ib + row*68 + x4),
                      xrb + (size_t)(c0 + ci)*LSEQ + hc*64 + x4, ok);
            }
        }
        cp_commit();
    };

    ld_chunk(0, 0);

    for (int c = 0; c < 32; ++c) {
        cp_wait_dyn(0);
        __syncthreads();
        if (c + 1 < 32) ld_chunk((c + 1) & 1, (c + 1) * 8);

        const float* Ab = Asm + (c & 1)*72*68;
        const float* Ib = Ism + (c & 1)*24*68;

#pragma unroll
        for (int kk = 0; kk < 9; ++kk) {
            const int kb = kk * 8;
            uint32_t afr[4], bfr[4][2];
            {
                int mb = wm + gid;
                afr[0] = __float_as_uint(Ab[(kb + tig    )*68 + mb]);
                afr[1] = __float_as_uint(Ab[(kb + tig    )*68 + mb + 8]);
                afr[2] = __float_as_uint(Ab[(kb + tig + 4)*68 + mb]);
                afr[3] = __float_as_uint(Ab[(kb + tig + 4)*68 + mb + 8]);
            }
            int k0 = kb + tig, k1 = kb + tig + 4;
            int ci0 = k0 / 9, t0 = k0 - ci0*9, di0 = t0 / 3, dj0 = t0 - di0*3;
            int ci1 = k1 / 9, t1 = k1 - ci1*9, di1 = t1 / 3, dj1 = t1 - di1*3;
            const float* r0 = Ib + (ci0*3 + di0)*68;
            const float* r1 = Ib + (ci1*3 + di1)*68;
#pragma unroll
            for (int ntl = 0; ntl < 4; ++ntl) {
                int w = wn + ntl*8 + gid;
                int x0 = w + dj0 - 1;
                int x1 = w + dj1 - 1;
                float v0 = (x0 >= 0 && x0 < 64) ? r0[x0] : 0.f;
                float v1 = (x1 >= 0 && x1 < 64) ? r1[x1] : 0.f;
                bfr[ntl][0] = f2tf(v0);
                bfr[ntl][1] = f2tf(v1);
            }
#pragma unroll
            for (int ntl = 0; ntl < 4; ++ntl)
                mma_tf32(acc[ntl], afr, bfr[ntl]);
        }
        __syncthreads();
    }

    // smem-staged coalesced epilogue: stage 64(ch) x 64(w) tile, write float2 rows
    {
        float* stage = Asm;   // 64*68 floats <= 2*72*68
#pragma unroll
        for (int ntl = 0; ntl < 4; ++ntl) {
            int w = wn + ntl*8 + 2*tig;
            int o = wm + gid;
            stage[(o    )*68 + w    ] = acc[ntl][0];
            stage[(o    )*68 + w + 1] = acc[ntl][1];
            stage[(o + 8)*68 + w    ] = acc[ntl][2];
            stage[(o + 8)*68 + w + 1] = acc[ntl][3];
        }
        __syncthreads();
#pragma unroll
        for (int rr = 0; rr < 8; ++rr) {
            int o = warp*8 + rr;
            float2 v = *reinterpret_cast<float2*>(stage + o*68 + (lane << 1));
            float bv = bias[oh*64 + o];
            float2 w2 = make_float2(v.x + bv, v.y + bv);
            *reinterpret_cast<float2*>(
                y2 + ((size_t)b*128 + oh*64 + o)*LSEQ + h*64 + (lane << 1)) = w2;
        }
    }
}

// ---------------- merged prep: all weight transposes+rounds, up_w round, skip copy ----------------
__device__ __forceinline__ void transp_tile(const float* __restrict__ in, float* __restrict__ out,
                                            int R, int C, int Rp, int bx, int by)
{
    __shared__ float t[32][33];
    int r0 = by * 32, c0 = bx * 32;
    int x = threadIdx.x & 31, y = (threadIdx.x >> 5) ;
    for (int i = y; i < 32; i += 8) {
        int r = r0 + i, c = c0 + x;
        t[i][x] = (r < R && c < C) ? round_tf(in[(size_t)r*C + c]) : 0.f;
    }
    __syncthreads();
    for (int i = y; i < 32; i += 8) {
        int c = c0 + i, r = r0 + x;
        if (c < C && r < Rp) out[(size_t)c*Rp + r] = t[x][i];
    }
}

__global__ __launch_bounds__(256)
void prep_kernel(const float* __restrict__ in_proj, const float* __restrict__ outw,
                 const float* __restrict__ xproj,   const float* __restrict__ cw,
                 const float* __restrict__ up_w,    const float* __restrict__ skip,
                 float* __restrict__ wt1, float* __restrict__ wt2,
                 float* __restrict__ wt3, float* __restrict__ wt4,
                 float* __restrict__ upw, float* __restrict__ xc)
{
    int bid = blockIdx.x;
    if (bid < 256) {                 // wt1: in_proj (1024x256) -> (256,1024)
        transp_tile(in_proj, wt1, 1024, 256, 1024, bid & 7, bid >> 3);
    } else if (bid < 384) {          // wt2: outw (256x512) -> (512,256)
        int id = bid - 256;
        transp_tile(outw, wt2, 256, 512, 256, id & 15, id >> 4);
    } else if (bid < 448) {          // wt3: xproj (48x512) -> (512,128 pad)
        int id = bid - 384;
        transp_tile(xproj, wt3, 48, 512, 128, id & 15, id >> 4);
    } else if (bid < 736) {          // wt4: cw (128x2304) -> (2304,128)
        int id = bid - 448;
        transp_tile(cw, wt4, 128, 2304, 128, id % 72, id / 72);
    } else if (bid < 1248) {         // upw round copy
        int idx = (bid - 736) * 256 + threadIdx.x;
        upw[idx] = round_tf(up_w[idx]);
    } else {                         // skip copy (float4)
        int idx = (bid - 1248) * 256 + threadIdx.x;
        const float4* s4 = reinterpret_cast<const float4*>(skip);
        float4* x4 = reinterpret_cast<float4*>(xc);
        int b = idx >> 17;
        int rem = idx & 131071;
        x4[(size_t)(b*256 + 128)*1024 + rem] = s4[(size_t)b*131072 + rem];
    }
}

// ---------------- epilogues ----------------
struct EpiUp {
    static const bool STAGED = false;
    float* xc; const float* up_b;
    __device__ void operator()(int b, int m, int n, float v) const {
        int o = m >> 2, i = (m >> 1) & 1, j = m & 1;
        int h = n >> 5, w = n & 31;
        xc[((size_t)b*DM + o)*LSEQ + (2*h + i)*64 + (2*w + j)] = v + up_b[o];
    }
    __device__ void store_row(int, int, int, float4) const {}
};
struct EpiXZ {
    static const bool STAGED = true;
    float* xi; float* z;
    __device__ void operator()(int, int, int, float) const {}
    __device__ void store_row(int b, int n, int m, float4 v) const {
        float* p = (n < DI) ? xi + ((size_t)b*DI + n)*LSEQ + m
                            : z  + ((size_t)b*DI + (n - DI))*LSEQ + m;
        *reinterpret_cast<float4*>(p) = v;
    }
};
struct EpiDbc {
    static const bool STAGED = true;
    float* dbc;
    __device__ void operator()(int, int, int, float) const {}
    __device__ void store_row(int b, int n, int m, float4 v) const {
        if (n < 48)
            *reinterpret_cast<float4*>(dbc + (size_t)n*(NB*LSEQ) + b*LSEQ + m) = v;
    }
};
struct EpiOut {
    static const bool STAGED = true;
    const float* xc; float* xr;
    __device__ void operator()(int, int, int, float) const {}
    __device__ void store_row(int b, int n, int m, float4 v) const {
        size_t idx = ((size_t)b*DM + n)*LSEQ + m;
        float4 c = *reinterpret_cast<const float4*>(xc + idx);
        v.x += c.x; v.y += c.y; v.z += c.z; v.w += c.w;
        *reinterpret_cast<float4*>(xr + idx) = v;
    }
};

// ---------------- depthwise causal conv1d + silu (coalesced) ----------------
__global__ __launch_bounds__(256)
void conv1d_kernel(const float* __restrict__ xi, const float* __restrict__ w,
                   const float* __restrict__ bias, float* __restrict__ u)
{
    __shared__ float s[32][132];
    __shared__ float sw[32][4];
    __shared__ float sb[32];
    int b  = blockIdx.z;
    int d0 = blockIdx.y * 32;
    int l0 = blockIdx.x * 128;
    int tid = threadIdx.x;
    for (int e = tid; e < 32*132; e += 256) {
        int dd = e / 132, li = e - dd*132;
        if (li < 131) {
            int l = l0 - 3 + li;
            s[dd][li] = (l >= 0 && l < LSEQ) ? xi[((size_t)b*DI + d0 + dd)*LSEQ + l] : 0.f;
        }
    }
    if (tid < 128) sw[tid >> 2][tid & 3] = w[(d0 + (tid >> 2))*4 + (tid & 3)];
    if (tid < 32)  sb[tid] = bias[d0 + tid];
    __syncthreads();
#pragma unroll
    for (int it = 0; it < 16; ++it) {
        int idx = it*256 + tid;
        int dd = idx >> 7, li = idx & 127;
        float a = s[dd][li]*sw[dd][0] + s[dd][li+1]*sw[dd][1]
                + s[dd][li+2]*sw[dd][2] + s[dd][li+3]*sw[dd][3] + sb[dd];
        float sv = a / (1.f + __expf(-a));
        u[((size_t)b*DI + d0 + dd)*LSEQ + l0 + li] = sv;
    }
}

// ---------------- dt = softplus(dbc[:,:16] @ dtw^T + dtb), out (b,d,l) ----------------
__global__ __launch_bounds__(256)
void dt_kernel(const float* __restrict__ dbc, const float* __restrict__ dtw,
               const float* __restrict__ dtb, float* __restrict__ dt)
{
    __shared__ float swt[DI*16];
    __shared__ float sbc[16*64];
    __shared__ float sbias[DI];
    int bl0 = blockIdx.x * 64;
    int tid = threadIdx.x;
    for (int i = tid; i < DI*16; i += 256) swt[i] = dtw[i];
    for (int i = tid; i < DI; i += 256) sbias[i] = dtb[i];
    for (int i = tid; i < 16*64; i += 256) {
        int r = i >> 6, li = i & 63;
        sbc[i] = dbc[(size_t)r*(NB*LSEQ) + bl0 + li];
    }
    __syncthreads();
    int b  = bl0 >> 12;
    int l0 = bl0 & (LSEQ - 1);
#pragma unroll 4
    for (int it = 0; it < 128; ++it) {
        int idx = it*256 + tid;
        int d = idx >> 6, li = idx & 63;
        float acc = sbias[d];
#pragma unroll
        for (int r = 0; r < 16; ++r) acc += swt[d*16 + r] * sbc[r*64 + li];
        float sp = (acc > 20.f) ? acc : log1pf(__expf(acc));
        dt[((size_t)b*DI + d)*LSEQ + l0 + li] = sp;
    }
}

// ================= chunked selective scan =================
__global__ __launch_bounds__(128)
void scan_pass1(const float* __restrict__ dt, const float* __restrict__ u,
                const float* __restrict__ dbc, const float* __restrict__ A_log,
                float* __restrict__ S, float* __restrict__ sd)
{
    int lane = threadIdx.x & 31;
    int n    = lane & 15;
    int half = lane >> 4;
    int warp = threadIdx.x >> 5;
    int gch  = blockIdx.y * 8 + warp * 2 + half;
    int c    = blockIdx.x;
    int b = gch >> 9, d = gch & (DI - 1);

    float A = -__expf(A_log[d*DS + n]);
    const float* dtp = dt  + (size_t)gch*LSEQ + c*CT;
    const float* up  = u   + (size_t)gch*LSEQ + c*CT;
    const float* bp  = dbc + (size_t)(16 + n)*(NB*LSEQ) + b*LSEQ + c*CT;

    float h = 0.f, sda = 0.f;
#pragma unroll 8
    for (int l = 0; l < CT; ++l) {
        float dtv = dtp[l], uv = up[l], bn = bp[l];
        float dA = __expf(dtv * A);
        h = dA * h + (dtv * uv) * bn;
        sda += dtv;
    }
    S[((size_t)gch*NCH + c)*DS + n] = h;
    if (n == 0) sd[(size_t)gch*NCH + c] = sda;
}

__global__ __launch_bounds__(128)
void scan_pass2(const float* __restrict__ S, const float* __restrict__ sd,
                const float* __restrict__ A_log, float* __restrict__ hs)
{
    int lane = threadIdx.x & 31;
    int n    = lane & 15;
    int half = lane >> 4;
    int warp = threadIdx.x >> 5;
    int gch  = blockIdx.x * 8 + warp * 2 + half;
    int d = gch & (DI - 1);
    float A = -__expf(A_log[d*DS + n]);
    float h = 0.f;
    for (int c = 0; c < NCH; ++c) {
        size_t idx = ((size_t)gch*NCH + c)*DS + n;
        hs[idx] = h;
        float P = __expf(A * sd[(size_t)gch*NCH + c]);
        h = P * h + S[idx];
    }
}

__global__ __launch_bounds__(128)
void scan_pass3(const float* __restrict__ dt, const float* __restrict__ u,
                const float* __restrict__ dbc, const float* __restrict__ z,
                const float* __restrict__ A_log, const float* __restrict__ Dp,
                const float* __restrict__ hs, float* __restrict__ y)
{
    int lane = threadIdx.x & 31;
    int n    = lane & 15;
    int half = lane >> 4;
    int warp = threadIdx.x >> 5;
    int gch  = blockIdx.y * 8 + warp * 2 + half;
    int c    = blockIdx.x;
    int b = gch >> 9, d = gch & (DI - 1);

    float A  = -__expf(A_log[d*DS + n]);
    float Dv = Dp[d];
    const float* dtp = dt  + (size_t)gch*LSEQ + c*CT;
    const float* up  = u   + (size_t)gch*LSEQ + c*CT;
    const float* zp  = z   + (size_t)gch*LSEQ + c*CT;
    const float* bp  = dbc + (size_t)(16 + n)*(NB*LSEQ) + b*LSEQ + c*CT;
    const float* cp  = dbc + (size_t)(32 + n)*(NB*LSEQ) + b*LSEQ + c*CT;
    float*       yp  = y   + (size_t)gch*LSEQ + c*CT;

    float h = hs[((size_t)gch*NCH + c)*DS + n];
#pragma unroll 4
    for (int l = 0; l < CT; ++l) {
        float dtv = dtp[l], uv = up[l];
        float bn = bp[l], cn = cp[l];
        float dA = __expf(dtv * A);
        h = dA * h + (dtv * uv) * bn;
        float yv = h * cn;
        yv += __shfl_xor_sync(0xffffffffu, yv, 1);
        yv += __shfl_xor_sync(0xffffffffu, yv, 2);
        yv += __shfl_xor_sync(0xffffffffu, yv, 4);
        yv += __shfl_xor_sync(0xffffffffu, yv, 8);
        if (n == 0) {
            float out = yv + uv * Dv;
            float zv = zp[l];
            float sg = zv / (1.f + __expf(-zv));
            yp[l] = out * sg;
        }
    }
}

// ---------------- batchnorm stats + apply + gelu ----------------
__global__ void bn_stats(const float* __restrict__ y2, float* __restrict__ mv) {
    int o = blockIdx.x;
    float s = 0.f, s2 = 0.f;
    for (int i = threadIdx.x; i < NB*LSEQ; i += 256) {
        int b = i >> 12, l = i & (LSEQ - 1);
        float v = y2[((size_t)b*128 + o)*LSEQ + l];
        s += v; s2 += v*v;
    }
    __shared__ float sh0[256], sh1[256];
    sh0[threadIdx.x] = s; sh1[threadIdx.x] = s2;
    __syncthreads();
    for (int st = 128; st > 0; st >>= 1) {
        if (threadIdx.x < st) {
            sh0[threadIdx.x] += sh0[threadIdx.x + st];
            sh1[threadIdx.x] += sh1[threadIdx.x + st];
        }
        __syncthreads();
    }
    if (threadIdx.x == 0) {
        float inv = 1.f / (NB * LSEQ);
        float mu = sh0[0] * inv;
        float var = sh1[0] * inv - mu * mu;
        mv[o] = mu; mv[128 + o] = var;
    }
}

__global__ void bn_apply(const float* __restrict__ y2, const float* __restrict__ mv,
                         const float* __restrict__ gamma, const float* __restrict__ beta,
                         float* __restrict__ out)
{
    int idx = blockIdx.x * blockDim.x + threadIdx.x;
    if (idx >= NB*128*LSEQ) return;
    int o = (idx >> 12) & 127;
    float mu = mv[o], var = mv[128 + o];
    float v = (y2[idx] - mu) * rsqrtf(var + 1e-5f) * gamma[o] + beta[o];
    out[idx] = 0.5f * v * (1.f + erff(v * 0.70710678118654752440f));
}

// ---------------- launch ----------------
extern "C" void kernel_launch(void* const* d_in, const int* in_sizes, int n_in,
                              void* d_out, int out_size)
{
    const float* x        = (const float*)d_in[0];
    const float* skip     = (const float*)d_in[1];
    const float* up_w     = (const float*)d_in[2];
    const float* up_b     = (const float*)d_in[3];
    const float* in_proj  = (const float*)d_in[4];
    const float* c1w      = (const float*)d_in[5];
    const float* c1b      = (const float*)d_in[6];
    const float* xproj    = (const float*)d_in[7];
    const float* dtw      = (const float*)d_in[8];
    const float* dtb      = (const float*)d_in[9];
    const float* A_log    = (const float*)d_in[10];
    const float* Dp       = (const float*)d_in[11];
    const float* outw     = (const float*)d_in[12];
    const float* cw       = (const float*)d_in[13];
    const float* cb       = (const float*)d_in[14];
    const float* bng      = (const float*)d_in[15];
    const float* bnb      = (const float*)d_in[16];
    float* out = (float*)d_out;

    float *xc, *xi, *z, *u, *dbc, *dtv, *y, *xr, *y2, *mv, *S, *hs, *sd;
    float *wt1, *wt2, *wt3, *wt4, *upw;
    cudaGetSymbolAddress((void**)&xc,  g_xc);
    cudaGetSymbolAddress((void**)&xi,  g_xi);
    cudaGetSymbolAddress((void**)&z,   g_z);
    cudaGetSymbolAddress((void**)&u,   g_u);
    cudaGetSymbolAddress((void**)&dbc, g_dbc);
    cudaGetSymbolAddress((void**)&dtv, g_dt);
    cudaGetSymbolAddress((void**)&y,   g_y);
    cudaGetSymbolAddress((void**)&xr,  g_xr);
    cudaGetSymbolAddress((void**)&y2,  g_y2);
    cudaGetSymbolAddress((void**)&mv,  g_mv);
    cudaGetSymbolAddress((void**)&S,   g_S);
    cudaGetSymbolAddress((void**)&hs,  g_hs);
    cudaGetSymbolAddress((void**)&sd,  g_sd);
    cudaGetSymbolAddress((void**)&wt1, g_wt1);
    cudaGetSymbolAddress((void**)&wt2, g_wt2);
    cudaGetSymbolAddress((void**)&wt3, g_wt3);
    cudaGetSymbolAddress((void**)&wt4, g_wt4);
    cudaGetSymbolAddress((void**)&upw, g_upw);

    cudaFuncSetAttribute(conv3_tc, cudaFuncAttributeMaxDynamicSharedMemorySize, C3_SMEM);
    cudaFuncSetAttribute(gemm128_tc<false, true,  EpiUp >, cudaFuncAttributeMaxDynamicSharedMemorySize, GT_SMEM);
    cudaFuncSetAttribute(gemm128_tc<true,  false, EpiXZ >, cudaFuncAttributeMaxDynamicSharedMemorySize, GT_SMEM);
    cudaFuncSetAttribute(gemm128_tc<true,  false, EpiDbc>, cudaFuncAttributeMaxDynamicSharedMemorySize, GT_SMEM);
    cudaFuncSetAttribute(gemm128_tc<true,  false, EpiOut>, cudaFuncAttributeMaxDynamicSharedMemorySize, GT_SMEM);

    // 0) merged prep: weight transposes/rounds + up_w round + skip concat copy
    prep_kernel<<<2272, 256>>>(in_proj, outw, xproj, cw, up_w, skip,
                               wt1, wt2, wt3, wt4, upw, xc);

    // 1) upsample GEMM (tf32 TC): A = pre-rounded up_w, B = x (cvt in-kernel)
    gemm128_tc<false, true, EpiUp><<<dim3(8, 4, NB), 256, GT_SMEM>>>(
        upw, 512, 0, x, 1024, (long)256*1024, 512, 1024, 256, EpiUp{xc, up_b});

    // 2) in_proj GEMM (tf32 TC), staged coalesced epilogue
    gemm128_tc<true, false, EpiXZ><<<dim3(8, 32, NB), 256, GT_SMEM>>>(
        xc, LSEQ, (long)DM*LSEQ, wt1, 1024, 0, LSEQ, 2*DI, DM, EpiXZ{xi, z});

    // 3) depthwise conv1d + silu
    conv1d_kernel<<<dim3(LSEQ/128, DI/32, NB), 256>>>(xi, c1w, c1b, u);

    // 4) x_proj GEMM (tf32 TC, N padded 48->128), staged epilogue
    gemm128_tc<true, false, EpiDbc><<<dim3(1, 32, NB), 256, GT_SMEM>>>(
        u, LSEQ, (long)DI*LSEQ, wt3, 128, 0, LSEQ, 128, DI, EpiDbc{dbc});

    // 5) dt = softplus(dbc[:16]^T @ dtw^T + dtb)
    dt_kernel<<<NB*LSEQ/64, 256>>>(dbc, dtw, dtb, dtv);

    // 6) chunked selective scan
    scan_pass1<<<dim3(NCH, NB*DI/8), 128>>>(dtv, u, dbc, A_log, S, sd);
    scan_pass2<<<NB*DI/8, 128>>>(S, sd, A_log, hs);
    scan_pass3<<<dim3(NCH, NB*DI/8), 128>>>(dtv, u, dbc, z, A_log, Dp, hs, y);

    // 7) out_proj GEMM (tf32 TC) + residual, staged epilogue
    gemm128_tc<true, false, EpiOut><<<dim3(2, 32, NB), 256, GT_SMEM>>>(
        y, LSEQ, (long)DI*LSEQ, wt2, 256, 0, LSEQ, DM, DI, EpiOut{xc, xr});

    // 8) 3x3 conv as TF32 implicit GEMM, staged epilogue (256 blocks)
    conv3_tc<<<dim3(64, 2, NB), 256, C3_SMEM>>>(xr, wt4, cb, y2);

    // 9) batchnorm stats
    bn_stats<<<128, 256>>>(y2, mv);

    // 10) batchnorm apply + gelu
    bn_apply<<<(NB*128*LSEQ + 255)/256, 256>>>(y2, mv, bng, bnb, out);
}

// round 15
// speedup vs baseline: 1.4436x; 1.0246x over previous
#include <cuda_runtime.h>
#include <math.h>
#include <stdint.h>

#define LSEQ 4096
#define DM   256
#define DI   512
#define DS   16
#define NB   2
#define NCH  64   // scan chunks
#define CT   64   // chunk length

// ---------------- scratch (device globals; no runtime alloc allowed) ----------------
__device__ __align__(16) float g_xc [NB*DM*LSEQ];    // (b, c=256, l)
__device__ __align__(16) float g_xi [NB*DI*LSEQ];    // (b, d, l)
__device__ __align__(16) float g_z  [NB*DI*LSEQ];    // (b, d, l)
__device__ __align__(16) float g_u  [NB*DI*LSEQ];    // (b, d, l)
__device__ __align__(16) float g_dbc[48*NB*LSEQ];    // (j=48, b*l)
__device__ __align__(16) float g_dt [NB*DI*LSEQ];    // (b, d, l)
__device__ __align__(16) float g_y  [NB*DI*LSEQ];    // (b, d, l)
__device__ __align__(16) float g_xr [NB*DM*LSEQ];    // (b, c, l)
__device__ __align__(16) float g_y2 [NB*128*LSEQ];   // (b, o, l)
__device__ __align__(16) float g_S  [NB*DI*NCH*DS];
__device__ __align__(16) float g_hs [NB*DI*NCH*DS];
__device__ __align__(16) float g_sd [NB*DI*NCH];
// packed weights: [K/16][N][16] with k-perm (p -> k = (p%4)*4 + p/4), tf32-rounded
__device__ __align__(16) float g_wp1[16*1024*16];    // in_proj_w  (K=256, N=1024)
__device__ __align__(16) float g_wp2[32*256*16];     // out_proj_w (K=512, N=256)
__device__ __align__(16) float g_wp3[32*128*16];     // x_proj_w   (K=512, N=128 pad)
__device__ __align__(16) float g_upp[16*512*16];     // up_w packed as A (K=256, M=512)
__device__ __align__(16) float g_wt4[2304*128];      // conv_w^T (k=c*9+t, o=128), tf32-rounded

// ---------------- cp.async helpers ----------------
__device__ __forceinline__ void cp16(uint32_t dst, const float* src) {
    asm volatile("cp.async.cg.shared.global [%0], [%1], 16;\n" :: "r"(dst), "l"(src));
}
__device__ __forceinline__ void cp16z(uint32_t dst, const float* src, int sz) {
    asm volatile("cp.async.cg.shared.global [%0], [%1], 16, %2;\n" :: "r"(dst), "l"(src), "r"(sz));
}
__device__ __forceinline__ void cp_commit() {
    asm volatile("cp.async.commit_group;\n");
}
__device__ __forceinline__ void cp_wait_dyn(int allow) {
    if (allow <= 0)      asm volatile("cp.async.wait_group 0;\n");
    else                 asm volatile("cp.async.wait_group 1;\n");
}

// ---------------- tf32 helpers ----------------
__device__ __forceinline__ uint32_t f2tf(float f) {
    uint32_t r;
    asm("cvt.rna.tf32.f32 %0, %1;" : "=r"(r) : "f"(f));
    return r;
}
__device__ __forceinline__ float round_tf(float f) {
    return __uint_as_float(f2tf(f));
}
__device__ __forceinline__ void mma_tf32(float* c, const uint32_t* a, const uint32_t* b) {
    asm volatile(
        "mma.sync.aligned.m16n8k8.row.col.f32.tf32.tf32.f32 "
        "{%0,%1,%2,%3}, {%4,%5,%6,%7}, {%8,%9}, {%0,%1,%2,%3};"
        : "+f"(c[0]), "+f"(c[1]), "+f"(c[2]), "+f"(c[3])
        : "r"(a[0]), "r"(a[1]), "r"(a[2]), "r"(a[3]), "r"(b[0]), "r"(b[1]));
}

// ================= 128x128x16, 3-stage cp.async, TF32 tensor-core GEMM =================
// CA/CB true: operand is an activation in k-major layout; fragments loaded scalar + cvt.
// CA/CB false: operand is a PRE-PACKED weight [K/16][rows][16] (perm-k); fragments via LDS.128.
// lda/ldb: k-major leading dim (activations) or total packed rows (weights).
#define GT_SMEM ((3*16*132 + 3*2048)*4)
template<bool CA, bool CB, class Epi>
__global__ __launch_bounds__(256)
void gemm128_tc(const float* __restrict__ A, int lda, long sA,
                const float* __restrict__ B, int ldb, long sB,
                int M, int N, int K, Epi epi)
{
    extern __shared__ float smg[];
    constexpr int ASZ = CA ? 16*132 : 2048;
    constexpr int BSZ = CB ? 16*132 : 2048;
    float* Asm = smg;
    float* Bsm = smg + 3*ASZ;
    const int tid = threadIdx.x;
    const int bz  = blockIdx.z;
    const float* Ab = A + (size_t)bz * sA;
    const float* Bb = B + (size_t)bz * sB;
    const int m0 = blockIdx.y * 128;
    const int n0 = blockIdx.x * 128;

    const int warp = tid >> 5;
    const int lane = tid & 31;
    const int gid  = lane >> 2;
    const int tig  = lane & 3;
    const int wm   = (warp >> 2) * 64;
    const int wn   = (warp & 3) * 32;

    float acc[4][4][4];
#pragma unroll
    for (int i = 0; i < 4; i++)
#pragma unroll
        for (int j = 0; j < 4; j++)
#pragma unroll
            for (int q = 0; q < 4; q++) acc[i][j][q] = 0.f;

    const int nt = K >> 4;

    auto ldtile = [&](int st, int k0) {
#pragma unroll
        for (int i = 0; i < 2; ++i) {
            int e  = i*256 + tid;          // 0..511
            if (CA) {
                int kr = e >> 5, m4 = (e & 31) << 2;
                cp16((uint32_t)__cvta_generic_to_shared(Asm + st*ASZ + kr*132 + m4),
                     Ab + (size_t)(k0 + kr)*lda + m0 + m4);
            } else {
                int mr = e >> 2, pq = (e & 3) << 2;
                cp16((uint32_t)__cvta_generic_to_shared(Asm + st*ASZ + mr*16 + pq),
                     Ab + ((size_t)(k0 >> 4)*lda + m0 + mr)*16 + pq);
            }
            if (CB) {
                int kr = e >> 5, m4 = (e & 31) << 2;
                cp16((uint32_t)__cvta_generic_to_shared(Bsm + st*BSZ + kr*132 + m4),
                     Bb + (size_t)(k0 + kr)*ldb + n0 + m4);
            } else {
                int nr = e >> 2, pq = (e & 3) << 2;
                cp16((uint32_t)__cvta_generic_to_shared(Bsm + st*BSZ + nr*16 + pq),
                     Bb + ((size_t)(k0 >> 4)*ldb + n0 + nr)*16 + pq);
            }
        }
        cp_commit();
    };

    ldtile(0, 0);
    ldtile(1, 16);

    for (int kt = 0; kt < nt; ++kt) {
        cp_wait_dyn((kt + 1 < nt) ? 1 : 0);
        __syncthreads();
        if (kt + 2 < nt) ldtile((kt + 2) % 3, (kt + 2) << 4);

        const int st = kt % 3;
        const float* As = Asm + st*ASZ;
        const float* Bs = Bsm + st*BSZ;

        float4 qa[4][2], qb[4];
        if (!CA) {
#pragma unroll
            for (int mt = 0; mt < 4; ++mt) {
                int mb = wm + mt*16 + gid;
                qa[mt][0] = *reinterpret_cast<const float4*>(As + mb*16 + tig*4);
                qa[mt][1] = *reinterpret_cast<const float4*>(As + (mb + 8)*16 + tig*4);
            }
        }
        if (!CB) {
#pragma unroll
            for (int ntl = 0; ntl < 4; ++ntl) {
                int nb = wn + ntl*8 + gid;
                qb[ntl] = *reinterpret_cast<const float4*>(Bs + nb*16 + tig*4);
            }
        }

#pragma unroll
        for (int kbi = 0; kbi < 2; ++kbi) {
            const int kb = kbi * 8;
            uint32_t afr[4][4], bfr[4][2];
#pragma unroll
            for (int mt = 0; mt < 4; ++mt) {
                if (CA) {
                    int mb = wm + mt*16 + gid;
                    afr[mt][0] = f2tf(As[(kb + tig    )*132 + mb]);
                    afr[mt][1] = f2tf(As[(kb + tig    )*132 + mb + 8]);
                    afr[mt][2] = f2tf(As[(kb + tig + 4)*132 + mb]);
                    afr[mt][3] = f2tf(As[(kb + tig + 4)*132 + mb + 8]);
                } else {
                    afr[mt][0] = __float_as_uint(kbi ? qa[mt][0].z : qa[mt][0].x);
                    afr[mt][1] = __float_as_uint(kbi ? qa[mt][1].z : qa[mt][1].x);
                    afr[mt][2] = __float_as_uint(kbi ? qa[mt][0].w : qa[mt][0].y);
                    afr[mt][3] = __float_as_uint(kbi ? qa[mt][1].w : qa[mt][1].y);
                }
            }
#pragma unroll
            for (int ntl = 0; ntl < 4; ++ntl) {
                if (CB) {
                    int nb = wn + ntl*8 + gid;
                    bfr[ntl][0] = f2tf(Bs[(kb + tig    )*132 + nb]);
                    bfr[ntl][1] = f2tf(Bs[(kb + tig + 4)*132 + nb]);
                } else {
                    bfr[ntl][0] = __float_as_uint(kbi ? qb[ntl].z : qb[ntl].x);
                    bfr[ntl][1] = __float_as_uint(kbi ? qb[ntl].w : qb[ntl].y);
                }
            }
#pragma unroll
            for (int mt = 0; mt < 4; ++mt)
#pragma unroll
                for (int ntl = 0; ntl < 4; ++ntl)
                    mma_tf32(acc[mt][ntl], afr[mt], bfr[ntl]);
        }
    }

    if (Epi::STAGED) {
        float* stage = smg;   // 64 x 132 floats <= GT_SMEM
        __syncthreads();
#pragma unroll
        for (int half = 0; half < 2; ++half) {
            if (((warp & 3) >> 1) == half) {
                int wns = wn - half*64;
#pragma unroll
                for (int mt = 0; mt < 4; ++mt)
#pragma unroll
                    for (int ntl = 0; ntl < 4; ++ntl) {
                        int nl = wns + ntl*8 + 2*tig;
                        int mm = wm + mt*16 + gid;
                        stage[(nl    )*132 + mm    ] = acc[mt][ntl][0];
                        stage[(nl + 1)*132 + mm    ] = acc[mt][ntl][1];
                        stage[(nl    )*132 + mm + 8] = acc[mt][ntl][2];
                        stage[(nl + 1)*132 + mm + 8] = acc[mt][ntl][3];
                    }
            }
            __syncthreads();
#pragma unroll
            for (int rr = 0; rr < 8; ++rr) {
                int nl = warp*8 + rr;
                float4 v = *reinterpret_cast<float4*>(stage + nl*132 + (lane << 2));
                epi.store_row(bz, n0 + half*64 + nl, m0 + (lane << 2), v);
            }
            __syncthreads();
        }
    } else {
#pragma unroll
        for (int mt = 0; mt < 4; ++mt) {
            int mb = m0 + wm + mt*16;
#pragma unroll
            for (int ntl = 0; ntl < 4; ++ntl) {
                int nb = n0 + wn + ntl*8;
                epi(bz, mb + gid,     nb + 2*tig,     acc[mt][ntl][0]);
                epi(bz, mb + gid,     nb + 2*tig + 1, acc[mt][ntl][1]);
                epi(bz, mb + gid + 8, nb + 2*tig,     acc[mt][ntl][2]);
                epi(bz, mb + gid + 8, nb + 2*tig + 1, acc[mt][ntl][3]);
            }
        }
    }
}

// ================= conv3x3 as TF32 implicit GEMM, 64 out-ch per block =================
#define C3_SMEM ((2*72*68 + 2*24*68)*4)
__global__ __launch_bounds__(256)
void conv3_tc(const float* __restrict__ xr, const float* __restrict__ Wt,
              const float* __restrict__ bias, float* __restrict__ y2)
{
    extern __shared__ float sm[];
    float* Asm = sm;                       // 2 bufs x 72 x 68
    float* Ism = sm + 2*72*68;             // 2 bufs x 24 x 68

    const int b  = blockIdx.z;
    const int oh = blockIdx.y;
    const int h  = blockIdx.x;
    const int tid = threadIdx.x;
    const int warp = tid >> 5;
    const int lane = tid & 31;
    const int gid  = lane >> 2;
    const int tig  = lane & 3;
    const int wm   = (warp >> 1) * 16;
    const int wn   = (warp & 1) * 32;

    float acc[4][4];
#pragma unroll
    for (int j = 0; j < 4; j++)
#pragma unroll
        for (int q = 0; q < 4; q++) acc[j][q] = 0.f;

    const float* xrb = xr + (size_t)b * DM * LSEQ;

    auto ld_chunk = [&](int buf, int c0) {
        float* Ab = Asm + buf*72*68;
#pragma unroll
        for (int i = 0; i < 5; ++i) {
            int e = i*256 + tid;
            if (e < 1152) {
                int k  = e >> 4;
                int m4 = (e & 15) << 2;
                cp16((uint32_t)__cvta_generic_to_shared(Ab + k*68 + m4),
                     Wt + (size_t)(c0*9 + k)*128 + oh*64 + m4);
            }
        }
        float* Ib = Ism + buf*24*68;
#pragma unroll
        for (int i = 0; i < 2; ++i) {
            int e = i*256 + tid;
            if (e < 384) {
                int row = e >> 4;
                int di  = row % 3;
                int ci  = row / 3;
                int x4  = (e & 15) << 2;
                int hh  = h + di - 1;
                int ok  = (hh >= 0 && hh < 64) ? 16 : 0;
                int hc  = ok ? hh : 0;
                cp16z((uint32_t)__cvta_generic_to_shared(Ib + row*68 + x4),
                      xrb + (size_t)(c0 + ci)*LSEQ + hc*64 + x4, ok);
            }
        }
        cp_commit();
    };

    ld_chunk(0, 0);

    for (int c = 0; c < 32; ++c) {
        cp_wait_dyn(0);
        __syncthreads();
        if (c + 1 < 32) ld_chunk((c + 1) & 1, (c + 1) * 8);

        const float* Ab = Asm + (c & 1)*72*68;
        const float* Ib = Ism + (c & 1)*24*68;

#pragma unroll
        for (int kk = 0; kk < 9; ++kk) {
            const int kb = kk * 8;
            uint32_t afr[4], bfr[4][2];
            {
                int mb = wm + gid;
                afr[0] = __float_as_uint(Ab[(kb + tig    )*68 + mb]);
                afr[1] = __float_as_uint(Ab[(kb + tig    )*68 + mb + 8]);
                afr[2] = __float_as_uint(Ab[(kb + tig + 4)*68 + mb]);
                afr[3] = __float_as_uint(Ab[(kb + tig + 4)*68 + mb + 8]);
            }
            int k0 = kb + tig, k1 = kb + tig + 4;
            int ci0 = k0 / 9, t0 = k0 - ci0*9, di0 = t0 / 3, dj0 = t0 - di0*3;
            int ci1 = k1 / 9, t1 = k1 - ci1*9, di1 = t1 / 3, dj1 = t1 - di1*3;
            const float* r0 = Ib + (ci0*3 + di0)*68;
            const float* r1 = Ib + (ci1*3 + di1)*68;
#pragma unroll
            for (int ntl = 0; ntl < 4; ++ntl) {
                int w = wn + ntl*8 + gid;
                int x0 = w + dj0 - 1;
                int x1 = w + dj1 - 1;
                float v0 = (x0 >= 0 && x0 < 64) ? r0[x0] : 0.f;
                float v1 = (x1 >= 0 && x1 < 64) ? r1[x1] : 0.f;
                bfr[ntl][0] = f2tf(v0);
                bfr[ntl][1] = f2tf(v1);
            }
#pragma unroll
            for (int ntl = 0; ntl < 4; ++ntl)
                mma_tf32(acc[ntl], afr, bfr[ntl]);
        }
        __syncthreads();
    }

    {
        float* stage = Asm;
#pragma unroll
        for (int ntl = 0; ntl < 4; ++ntl) {
            int w = wn + ntl*8 + 2*tig;
            int o = wm + gid;
            stage[(o    )*68 + w    ] = acc[ntl][0];
            stage[(o    )*68 + w + 1] = acc[ntl][1];
            stage[(o + 8)*68 + w    ] = acc[ntl][2];
            stage[(o + 8)*68 + w + 1] = acc[ntl][3];
        }
        __syncthreads();
#pragma unroll
        for (int rr = 0; rr < 8; ++rr) {
            int o = warp*8 + rr;
            float2 v = *reinterpret_cast<float2*>(stage + o*68 + (lane << 1));
            float bv = bias[oh*64 + o];
            float2 w2 = make_float2(v.x + bv, v.y + bv);
            *reinterpret_cast<float2*>(
                y2 + ((size_t)b*128 + oh*64 + o)*LSEQ + h*64 + (lane << 1)) = w2;
        }
    }
}

// ---------------- merged prep ----------------
__device__ __forceinline__ void transp_tile(const float* __restrict__ in, float* __restrict__ out,
                                            int R, int C, int Rp, int bx, int by)
{
    __shared__ float t[32][33];
    int r0 = by * 32, c0 = bx * 32;
    int x = threadIdx.x & 31, y = (threadIdx.x >> 5);
    for (int i = y; i < 32; i += 8) {
        int r = r0 + i, c = c0 + x;
        t[i][x] = (r < R && c < C) ? round_tf(in[(size_t)r*C + c]) : 0.f;
    }
    __syncthreads();
    for (int i = y; i < 32; i += 8) {
        int c = c0 + i, r = r0 + x;
        if (c < C && r < Rp) out[(size_t)c*Rp + r] = t[x][i];
    }
}

__global__ __launch_bounds__(256)
void prep_kernel(const float* __restrict__ in_proj, const float* __restrict__ outw,
                 const float* __restrict__ xproj,   const float* __restrict__ cw,
                 const float* __restrict__ up_w,    const float* __restrict__ skip,
                 float* __restrict__ wp1, float* __restrict__ wp2,
                 float* __restrict__ wp3, float* __restrict__ wt4,
                 float* __restrict__ upp, float* __restrict__ xc)
{
    int bid = blockIdx.x;
    int tid = threadIdx.x;
    if (bid < 288) {                 // wt4: cw (128x2304) -> (2304,128)
        transp_tile(cw, wt4, 128, 2304, 128, bid % 72, bid / 72);
    } else if (bid < 1312) {         // wp1: [16][1024][16]
        int idx = (bid - 288) * 256 + tid;
        int p = idx & 15, n = (idx >> 4) & 1023, kt = idx >> 14;
        int k = kt*16 + (p & 3)*4 + (p >> 2);
        wp1[idx] = round_tf(in_proj[(size_t)n*256 + k]);
    } else if (bid < 1824) {         // wp2: [32][256][16]
        int idx = (bid - 1312) * 256 + tid;
        int p = idx & 15, n = (idx >> 4) & 255, kt = idx >> 12;
        int k = kt*16 + (p & 3)*4 + (p >> 2);
        wp2[idx] = round_tf(outw[(size_t)n*512 + k]);
    } else if (bid < 2080) {         // wp3: [32][128][16], zero pad n>=48
        int idx = (bid - 1824) * 256 + tid;
        int p = idx & 15, n = (idx >> 4) & 127, kt = idx >> 11;
        int k = kt*16 + (p & 3)*4 + (p >> 2);
        wp3[idx] = (n < 48) ? round_tf(xproj[(size_t)n*512 + k]) : 0.f;
    } else if (bid < 2592) {         // upp: [16][512][16]
        int idx = (bid - 2080) * 256 + tid;
        int p = idx & 15, m = (idx >> 4) & 511, kt = idx >> 13;
        int k = kt*16 + (p & 3)*4 + (p >> 2);
        upp[idx] = round_tf(up_w[(size_t)k*512 + m]);
    } else {                         // skip copy (float4)
        int idx = (bid - 2592) * 256 + tid;
        const float4* s4 = reinterpret_cast<const float4*>(skip);
        float4* x4 = reinterpret_cast<float4*>(xc);
        int b = idx >> 17;
        int rem = idx & 131071;
        x4[(size_t)(b*256 + 128)*1024 + rem] = s4[(size_t)b*131072 + rem];
    }
}

// ---------------- epilogues ----------------
struct EpiUp {
    static const bool STAGED = false;
    float* xc; const float* up_b;
    __device__ void operator()(int b, int m, int n, float v) const {
        int o = m >> 2, i = (m >> 1) & 1, j = m & 1;
        int h = n >> 5, w = n & 31;
        xc[((size_t)b*DM + o)*LSEQ + (2*h + i)*64 + (2*w + j)] = v + up_b[o];
    }
    __device__ void store_row(int, int, int, float4) const {}
};
struct EpiXZ {
    static const bool STAGED = true;
    float* xi; float* z;
    __device__ void operator()(int, int, int, float) const {}
    __device__ void store_row(int b, int n, int m, float4 v) const {
        float* p = (n < DI) ? xi + ((size_t)b*DI + n)*LSEQ + m
                            : z  + ((size_t)b*DI + (n - DI))*LSEQ + m;
        *reinterpret_cast<float4*>(p) = v;
    }
};
struct EpiDbc {
    static const bool STAGED = true;
    float* dbc;
    __device__ void operator()(int, int, int, float) const {}
    __device__ void store_row(int b, int n, int m, float4 v) const {
        if (n < 48)
            *reinterpret_cast<float4*>(dbc + (size_t)n*(NB*LSEQ) + b*LSEQ + m) = v;
    }
};
struct EpiOut {
    static const bool STAGED = true;
    const float* xc; float* xr;
    __device__ void operator()(int, int, int, float) const {}
    __device__ void store_row(int b, int n, int m, float4 v) const {
        size_t idx = ((size_t)b*DM + n)*LSEQ + m;
        float4 c = *reinterpret_cast<const float4*>(xc + idx);
        v.x += c.x; v.y += c.y; v.z += c.z; v.w += c.w;
        *reinterpret_cast<float4*>(xr + idx) = v;
    }
};

// ---------------- depthwise causal conv1d + silu ----------------
__global__ __launch_bounds__(256)
void conv1d_kernel(const float* __restrict__ xi, const float* __restrict__ w,
                   const float* __restrict__ bias, float* __restrict__ u)
{
    __shared__ float s[32][132];
    __shared__ float sw[32][4];
    __shared__ float sb[32];
    int b  = blockIdx.z;
    int d0 = blockIdx.y * 32;
    int l0 = blockIdx.x * 128;
    int tid = threadIdx.x;
    for (int e = tid; e < 32*132; e += 256) {
        int dd = e / 132, li = e - dd*132;
        if (li < 131) {
            int l = l0 - 3 + li;
            s[dd][li] = (l >= 0 && l < LSEQ) ? xi[((size_t)b*DI + d0 + dd)*LSEQ + l] : 0.f;
        }
    }
    if (tid < 128) sw[tid >> 2][tid & 3] = w[(d0 + (tid >> 2))*4 + (tid & 3)];
    if (tid < 32)  sb[tid] = bias[d0 + tid];
    __syncthreads();
#pragma unroll
    for (int it = 0; it < 16; ++it) {
        int idx = it*256 + tid;
        int dd = idx >> 7, li = idx & 127;
        float a = s[dd][li]*sw[dd][0] + s[dd][li+1]*sw[dd][1]
                + s[dd][li+2]*sw[dd][2] + s[dd][li+3]*sw[dd][3] + sb[dd];
        float sv = a / (1.f + __expf(-a));
        u[((size_t)b*DI + d0 + dd)*LSEQ + l0 + li] = sv;
    }
}

// ---------------- dt = softplus(dbc[:,:16] @ dtw^T + dtb), out (b,d,l) ----------------
__global__ __launch_bounds__(256)
void dt_kernel(const float* __restrict__ dbc, const float* __restrict__ dtw,
               const float* __restrict__ dtb, float* __restrict__ dt)
{
    __shared__ float swt[DI*16];
    __shared__ float sbc[16*64];
    __shared__ float sbias[DI];
    int bl0 = blockIdx.x * 64;
    int tid = threadIdx.x;
    for (int i = tid; i < DI*16; i += 256) swt[i] = dtw[i];
    for (int i = tid; i < DI; i += 256) sbias[i] = dtb[i];
    for (int i = tid; i < 16*64; i += 256) {
        int r = i >> 6, li = i & 63;
        sbc[i] = dbc[(size_t)r*(NB*LSEQ) + bl0 + li];
    }
    __syncthreads();
    int b  = bl0 >> 12;
    int l0 = bl0 & (LSEQ - 1);
#pragma unroll 4
    for (int it = 0; it < 128; ++it) {
        int idx = it*256 + tid;
        int d = idx >> 6, li = idx & 63;
        float acc = sbias[d];
#pragma unroll
        for (int r = 0; r < 16; ++r) acc += swt[d*16 + r] * sbc[r*64 + li];
        float sp = (acc > 20.f) ? acc : log1pf(__expf(acc));
        dt[((size_t)b*DI + d)*LSEQ + l0 + li] = sp;
    }
}

// ================= chunked selective scan =================
__global__ __launch_bounds__(128)
void scan_pass1(const float* __restrict__ dt, const float* __restrict__ u,
                const float* __restrict__ dbc, const float* __restrict__ A_log,
                float* __restrict__ S, float* __restrict__ sd)
{
    int lane = threadIdx.x & 31;
    int n    = lane & 15;
    int half = lane >> 4;
    int warp = threadIdx.x >> 5;
    int gch  = blockIdx.y * 8 + warp * 2 + half;
    int c    = blockIdx.x;
    int b = gch >> 9, d = gch & (DI - 1);

    float A = -__expf(A_log[d*DS + n]);
    const float* dtp = dt  + (size_t)gch*LSEQ + c*CT;
    const float* up  = u   + (size_t)gch*LSEQ + c*CT;
    const float* bp  = dbc + (size_t)(16 + n)*(NB*LSEQ) + b*LSEQ + c*CT;

    float h = 0.f, sda = 0.f;
#pragma unroll 8
    for (int l = 0; l < CT; ++l) {
        float dtv = dtp[l], uv = up[l], bn = bp[l];
        float dA = __expf(dtv * A);
        h = dA * h + (dtv * uv) * bn;
        sda += dtv;
    }
    S[((size_t)gch*NCH + c)*DS + n] = h;
    if (n == 0) sd[(size_t)gch*NCH + c] = sda;
}

__global__ __launch_bounds__(128)
void scan_pass2(const float* __restrict__ S, const float* __restrict__ sd,
                const float* __restrict__ A_log, float* __restrict__ hs)
{
    int lane = threadIdx.x & 31;
    int n    = lane & 15;
    int half = lane >> 4;
    int warp = threadIdx.x >> 5;
    int gch  = blockIdx.x * 8 + warp * 2 + half;
    int d = gch & (DI - 1);
    float A = -__expf(A_log[d*DS + n]);
    float h = 0.f;
    for (int c = 0; c < NCH; ++c) {
        size_t idx = ((size_t)gch*NCH + c)*DS + n;
        hs[idx] = h;
        float P = __expf(A * sd[(size_t)gch*NCH + c]);
        h = P * h + S[idx];
    }
}

__global__ __launch_bounds__(128)
void scan_pass3(const float* __restrict__ dt, const float* __restrict__ u,
                const float* __restrict__ dbc, const float* __restrict__ z,
                const float* __restrict__ A_log, const float* __restrict__ Dp,
                const float* __restrict__ hs, float* __restrict__ y)
{
    int lane = threadIdx.x & 31;
    int n    = lane & 15;
    int half = lane >> 4;
    int warp = threadIdx.x >> 5;
    int gch  = blockIdx.y * 8 + warp * 2 + half;
    int c    = blockIdx.x;
    int b = gch >> 9, d = gch & (DI - 1);

    float A  = -__expf(A_log[d*DS + n]);
    float Dv = Dp[d];
    const float* dtp = dt  + (size_t)gch*LSEQ + c*CT;
    const float* up  = u   + (size_t)gch*LSEQ + c*CT;
    const float* zp  = z   + (size_t)gch*LSEQ + c*CT;
    const float* bp  = dbc + (size_t)(16 + n)*(NB*LSEQ) + b*LSEQ + c*CT;
    const float* cp  = dbc + (size_t)(32 + n)*(NB*LSEQ) + b*LSEQ + c*CT;
    float*       yp  = y   + (size_t)gch*LSEQ + c*CT;

    float h = hs[((size_t)gch*NCH + c)*DS + n];
#pragma unroll 4
    for (int l = 0; l < CT; ++l) {
        float dtv = dtp[l], uv = up[l];
        float bn = bp[l], cn = cp[l];
        float dA = __expf(dtv * A);
        h = dA * h + (dtv * uv) * bn;
        float yv = h * cn;
        yv += __shfl_xor_sync(0xffffffffu, yv, 1);
        yv += __shfl_xor_sync(0xffffffffu, yv, 2);
        yv += __shfl_xor_sync(0xffffffffu, yv, 4);
        yv += __shfl_xor_sync(0xffffffffu, yv, 8);
        if (n == 0) {
            float out = yv + uv * Dv;
            float zv = zp[l];
            float sg = zv / (1.f + __expf(-zv));
            yp[l] = out * sg;
        }
    }
}

// ---------------- fused batchnorm (stats + apply + gelu), one channel per block ----------------
__global__ __launch_bounds__(256)
void bn_fused(const float* __restrict__ y2, const float* __restrict__ gamma,
              const float* __restrict__ beta, float* __restrict__ out)
{
    __shared__ float sy[8192];          // full channel slice (2 batches x 4096)
    __shared__ float red[18];
    int o = blockIdx.x, tid = threadIdx.x;
    float s = 0.f, s2 = 0.f;
#pragma unroll
    for (int i = 0; i < 8; ++i) {
        int e = i*256 + tid;            // float4 index 0..2047
        int b = e >> 10, l4 = e & 1023;
        float4 v = *reinterpret_cast<const float4*>(y2 + ((size_t)b*128 + o)*LSEQ + l4*4);
        *reinterpret_cast<float4*>(sy + e*4) = v;
        s  += v.x + v.y + v.z + v.w;
        s2 += v.x*v.x + v.y*v.y + v.z*v.z + v.w*v.w;
    }
#pragma unroll
    for (int st = 16; st > 0; st >>= 1) {
        s  += __shfl_xor_sync(0xffffffffu, s,  st);
        s2 += __shfl_xor_sync(0xffffffffu, s2, st);
    }
    if ((tid & 31) == 0) { red[tid >> 5] = s; red[8 + (tid >> 5)] = s2; }
    __syncthreads();
    if (tid == 0) {
        float a = 0.f, b2 = 0.f;
#pragma unroll
        for (int i = 0; i < 8; ++i) { a += red[i]; b2 += red[8 + i]; }
        red[16] = a; red[17] = b2;
    }
    __syncthreads();
    float mu  = red[16] * (1.f/8192.f);
    float var = red[17] * (1.f/8192.f) - mu*mu;
    float sc  = rsqrtf(var + 1e-5f) * gamma[o];
    float bt  = beta[o];
#pragma unroll
    for (int i = 0; i < 8; ++i) {
        int e = i*256 + tid;
        int b = e >> 10, l4 = e & 1023;
        float4 v = *reinterpret_cast<float4*>(sy + e*4);
        float4 r;
        r.x = (v.x - mu)*sc + bt; r.y = (v.y - mu)*sc + bt;
        r.z = (v.z - mu)*sc + bt; r.w = (v.w - mu)*sc + bt;
        r.x = 0.5f*r.x*(1.f + erff(r.x*0.70710678118654752440f));
        r.y = 0.5f*r.y*(1.f + erff(r.y*0.70710678118654752440f));
        r.z = 0.5f*r.z*(1.f + erff(r.z*0.70710678118654752440f));
        r.w = 0.5f*r.w*(1.f + erff(r.w*0.70710678118654752440f));
        *reinterpret_cast<float4*>(out + ((size_t)b*128 + o)*LSEQ + l4*4) = r;
    }
}

// ---------------- launch ----------------
extern "C" void kernel_launch(void* const* d_in, const int* in_sizes, int n_in,
                              void* d_out, int out_size)
{
    const float* x        = (const float*)d_in[0];
    const float* skip     = (const float*)d_in[1];
    const float* up_w     = (const float*)d_in[2];
    const float* up_b     = (const float*)d_in[3];
    const float* in_proj  = (const float*)d_in[4];
    const float* c1w      = (const float*)d_in[5];
    const float* c1b      = (const float*)d_in[6];
    const float* xproj    = (const float*)d_in[7];
    const float* dtw      = (const float*)d_in[8];
    const float* dtb      = (const float*)d_in[9];
    const float* A_log    = (const float*)d_in[10];
    const float* Dp       = (const float*)d_in[11];
    const float* outw     = (const float*)d_in[12];
    const float* cw       = (const float*)d_in[13];
    const float* cb       = (const float*)d_in[14];
    const float* bng      = (const float*)d_in[15];
    const float* bnb      = (const float*)d_in[16];
    float* out = (float*)d_out;

    float *xc, *xi, *z, *u, *dbc, *dtv, *y, *xr, *y2, *S, *hs, *sd;
    float *wp1, *wp2, *wp3, *wt4, *upp;
    cudaGetSymbolAddress((void**)&xc,  g_xc);
    cudaGetSymbolAddress((void**)&xi,  g_xi);
    cudaGetSymbolAddress((void**)&z,   g_z);
    cudaGetSymbolAddress((void**)&u,   g_u);
    cudaGetSymbolAddress((void**)&dbc, g_dbc);
    cudaGetSymbolAddress((void**)&dtv, g_dt);
    cudaGetSymbolAddress((void**)&y,   g_y);
    cudaGetSymbolAddress((void**)&xr,  g_xr);
    cudaGetSymbolAddress((void**)&y2,  g_y2);
    cudaGetSymbolAddress((void**)&S,   g_S);
    cudaGetSymbolAddress((void**)&hs,  g_hs);
    cudaGetSymbolAddress((void**)&sd,  g_sd);
    cudaGetSymbolAddress((void**)&wp1, g_wp1);
    cudaGetSymbolAddress((void**)&wp2, g_wp2);
    cudaGetSymbolAddress((void**)&wp3, g_wp3);
    cudaGetSymbolAddress((void**)&wt4, g_wt4);
    cudaGetSymbolAddress((void**)&upp, g_upp);

    cudaFuncSetAttribute(conv3_tc, cudaFuncAttributeMaxDynamicSharedMemorySize, C3_SMEM);
    cudaFuncSetAttribute(gemm128_tc<false, true,  EpiUp >, cudaFuncAttributeMaxDynamicSharedMemorySize, GT_SMEM);
    cudaFuncSetAttribute(gemm128_tc<true,  false, EpiXZ >, cudaFuncAttributeMaxDynamicSharedMemorySize, GT_SMEM);
    cudaFuncSetAttribute(gemm128_tc<true,  false, EpiDbc>, cudaFuncAttributeMaxDynamicSharedMemorySize, GT_SMEM);
    cudaFuncSetAttribute(gemm128_tc<true,  false, EpiOut>, cudaFuncAttributeMaxDynamicSharedMemorySize, GT_SMEM);

    // 0) merged prep: packed weight builds + conv weight transpose + skip copy
    prep_kernel<<<3616, 256>>>(in_proj, outw, xproj, cw, up_w, skip,
                               wp1, wp2, wp3, wt4, upp, xc);

    // 1) upsample GEMM: A = packed up_w (LDS.128), B = x (cvt)
    gemm128_tc<false, true, EpiUp><<<dim3(8, 4, NB), 256, GT_SMEM>>>(
        upp, 512, 0, x, 1024, (long)256*1024, 512, 1024, 256, EpiUp{xc, up_b});

    // 2) in_proj GEMM: A = xc (cvt), B = packed wp1
    gemm128_tc<true, false, EpiXZ><<<dim3(8, 32, NB), 256, GT_SMEM>>>(
        xc, LSEQ, (long)DM*LSEQ, wp1, 1024, 0, LSEQ, 2*DI, DM, EpiXZ{xi, z});

    // 3) depthwise conv1d + silu
    conv1d_kernel<<<dim3(LSEQ/128, DI/32, NB), 256>>>(xi, c1w, c1b, u);

    // 4) x_proj GEMM: A = u (cvt), B = packed wp3 (N padded 48->128)
    gemm128_tc<true, false, EpiDbc><<<dim3(1, 32, NB), 256, GT_SMEM>>>(
        u, LSEQ, (long)DI*LSEQ, wp3, 128, 0, LSEQ, 128, DI, EpiDbc{dbc});

    // 5) dt = softplus(dbc[:16]^T @ dtw^T + dtb)
    dt_kernel<<<NB*LSEQ/64, 256>>>(dbc, dtw, dtb, dtv);

    // 6) chunked selective scan
    scan_pass1<<<dim3(NCH, NB*DI/8), 128>>>(dtv, u, dbc, A_log, S, sd);
    scan_pass2<<<NB*DI/8, 128>>>(S, sd, A_log, hs);
    scan_pass3<<<dim3(NCH, NB*DI/8), 128>>>(dtv, u, dbc, z, A_log, Dp, hs, y);

    // 7) out_proj GEMM + residual: A = y (cvt), B = packed wp2
    gemm128_tc<true, false, EpiOut><<<dim3(2, 32, NB), 256, GT_SMEM>>>(
        y, LSEQ, (long)DI*LSEQ, wp2, 256, 0, LSEQ, DM, DI, EpiOut{xc, xr});

    // 8) 3x3 conv as TF32 implicit GEMM (256 blocks)
    conv3_tc<<<dim3(64, 2, NB), 256, C3_SMEM>>>(xr, wt4, cb, y2);

    // 9) fused batchnorm + gelu
    bn_fused<<<128, 256>>>(y2, bng, bnb, out);
}

// round 16
// speedup vs baseline: 1.5148x; 1.0493x over previous
#include <cuda_runtime.h>
#include <cuda_fp16.h>
#include <math.h>
#include <stdint.h>

#define LSEQ 4096
#define DM   256
#define DI   512
#define DS   16
#define NB   2
#define NCH  64   // scan chunks
#define CT   64   // chunk length

// ---------------- scratch (device globals; no runtime alloc allowed) ----------------
__device__ __align__(16) float g_xc [NB*DM*LSEQ];    // (b, c=256, l)
__device__ __align__(16) float g_xi [NB*DI*LSEQ];    // (b, d, l)
__device__ __align__(16) float g_z  [NB*DI*LSEQ];    // (b, d, l)
__device__ __align__(16) float g_u  [NB*DI*LSEQ];    // (b, d, l)
__device__ __align__(16) float g_dbc[48*NB*LSEQ];    // (j=48, b*l)
__device__ __align__(16) float g_dt [NB*DI*LSEQ];    // (b, d, l)
__device__ __align__(16) float g_y  [NB*DI*LSEQ];    // (b, d, l)
__device__ __align__(16) float g_xr [NB*DM*LSEQ];    // (b, c, l)
__device__ __align__(16) float g_y2 [NB*128*LSEQ];   // (b, o, l)
__device__ __align__(16) float g_S  [NB*DI*NCH*DS];
__device__ __align__(16) float g_hs [NB*DI*NCH*DS];
__device__ __align__(16) float g_sd [NB*DI*NCH];
// fp16 packed weights: [K/16][rows][16] with k-perm (r -> k = 2g + (r>>1)*8 + (r&1), g=p>>2)
__device__ __align__(16) __half g_wp1h[16*1024*16];  // in_proj_w  (K=256, N=1024)
__device__ __align__(16) __half g_wp2h[32*256*16];   // out_proj_w (K=512, N=256)
__device__ __align__(16) __half g_wp3h[32*128*16];   // x_proj_w   (K=512, N=128 pad)
__device__ __align__(16) __half g_upph[16*512*16];   // up_w as A  (K=256, M=512)
__device__ __align__(16) float  g_wt4[2304*128];     // conv_w^T (k=c*9+t, o=128), tf32-rounded

// ---------------- cp.async helpers ----------------
__device__ __forceinline__ void cp16(uint32_t dst, const void* src) {
    asm volatile("cp.async.cg.shared.global [%0], [%1], 16;\n" :: "r"(dst), "l"(src));
}
__device__ __forceinline__ void cp16z(uint32_t dst, const void* src, int sz) {
    asm volatile("cp.async.cg.shared.global [%0], [%1], 16, %2;\n" :: "r"(dst), "l"(src), "r"(sz));
}
__device__ __forceinline__ void cp_commit() {
    asm volatile("cp.async.commit_group;\n");
}
__device__ __forceinline__ void cp_wait_dyn(int allow) {
    if (allow <= 0)      asm volatile("cp.async.wait_group 0;\n");
    else                 asm volatile("cp.async.wait_group 1;\n");
}

// ---------------- numeric helpers ----------------
__device__ __forceinline__ uint32_t f2tf(float f) {
    uint32_t r;
    asm("cvt.rna.tf32.f32 %0, %1;" : "=r"(r) : "f"(f));
    return r;
}
__device__ __forceinline__ float round_tf(float f) {
    return __uint_as_float(f2tf(f));
}
__device__ __forceinline__ uint32_t packh2(float x, float y) {
    __half2 h = __floats2half2_rn(x, y);
    return *reinterpret_cast<uint32_t*>(&h);
}
__device__ __forceinline__ void mma_tf32(float* c, const uint32_t* a, const uint32_t* b) {
    asm volatile(
        "mma.sync.aligned.m16n8k8.row.col.f32.tf32.tf32.f32 "
        "{%0,%1,%2,%3}, {%4,%5,%6,%7}, {%8,%9}, {%0,%1,%2,%3};"
        : "+f"(c[0]), "+f"(c[1]), "+f"(c[2]), "+f"(c[3])
        : "r"(a[0]), "r"(a[1]), "r"(a[2]), "r"(a[3]), "r"(b[0]), "r"(b[1]));
}
__device__ __forceinline__ void mma_f16(float* c, const uint32_t* a, uint32_t b0, uint32_t b1) {
    asm volatile(
        "mma.sync.aligned.m16n8k16.row.col.f32.f16.f16.f32 "
        "{%0,%1,%2,%3}, {%4,%5,%6,%7}, {%8,%9}, {%0,%1,%2,%3};"
        : "+f"(c[0]), "+f"(c[1]), "+f"(c[2]), "+f"(c[3])
        : "r"(a[0]), "r"(a[1]), "r"(a[2]), "r"(a[3]), "r"(b0), "r"(b1));
}

// ================= 128x128x16, 3-stage cp.async, FP16 tensor-core GEMM =================
// AW/BW: operand is a pre-packed fp16 weight [K/16][rows][16] (perm-k), fragments via LDS.64.
// Otherwise operand is an fp32 activation (k-major), fragments scalar + cvt.rn.f16x2.
// Exactly one of AW/BW is true per instantiation here.
#define GH_SMEM ((3*2112 + 3*1024)*4)   // act stages (16x132 f32) + weight stages (2048 half)
template<bool AW, bool BW, class Epi>
__global__ __launch_bounds__(256)
void gemm128h(const void* Aop, int lda, long sA,
              const void* Bop, int ldb, long sB,
              int M, int N, int K, Epi epi)
{
    extern __shared__ float smg[];
    constexpr int ASZ = AW ? 1024 : 2112;   // floats
    constexpr int BSZ = BW ? 1024 : 2112;
    float* Asm = smg;
    float* Bsm = smg + 3*ASZ;
    const int tid = threadIdx.x;
    const int bz  = blockIdx.z;
    const int m0 = blockIdx.y * 128;
    const int n0 = blockIdx.x * 128;

    const float*  Aact = AW ? nullptr : ((const float*)Aop + (size_t)bz * sA);
    const __half* Awt  = AW ? (const __half*)Aop : nullptr;
    const float*  Bact = BW ? nullptr : ((const float*)Bop + (size_t)bz * sB);
    const __half* Bwt  = BW ? (const __half*)Bop : nullptr;

    const int warp = tid >> 5;
    const int lane = tid & 31;
    const int gid  = lane >> 2;
    const int tig  = lane & 3;
    const int wm   = (warp >> 2) * 64;
    const int wn   = (warp & 3) * 32;

    float acc[4][4][4];
#pragma unroll
    for (int i = 0; i < 4; i++)
#pragma unroll
        for (int j = 0; j < 4; j++)
#pragma unroll
            for (int q = 0; q < 4; q++) acc[i][j][q] = 0.f;

    const int nt = K >> 4;

    auto ldtile = [&](int st, int k0) {
        if (AW) {
            // 2048 halves = 256 x 16B
            uint32_t dst = (uint32_t)__cvta_generic_to_shared((char*)(Asm + st*ASZ) + tid*16);
            cp16(dst, Awt + ((size_t)(k0 >> 4)*lda + m0)*16 + tid*8);
        } else {
#pragma unroll
            for (int i = 0; i < 2; ++i) {
                int e  = i*256 + tid;
                int kr = e >> 5, m4 = (e & 31) << 2;
                cp16((uint32_t)__cvta_generic_to_shared(Asm + st*ASZ + kr*132 + m4),
                     Aact + (size_t)(k0 + kr)*lda + m0 + m4);
            }
        }
        if (BW) {
            uint32_t dst = (uint32_t)__cvta_generic_to_shared((char*)(Bsm + st*BSZ) + tid*16);
            cp16(dst, Bwt + ((size_t)(k0 >> 4)*ldb + n0)*16 + tid*8);
        } else {
#pragma unroll
            for (int i = 0; i < 2; ++i) {
                int e  = i*256 + tid;
                int kr = e >> 5, m4 = (e & 31) << 2;
                cp16((uint32_t)__cvta_generic_to_shared(Bsm + st*BSZ + kr*132 + m4),
                     Bact + (size_t)(k0 + kr)*ldb + n0 + m4);
            }
        }
        cp_commit();
    };

    ldtile(0, 0);
    ldtile(1, 16);

    for (int kt = 0; kt < nt; ++kt) {
        cp_wait_dyn((kt + 1 < nt) ? 1 : 0);
        __syncthreads();
        if (kt + 2 < nt) ldtile((kt + 2) % 3, (kt + 2) << 4);

        const int st = kt % 3;
        uint32_t afr[4][4], bfr[4][2];

        if (AW) {
            const __half* Ah = (const __half*)(Asm + st*ASZ);
#pragma unroll
            for (int mt = 0; mt < 4; ++mt) {
                int r0 = wm + mt*16 + gid;
                uint2 w0 = *reinterpret_cast<const uint2*>(Ah + r0*16 + tig*4);
                uint2 w1 = *reinterpret_cast<const uint2*>(Ah + (r0 + 8)*16 + tig*4);
                afr[mt][0] = w0.x; afr[mt][1] = w1.x;
                afr[mt][2] = w0.y; afr[mt][3] = w1.y;
            }
        } else {
            const float* As = Asm + st*ASZ;
#pragma unroll
            for (int mt = 0; mt < 4; ++mt) {
                int mb = wm + mt*16 + gid;
                afr[mt][0] = packh2(As[(2*tig    )*132 + mb    ], As[(2*tig + 1)*132 + mb    ]);
                afr[mt][1] = packh2(As[(2*tig    )*132 + mb + 8], As[(2*tig + 1)*132 + mb + 8]);
                afr[mt][2] = packh2(As[(2*tig + 8)*132 + mb    ], As[(2*tig + 9)*132 + mb    ]);
                afr[mt][3] = packh2(As[(2*tig + 8)*132 + mb + 8], As[(2*tig + 9)*132 + mb + 8]);
            }
        }
        if (BW) {
            const __half* Bh = (const __half*)(Bsm + st*BSZ);
#pragma unroll
            for (int ntl = 0; ntl < 4; ++ntl) {
                int nb = wn + ntl*8 + gid;
                uint2 w = *reinterpret_cast<const uint2*>(Bh + nb*16 + tig*4);
                bfr[ntl][0] = w.x; bfr[ntl][1] = w.y;
            }
        } else {
            const float* Bs = Bsm + st*BSZ;
#pragma unroll
            for (int ntl = 0; ntl < 4; ++ntl) {
                int nb = wn + ntl*8 + gid;
                bfr[ntl][0] = packh2(Bs[(2*tig    )*132 + nb], Bs[(2*tig + 1)*132 + nb]);
                bfr[ntl][1] = packh2(Bs[(2*tig + 8)*132 + nb], Bs[(2*tig + 9)*132 + nb]);
            }
        }
#pragma unroll
        for (int mt = 0; mt < 4; ++mt)
#pragma unroll
            for (int ntl = 0; ntl < 4; ++ntl)
                mma_f16(acc[mt][ntl], afr[mt], bfr[ntl][0], bfr[ntl][1]);
    }

    if (Epi::STAGED) {
        float* stage = smg;   // 64 x 132 floats = 8448 <= 9408
        __syncthreads();
#pragma unroll
        for (int half = 0; half < 2; ++half) {
            if (((warp & 3) >> 1) == half) {
                int wns = wn - half*64;
#pragma unroll
                for (int mt = 0; mt < 4; ++mt)
#pragma unroll
                    for (int ntl = 0; ntl < 4; ++ntl) {
                        int nl = wns + ntl*8 + 2*tig;
                        int mm = wm + mt*16 + gid;
                        stage[(nl    )*132 + mm    ] = acc[mt][ntl][0];
                        stage[(nl + 1)*132 + mm    ] = acc[mt][ntl][1];
                        stage[(nl    )*132 + mm + 8] = acc[mt][ntl][2];
                        stage[(nl + 1)*132 + mm + 8] = acc[mt][ntl][3];
                    }
            }
            __syncthreads();
#pragma unroll
            for (int rr = 0; rr < 8; ++rr) {
                int nl = warp*8 + rr;
                float4 v = *reinterpret_cast<float4*>(stage + nl*132 + (lane << 2));
                epi.store_row(bz, n0 + half*64 + nl, m0 + (lane << 2), v);
            }
            __syncthreads();
        }
    } else {
#pragma unroll
        for (int mt = 0; mt < 4; ++mt) {
            int mb = m0 + wm + mt*16;
#pragma unroll
            for (int ntl = 0; ntl < 4; ++ntl) {
                int nb = n0 + wn + ntl*8;
                epi(bz, mb + gid,     nb + 2*tig,     acc[mt][ntl][0]);
                epi(bz, mb + gid,     nb + 2*tig + 1, acc[mt][ntl][1]);
                epi(bz, mb + gid + 8, nb + 2*tig,     acc[mt][ntl][2]);
                epi(bz, mb + gid + 8, nb + 2*tig + 1, acc[mt][ntl][3]);
            }
        }
    }
}

// ================= conv3x3 as TF32 implicit GEMM, 64 out-ch per block =================
#define C3_SMEM ((2*72*68 + 2*24*68)*4)
__global__ __launch_bounds__(256)
void conv3_tc(const float* __restrict__ xr, const float* __restrict__ Wt,
              const float* __restrict__ bias, float* __restrict__ y2)
{
    extern __shared__ float sm[];
    float* Asm = sm;                       // 2 bufs x 72 x 68
    float* Ism = sm + 2*72*68;             // 2 bufs x 24 x 68

    const int b  = blockIdx.z;
    const int oh = blockIdx.y;
    const int h  = blockIdx.x;
    const int tid = threadIdx.x;
    const int warp = tid >> 5;
    const int lane = tid & 31;
    const int gid  = lane >> 2;
    const int tig  = lane & 3;
    const int wm   = (warp >> 1) * 16;
    const int wn   = (warp & 1) * 32;

    float acc[4][4];
#pragma unroll
    for (int j = 0; j < 4; j++)
#pragma unroll
        for (int q = 0; q < 4; q++) acc[j][q] = 0.f;

    const float* xrb = xr + (size_t)b * DM * LSEQ;

    auto ld_chunk = [&](int buf, int c0) {
        float* Ab = Asm + buf*72*68;
#pragma unroll
        for (int i = 0; i < 5; ++i) {
            int e = i*256 + tid;
            if (e < 1152) {
                int k  = e >> 4;
                int m4 = (e & 15) << 2;
                cp16((uint32_t)__cvta_generic_to_shared(Ab + k*68 + m4),
                     Wt + (size_t)(c0*9 + k)*128 + oh*64 + m4);
            }
        }
        float* Ib = Ism + buf*24*68;
#pragma unroll
        for (int i = 0; i < 2; ++i) {
            int e = i*256 + tid;
            if (e < 384) {
                int row = e >> 4;
                int di  = row % 3;
                int ci  = row / 3;
                int x4  = (e & 15) << 2;
                int hh  = h + di - 1;
                int ok  = (hh >= 0 && hh < 64) ? 16 : 0;
                int hc  = ok ? hh : 0;
                cp16z((uint32_t)__cvta_generic_to_shared(Ib + row*68 + x4),
                      xrb + (size_t)(c0 + ci)*LSEQ + hc*64 + x4, ok);
            }
        }
        cp_commit();
    };

    ld_chunk(0, 0);

    for (int c = 0; c < 32; ++c) {
        cp_wait_dyn(0);
        __syncthreads();
        if (c + 1 < 32) ld_chunk((c + 1) & 1, (c + 1) * 8);

        const float* Ab = Asm + (c & 1)*72*68;
        const float* Ib = Ism + (c & 1)*24*68;

#pragma unroll
        for (int kk = 0; kk < 9; ++kk) {
            const int kb = kk * 8;
            uint32_t afr[4], bfr[4][2];
            {
                int mb = wm + gid;
                afr[0] = __float_as_uint(Ab[(kb + tig    )*68 + mb]);
                afr[1] = __float_as_uint(Ab[(kb + tig    )*68 + mb + 8]);
                afr[2] = __float_as_uint(Ab[(kb + tig + 4)*68 + mb]);
                afr[3] = __float_as_uint(Ab[(kb + tig + 4)*68 + mb + 8]);
            }
            int k0 = kb + tig, k1 = kb + tig + 4;
            int ci0 = k0 / 9, t0 = k0 - ci0*9, di0 = t0 / 3, dj0 = t0 - di0*3;
            int ci1 = k1 / 9, t1 = k1 - ci1*9, di1 = t1 / 3, dj1 = t1 - di1*3;
            const float* r0 = Ib + (ci0*3 + di0)*68;
            const float* r1 = Ib + (ci1*3 + di1)*68;
#pragma unroll
            for (int ntl = 0; ntl < 4; ++ntl) {
                int w = wn + ntl*8 + gid;
                int x0 = w + dj0 - 1;
                int x1 = w + dj1 - 1;
                float v0 = (x0 >= 0 && x0 < 64) ? r0[x0] : 0.f;
                float v1 = (x1 >= 0 && x1 < 64) ? r1[x1] : 0.f;
                bfr[ntl][0] = f2tf(v0);
                bfr[ntl][1] = f2tf(v1);
            }
#pragma unroll
            for (int ntl = 0; ntl < 4; ++ntl)
                mma_tf32(acc[ntl], afr, bfr[ntl]);
        }
        __syncthreads();
    }

    {
        float* stage = Asm;
#pragma unroll
        for (int ntl = 0; ntl < 4; ++ntl) {
            int w = wn + ntl*8 + 2*tig;
            int o = wm + gid;
            stage[(o    )*68 + w    ] = acc[ntl][0];
            stage[(o    )*68 + w + 1] = acc[ntl][1];
            stage[(o + 8)*68 + w    ] = acc[ntl][2];
            stage[(o + 8)*68 + w + 1] = acc[ntl][3];
        }
        __syncthreads();
#pragma unroll
        for (int rr = 0; rr < 8; ++rr) {
            int o = warp*8 + rr;
            float2 v = *reinterpret_cast<float2*>(stage + o*68 + (lane << 1));
            float bv = bias[oh*64 + o];
            float2 w2 = make_float2(v.x + bv, v.y + bv);
            *reinterpret_cast<float2*>(
                y2 + ((size_t)b*128 + oh*64 + o)*LSEQ + h*64 + (lane << 1)) = w2;
        }
    }
}

// ---------------- merged prep ----------------
__device__ __forceinline__ void transp_tile(const float* __restrict__ in, float* __restrict__ out,
                                            int R, int C, int Rp, int bx, int by)
{
    __shared__ float t[32][33];
    int r0 = by * 32, c0 = bx * 32;
    int x = threadIdx.x & 31, y = (threadIdx.x >> 5);
    for (int i = y; i < 32; i += 8) {
        int r = r0 + i, c = c0 + x;
        t[i][x] = (r < R && c < C) ? round_tf(in[(size_t)r*C + c]) : 0.f;
    }
    __syncthreads();
    for (int i = y; i < 32; i += 8) {
        int c = c0 + i, r = r0 + x;
        if (c < C && r < Rp) out[(size_t)c*Rp + r] = t[x][i];
    }
}

__device__ __forceinline__ int kperm(int p) {
    return 2*(p >> 2) + ((p >> 1) & 1)*8 + (p & 1);
}

__global__ __launch_bounds__(256)
void prep_kernel(const float* __restrict__ in_proj, const float* __restrict__ outw,
                 const float* __restrict__ xproj,   const float* __restrict__ cw,
                 const float* __restrict__ up_w,    const float* __restrict__ skip,
                 __half* __restrict__ wp1, __half* __restrict__ wp2,
                 __half* __restrict__ wp3, float* __restrict__ wt4,
                 __half* __restrict__ upp, float* __restrict__ xc)
{
    int bid = blockIdx.x;
    int tid = threadIdx.x;
    if (bid < 288) {                 // wt4: cw (128x2304) -> (2304,128)
        transp_tile(cw, wt4, 128, 2304, 128, bid % 72, bid / 72);
    } else if (bid < 1312) {         // wp1: [16][1024][16] halves
        int idx = (bid - 288) * 256 + tid;
        int p = idx & 15, n = (idx >> 4) & 1023, kt = idx >> 14;
        int k = kt*16 + kperm(p);
        wp1[idx] = __float2half_rn(in_proj[(size_t)n*256 + k]);
    } else if (bid < 1824) {         // wp2: [32][256][16]
        int idx = (bid - 1312) * 256 + tid;
        int p = idx & 15, n = (idx >> 4) & 255, kt = idx >> 12;
        int k = kt*16 + kperm(p);
        wp2[idx] = __float2half_rn(outw[(size_t)n*512 + k]);
    } else if (bid < 2080) {         // wp3: [32][128][16], zero pad n>=48
        int idx = (bid - 1824) * 256 + tid;
        int p = idx & 15, n = (idx >> 4) & 127, kt = idx >> 11;
        int k = kt*16 + kperm(p);
        wp3[idx] = (n < 48) ? __float2half_rn(xproj[(size_t)n*512 + k]) : __half(0.f);
    } else if (bid < 2592) {         // upp: [16][512][16]
        int idx = (bid - 2080) * 256 + tid;
        int p = idx & 15, m = (idx >> 4) & 511, kt = idx >> 13;
        int k = kt*16 + kperm(p);
        upp[idx] = __float2half_rn(up_w[(size_t)k*512 + m]);
    } else {                         // skip copy (float4)
        int idx = (bid - 2592) * 256 + tid;
        const float4* s4 = reinterpret_cast<const float4*>(skip);
        float4* x4 = reinterpret_cast<float4*>(xc);
        int b = idx >> 17;
        int rem = idx & 131071;
        x4[(size_t)(b*256 + 128)*1024 + rem] = s4[(size_t)b*131072 + rem];
    }
}

// ---------------- epilogues ----------------
struct EpiUp {
    static const bool STAGED = false;
    float* xc; const float* up_b;
    __device__ void operator()(int b, int m, int n, float v) const {
        int o = m >> 2, i = (m >> 1) & 1, j = m & 1;
        int h = n >> 5, w = n & 31;
        xc[((size_t)b*DM + o)*LSEQ + (2*h + i)*64 + (2*w + j)] = v + up_b[o];
    }
    __device__ void store_row(int, int, int, float4) const {}
};
struct EpiXZ {
    static const bool STAGED = true;
    float* xi; float* z;
    __device__ void operator()(int, int, int, float) const {}
    __device__ void store_row(int b, int n, int m, float4 v) const {
        float* p = (n < DI) ? xi + ((size_t)b*DI + n)*LSEQ + m
                            : z  + ((size_t)b*DI + (n - DI))*LSEQ + m;
        *reinterpret_cast<float4*>(p) = v;
    }
};
struct EpiDbc {
    static const bool STAGED = true;
    float* dbc;
    __device__ void operator()(int, int, int, float) const {}
    __device__ void store_row(int b, int n, int m, float4 v) const {
        if (n < 48)
            *reinterpret_cast<float4*>(dbc + (size_t)n*(NB*LSEQ) + b*LSEQ + m) = v;
    }
};
struct EpiOut {
    static const bool STAGED = true;
    const float* xc; float* xr;
    __device__ void operator()(int, int, int, float) const {}
    __device__ void store_row(int b, int n, int m, float4 v) const {
        size_t idx = ((size_t)b*DM + n)*LSEQ + m;
        float4 c = *reinterpret_cast<const float4*>(xc + idx);
        v.x += c.x; v.y += c.y; v.z += c.z; v.w += c.w;
        *reinterpret_cast<float4*>(xr + idx) = v;
    }
};

// ---------------- depthwise causal conv1d + silu ----------------
__global__ __launch_bounds__(256)
void conv1d_kernel(const float* __restrict__ xi, const float* __restrict__ w,
                   const float* __restrict__ bias, float* __restrict__ u)
{
    __shared__ float s[32][132];
    __shared__ float sw[32][4];
    __shared__ float sb[32];
    int b  = blockIdx.z;
    int d0 = blockIdx.y * 32;
    int l0 = blockIdx.x * 128;
    int tid = threadIdx.x;
    for (int e = tid; e < 32*132; e += 256) {
        int dd = e / 132, li = e - dd*132;
        if (li < 131) {
            int l = l0 - 3 + li;
            s[dd][li] = (l >= 0 && l < LSEQ) ? xi[((size_t)b*DI + d0 + dd)*LSEQ + l] : 0.f;
        }
    }
    if (tid < 128) sw[tid >> 2][tid & 3] = w[(d0 + (tid >> 2))*4 + (tid & 3)];
    if (tid < 32)  sb[tid] = bias[d0 + tid];
    __syncthreads();
#pragma unroll
    for (int it = 0; it < 16; ++it) {
        int idx = it*256 + tid;
        int dd = idx >> 7, li = idx & 127;
        float a = s[dd][li]*sw[dd][0] + s[dd][li+1]*sw[dd][1]
                + s[dd][li+2]*sw[dd][2] + s[dd][li+3]*sw[dd][3] + sb[dd];
        float sv = a / (1.f + __expf(-a));
        u[((size_t)b*DI + d0 + dd)*LSEQ + l0 + li] = sv;
    }
}

// ---------------- dt = softplus(dbc[:,:16] @ dtw^T + dtb), out (b,d,l) ----------------
__global__ __launch_bounds__(256)
void dt_kernel(const float* __restrict__ dbc, const float* __restrict__ dtw,
               const float* __restrict__ dtb, float* __restrict__ dt)
{
    __shared__ float swt[DI*16];
    __shared__ float sbc[16*64];
    __shared__ float sbias[DI];
    int bl0 = blockIdx.x * 64;
    int tid = threadIdx.x;
    for (int i = tid; i < DI*16; i += 256) swt[i] = dtw[i];
    for (int i = tid; i < DI; i += 256) sbias[i] = dtb[i];
    for (int i = tid; i < 16*64; i += 256) {
        int r = i >> 6, li = i & 63;
        sbc[i] = dbc[(size_t)r*(NB*LSEQ) + bl0 + li];
    }
    __syncthreads();
    int b  = bl0 >> 12;
    int l0 = bl0 & (LSEQ - 1);
#pragma unroll 4
    for (int it = 0; it < 128; ++it) {
        int idx = it*256 + tid;
        int d = idx >> 6, li = idx & 63;
        float acc = sbias[d];
#pragma unroll
        for (int r = 0; r < 16; ++r) acc += swt[d*16 + r] * sbc[r*64 + li];
        float sp = (acc > 20.f) ? acc : log1pf(__expf(acc));
        dt[((size_t)b*DI + d)*LSEQ + l0 + li] = sp;
    }
}

// ================= chunked selective scan =================
__global__ __launch_bounds__(128)
void scan_pass1(const float* __restrict__ dt, const float* __restrict__ u,
                const float* __restrict__ dbc, const float* __restrict__ A_log,
                float* __restrict__ S, float* __restrict__ sd)
{
    int lane = threadIdx.x & 31;
    int n    = lane & 15;
    int half = lane >> 4;
    int warp = threadIdx.x >> 5;
    int gch  = blockIdx.y * 8 + warp * 2 + half;
    int c    = blockIdx.x;
    int b = gch >> 9, d = gch & (DI - 1);

    float A = -__expf(A_log[d*DS + n]);
    const float* dtp = dt  + (size_t)gch*LSEQ + c*CT;
    const float* up  = u   + (size_t)gch*LSEQ + c*CT;
    const float* bp  = dbc + (size_t)(16 + n)*(NB*LSEQ) + b*LSEQ + c*CT;

    float h = 0.f, sda = 0.f;
#pragma unroll 8
    for (int l = 0; l < CT; ++l) {
        float dtv = dtp[l], uv = up[l], bn = bp[l];
        float dA = __expf(dtv * A);
        h = dA * h + (dtv * uv) * bn;
        sda += dtv;
    }
    S[((size_t)gch*NCH + c)*DS + n] = h;
    if (n == 0) sd[(size_t)gch*NCH + c] = sda;
}

__global__ __launch_bounds__(128)
void scan_pass2(const float* __restrict__ S, const float* __restrict__ sd,
                const float* __restrict__ A_log, float* __restrict__ hs)
{
    int lane = threadIdx.x & 31;
    int n    = lane & 15;
    int half = lane >> 4;
    int warp = threadIdx.x >> 5;
    int gch  = blockIdx.x * 8 + warp * 2 + half;
    int d = gch & (DI - 1);
    float A = -__expf(A_log[d*DS + n]);
    float h = 0.f;
    for (int c = 0; c < NCH; ++c) {
        size_t idx = ((size_t)gch*NCH + c)*DS + n;
        hs[idx] = h;
        float P = __expf(A * sd[(size_t)gch*NCH + c]);
        h = P * h + S[idx];
    }
}

__global__ __launch_bounds__(128)
void scan_pass3(const float* __restrict__ dt, const float* __restrict__ u,
                const float* __restrict__ dbc, const float* __restrict__ z,
                const float* __restrict__ A_log, const float* __restrict__ Dp,
                const float* __restrict__ hs, float* __restrict__ y)
{
    int lane = threadIdx.x & 31;
    int n    = lane & 15;
    int half = lane >> 4;
    int warp = threadIdx.x >> 5;
    int gch  = blockIdx.y * 8 + warp * 2 + half;
    int c    = blockIdx.x;
    int b = gch >> 9, d = gch & (DI - 1);

    float A  = -__expf(A_log[d*DS + n]);
    float Dv = Dp[d];
    const float* dtp = dt  + (size_t)gch*LSEQ + c*CT;
    const float* up  = u   + (size_t)gch*LSEQ + c*CT;
    const float* zp  = z   + (size_t)gch*LSEQ + c*CT;
    const float* bp  = dbc + (size_t)(16 + n)*(NB*LSEQ) + b*LSEQ + c*CT;
    const float* cp  = dbc + (size_t)(32 + n)*(NB*LSEQ) + b*LSEQ + c*CT;
    float*       yp  = y   + (size_t)gch*LSEQ + c*CT;

    float h = hs[((size_t)gch*NCH + c)*DS + n];
#pragma unroll 4
    for (int l = 0; l < CT; ++l) {
        float dtv = dtp[l], uv = up[l];
        float bn = bp[l], cn = cp[l];
        float dA = __expf(dtv * A);
        h = dA * h + (dtv * uv) * bn;
        float yv = h * cn;
        yv += __shfl_xor_sync(0xffffffffu, yv, 1);
        yv += __shfl_xor_sync(0xffffffffu, yv, 2);
        yv += __shfl_xor_sync(0xffffffffu, yv, 4);
        yv += __shfl_xor_sync(0xffffffffu, yv, 8);
        if (n == 0) {
            float out = yv + uv * Dv;
            float zv = zp[l];
            float sg = zv / (1.f + __expf(-zv));
            yp[l] = out * sg;
        }
    }
}

// ---------------- fused batchnorm (stats + apply + gelu), one channel per block ----------------
__global__ __launch_bounds__(256)
void bn_fused(const float* __restrict__ y2, const float* __restrict__ gamma,
              const float* __restrict__ beta, float* __restrict__ out)
{
    __shared__ float sy[8192];
    __shared__ float red[18];
    int o = blockIdx.x, tid = threadIdx.x;
    float s = 0.f, s2 = 0.f;
#pragma unroll
    for (int i = 0; i < 8; ++i) {
        int e = i*256 + tid;
        int b = e >> 10, l4 = e & 1023;
        float4 v = *reinterpret_cast<const float4*>(y2 + ((size_t)b*128 + o)*LSEQ + l4*4);
        *reinterpret_cast<float4*>(sy + e*4) = v;
        s  += v.x + v.y + v.z + v.w;
        s2 += v.x*v.x + v.y*v.y + v.z*v.z + v.w*v.w;
    }
#pragma unroll
    for (int st = 16; st > 0; st >>= 1) {
        s  += __shfl_xor_sync(0xffffffffu, s,  st);
        s2 += __shfl_xor_sync(0xffffffffu, s2, st);
    }
    if ((tid & 31) == 0) { red[tid >> 5] = s; red[8 + (tid >> 5)] = s2; }
    __syncthreads();
    if (tid == 0) {
        float a = 0.f, b2 = 0.f;
#pragma unroll
        for (int i = 0; i < 8; ++i) { a += red[i]; b2 += red[8 + i]; }
        red[16] = a; red[17] = b2;
    }
    __syncthreads();
    float mu  = red[16] * (1.f/8192.f);
    float var = red[17] * (1.f/8192.f) - mu*mu;
    float sc  = rsqrtf(var + 1e-5f) * gamma[o];
    float bt  = beta[o];
#pragma unroll
    for (int i = 0; i < 8; ++i) {
        int e = i*256 + tid;
        int b = e >> 10, l4 = e & 1023;
        float4 v = *reinterpret_cast<float4*>(sy + e*4);
        float4 r;
        r.x = (v.x - mu)*sc + bt; r.y = (v.y - mu)*sc + bt;
        r.z = (v.z - mu)*sc + bt; r.w = (v.w - mu)*sc + bt;
        r.x = 0.5f*r.x*(1.f + erff(r.x*0.70710678118654752440f));
        r.y = 0.5f*r.y*(1.f + erff(r.y*0.70710678118654752440f));
        r.z = 0.5f*r.z*(1.f + erff(r.z*0.70710678118654752440f));
        r.w = 0.5f*r.w*(1.f + erff(r.w*0.70710678118654752440f));
        *reinterpret_cast<float4*>(out + ((size_t)b*128 + o)*LSEQ + l4*4) = r;
    }
}

// ---------------- launch ----------------
extern "C" void kernel_launch(void* const* d_in, const int* in_sizes, int n_in,
                              void* d_out, int out_size)
{
    const float* x        = (const float*)d_in[0];
    const float* skip     = (const float*)d_in[1];
    const float* up_w     = (const float*)d_in[2];
    const float* up_b     = (const float*)d_in[3];
    const float* in_proj  = (const float*)d_in[4];
    const float* c1w      = (const float*)d_in[5];
    const float* c1b      = (const float*)d_in[6];
    const float* xproj    = (const float*)d_in[7];
    const float* dtw      = (const float*)d_in[8];
    const float* dtb      = (const float*)d_in[9];
    const float* A_log    = (const float*)d_in[10];
    const float* Dp       = (const float*)d_in[11];
    const float* outw     = (const float*)d_in[12];
    const float* cw       = (const float*)d_in[13];
    const float* cb       = (const float*)d_in[14];
    const float* bng      = (const float*)d_in[15];
    const float* bnb      = (const float*)d_in[16];
    float* out = (float*)d_out;

    float *xc, *xi, *z, *u, *dbc, *dtv, *y, *xr, *y2, *S, *hs, *sd, *wt4;
    __half *wp1, *wp2, *wp3, *upp;
    cudaGetSymbolAddress((void**)&xc,  g_xc);
    cudaGetSymbolAddress((void**)&xi,  g_xi);
    cudaGetSymbolAddress((void**)&z,   g_z);
    cudaGetSymbolAddress((void**)&u,   g_u);
    cudaGetSymbolAddress((void**)&dbc, g_dbc);
    cudaGetSymbolAddress((void**)&dtv, g_dt);
    cudaGetSymbolAddress((void**)&y,   g_y);
    cudaGetSymbolAddress((void**)&xr,  g_xr);
    cudaGetSymbolAddress((void**)&y2,  g_y2);
    cudaGetSymbolAddress((void**)&S,   g_S);
    cudaGetSymbolAddress((void**)&hs,  g_hs);
    cudaGetSymbolAddress((void**)&sd,  g_sd);
    cudaGetSymbolAddress((void**)&wp1, g_wp1h);
    cudaGetSymbolAddress((void**)&wp2, g_wp2h);
    cudaGetSymbolAddress((void**)&wp3, g_wp3h);
    cudaGetSymbolAddress((void**)&wt4, g_wt4);
    cudaGetSymbolAddress((void**)&upp, g_upph);

    cudaFuncSetAttribute(conv3_tc, cudaFuncAttributeMaxDynamicSharedMemorySize, C3_SMEM);
    cudaFuncSetAttribute(gemm128h<true,  false, EpiUp >, cudaFuncAttributeMaxDynamicSharedMemorySize, GH_SMEM);
    cudaFuncSetAttribute(gemm128h<false, true,  EpiXZ >, cudaFuncAttributeMaxDynamicSharedMemorySize, GH_SMEM);
    cudaFuncSetAttribute(gemm128h<false, true,  EpiDbc>, cudaFuncAttributeMaxDynamicSharedMemorySize, GH_SMEM);
    cudaFuncSetAttribute(gemm128h<false, true,  EpiOut>, cudaFuncAttributeMaxDynamicSharedMemorySize, GH_SMEM);

    // 0) merged prep: fp16 packed weight builds + conv weight transpose + skip copy
    prep_kernel<<<3616, 256>>>(in_proj, outw, xproj, cw, up_w, skip,
                               wp1, wp2, wp3, wt4, upp, xc);

    // 1) upsample GEMM (fp16 TC): A = packed up_w, B = x (cvt)
    gemm128h<true, false, EpiUp><<<dim3(8, 4, NB), 256, GH_SMEM>>>(
        upp, 512, 0, x, 1024, (long)256*1024, 512, 1024, 256, EpiUp{xc, up_b});

    // 2) in_proj GEMM (fp16 TC): A = xc (cvt), B = packed wp1
    gemm128h<false, true, EpiXZ><<<dim3(8, 32, NB), 256, GH_SMEM>>>(
        xc, LSEQ, (long)DM*LSEQ, wp1, 1024, 0, LSEQ, 2*DI, DM, EpiXZ{xi, z});

    // 3) depthwise conv1d + silu
    conv1d_kernel<<<dim3(LSEQ/128, DI/32, NB), 256>>>(xi, c1w, c1b, u);

    // 4) x_proj GEMM (fp16 TC, N padded 48->128): A = u (cvt), B = packed wp3
    gemm128h<false, true, EpiDbc><<<dim3(1, 32, NB), 256, GH_SMEM>>>(
        u, LSEQ, (long)DI*LSEQ, wp3, 128, 0, LSEQ, 128, DI, EpiDbc{dbc});

    // 5) dt = softplus(dbc[:16]^T @ dtw^T + dtb)
    dt_kernel<<<NB*LSEQ/64, 256>>>(dbc, dtw, dtb, dtv);

    // 6) chunked selective scan
    scan_pass1<<<dim3(NCH, NB*DI/8), 128>>>(dtv, u, dbc, A_log, S, sd);
    scan_pass2<<<NB*DI/8, 128>>>(S, sd, A_log, hs);
    scan_pass3<<<dim3(NCH, NB*DI/8), 128>>>(dtv, u, dbc, z, A_log, Dp, hs, y);

    // 7) out_proj GEMM (fp16 TC) + residual: A = y (cvt), B = packed wp2
    gemm128h<false, true, EpiOut><<<dim3(2, 32, NB), 256, GH_SMEM>>>(
        y, LSEQ, (long)DI*LSEQ, wp2, 256, 0, LSEQ, DM, DI, EpiOut{xc, xr});

    // 8) 3x3 conv as TF32 implicit GEMM (256 blocks)
    conv3_tc<<<dim3(64, 2, NB), 256, C3_SMEM>>>(xr, wt4, cb, y2);

    // 9) fused batchnorm + gelu
    bn_fused<<<128, 256>>>(y2, bng, bnb, out);
}